// round 8
// baseline (speedup 1.0000x reference)
#include <cuda_runtime.h>
#include <math.h>

#define TMAX 256
#define LOG2PI 1.8378770664093453

// ---------------- device scratch ----------------
__device__ float g_P[TMAX][256];
__device__ float g_ba[TMAX][16];
__device__ float g_Lr[TMAX][256];
__device__ float g_Lu[TMAX][16];
__device__ float g_Sr[32][256];
__device__ float g_Su[32][16];
__device__ float g_Gr[32][256];
__device__ float g_Gu[32][16];
__device__ float g_OmP[256], g_om[256], g_Om0[256];
__device__ float g_fcF[256], g_fmF[16];
__device__ double g_part[65];

#define BARH() asm volatile("bar.sync 5, 160;" ::: "memory")

// ---------------- dot helpers ----------------
__device__ __forceinline__ float dot_rc(const float* A, const float* B, int i, int j) {
    float s = 0.f;
#pragma unroll
    for (int k = 0; k < 16; k++) s = fmaf(A[i * 16 + k], B[k * 16 + j], s);
    return s;
}
// A-row loaded as float4 (A 16B-aligned rows), B column scalar.
__device__ __forceinline__ float dot_rc4(const float* A, const float* B, int i, int j) {
    const float4* a4 = reinterpret_cast<const float4*>(A + i * 16);
    float4 x0 = a4[0], x1 = a4[1], x2 = a4[2], x3 = a4[3];
    float s = 0.f;
    s = fmaf(x0.x, B[0 * 16 + j], s);
    s = fmaf(x0.y, B[1 * 16 + j], s);
    s = fmaf(x0.z, B[2 * 16 + j], s);
    s = fmaf(x0.w, B[3 * 16 + j], s);
    s = fmaf(x1.x, B[4 * 16 + j], s);
    s = fmaf(x1.y, B[5 * 16 + j], s);
    s = fmaf(x1.z, B[6 * 16 + j], s);
    s = fmaf(x1.w, B[7 * 16 + j], s);
    s = fmaf(x2.x, B[8 * 16 + j], s);
    s = fmaf(x2.y, B[9 * 16 + j], s);
    s = fmaf(x2.z, B[10 * 16 + j], s);
    s = fmaf(x2.w, B[11 * 16 + j], s);
    s = fmaf(x3.x, B[12 * 16 + j], s);
    s = fmaf(x3.y, B[13 * 16 + j], s);
    s = fmaf(x3.z, B[14 * 16 + j], s);
    s = fmaf(x3.w, B[15 * 16 + j], s);
    return s;
}
__device__ __forceinline__ float dot_tc(const float* A, const float* B, int i, int j) { // A^T B
    float s = 0.f;
#pragma unroll
    for (int k = 0; k < 16; k++) s = fmaf(A[k * 16 + i], B[k * 16 + j], s);
    return s;
}
__device__ __forceinline__ float dot_rt(const float* A, const float* B, int i, int j) { // A B^T
    float s = 0.f;
#pragma unroll
    for (int k = 0; k < 16; k++) s = fmaf(A[i * 16 + k], B[j * 16 + k], s);
    return s;
}
__device__ __forceinline__ float dot_rowreg_col(const float* row, const float* B, int j) {
    float s = 0.f;
#pragma unroll
    for (int k = 0; k < 16; k++) s = fmaf(row[k], B[k * 16 + j], s);
    return s;
}
__device__ __forceinline__ float mv(const float* M, const float* v, int r) {
    float s = 0.f;
#pragma unroll
    for (int k = 0; k < 16; k++) s = fmaf(M[r * 16 + k], v[k], s);
    return s;
}

// Single-warp register-resident Gauss-Jordan solve: A (16x16 SPD) X = B.
// Writes X^T (row-major) to Xt. Returns logdet(A) on all lanes.
__device__ __forceinline__ float warp_gj_solve(const float* Am, const float* Bm,
                                               float* Xt, int lane) {
    float a[16];
    {
        const float* src = (lane < 16) ? (Am + lane) : (Bm + lane - 16);
#pragma unroll
        for (int r = 0; r < 16; r++) a[r] = src[r * 16];
    }
    float mypiv = 1.f;
#pragma unroll
    for (int p = 0; p < 16; p++) {
        float f[16];
#pragma unroll
        for (int r = 0; r < 16; r++) f[r] = __shfl_sync(0xffffffffu, a[r], p);
        float x = f[p];
        if (lane == p) mypiv = x;
        float r0;
        asm("rcp.approx.f32 %0, %1;" : "=f"(r0) : "f"(x));
        float pivinv = r0 * (2.0f - x * r0);
        a[p] *= pivinv;
#pragma unroll
        for (int r = 0; r < 16; r++)
            if (r != p) a[r] = fmaf(-f[r], a[p], a[r]);
    }
    float lg = __logf(mypiv);
#pragma unroll
    for (int o = 16; o; o >>= 1) lg += __shfl_xor_sync(0xffffffffu, lg, o);
    if (lane >= 16) {
        float4* dst = reinterpret_cast<float4*>(Xt + (lane - 16) * 16);
        dst[0] = make_float4(a[0], a[1], a[2], a[3]);
        dst[1] = make_float4(a[4], a[5], a[6], a[7]);
        dst[2] = make_float4(a[8], a[9], a[10], a[11]);
        dst[3] = make_float4(a[12], a[13], a[14], a[15]);
    }
    return lg;
}

// ---------------- forward kernel ----------------
struct __align__(16) SMF {
    // all 256-float arrays first (1024B each -> rows stay 16B aligned)
    float Wq[256], Sq[256], Hq[256], Rq[256], Wp[256], Wep[256];
    float WH[256], C1[256], C2[256];
    float Om_p[256], om[256], Om0[256], Em[256], Fm[256];
    float fcb[2][256], M[2][256], pc[2][256], Hpc[2][256], bA[2][256];
    float S[256], K[256], U[256];
    float t1[256], t2[256], t3[256], OmpA[256], G[256], Go[256], bcov[256];
    float bq[16], dq[16], bp[16], ebp[16], ppm[16];
    float fmb[2][16], pm[2][16], innov[16], y[16];
    double dred[8], dsc[2];
};

__global__ void __launch_bounds__(256, 1) lgq_fwd(
    const float* obs, const float* p_prior_mean, const float* p_prior_cov,
    const float* p_trans_w, const float* p_trans_b, const float* p_trans_cov,
    const float* p_emis_w, const float* p_emis_b, const float* p_emis_cov,
    const float* q_prior_mean, const float* q_prior_cov, const float* q_trans_w,
    const float* q_trans_b, const float* q_trans_cov, const float* q_emis_w,
    const float* q_emis_b, const float* q_emis_cov, int Tn) {
    __shared__ SMF s;
    const int tid = threadIdx.x;
    const int i = tid >> 4, j = tid & 15;
    const int lane = tid & 31, wid = tid >> 5;

    // load constants
    s.Wq[tid] = q_trans_w[tid];
    s.Sq[tid] = q_trans_cov[tid];
    s.Hq[tid] = q_emis_w[tid];
    s.Rq[tid] = q_emis_cov[tid];
    s.Wp[tid] = p_trans_w[tid];
    s.Wep[tid] = p_emis_w[tid];
    if (tid < 16) {
        s.bq[tid] = q_trans_b[tid];
        s.dq[tid] = q_emis_b[tid];
        s.bp[tid] = p_trans_b[tid];
        s.ebp[tid] = p_emis_b[tid];
        s.ppm[tid] = p_prior_mean[tid];
    }
    __syncthreads();

    // derived constants
    s.WH[tid] = dot_rc(s.Hq, s.Wq, i, j);
    s.C1[tid] = dot_rc(s.Hq, s.Sq, i, j);

    // ---- setup: constant inverses / logdets ----
    float LDp = 0.f, LDe = 0.f, LDpr = 0.f, LDSq = 0.f, LDRq = 0.f, ldqp = 0.f, ldS0 = 0.f;
    s.t2[tid] = (i == j) ? 1.f : 0.f;  // identity RHS
    s.S[tid] = p_trans_cov[tid];
    __syncthreads();
    s.C2[tid] = dot_rt(s.C1, s.Hq, i, j) + s.Rq[tid];
    if (wid == 0) LDp = warp_gj_solve(s.S, s.t2, s.K, lane);
    __syncthreads();
    s.Om_p[tid] = -0.5f * s.K[tid];
    s.t3[tid] = dot_rc(s.K, s.Wp, i, j);
    __syncthreads();
    s.Fm[tid] = dot_tc(s.Wp, s.t3, i, j);
    s.S[tid] = p_emis_cov[tid];
    __syncthreads();
    if (wid == 0) LDe = warp_gj_solve(s.S, s.t2, s.K, lane);
    __syncthreads();
    s.om[tid] = -0.5f * s.K[tid];
    s.S[tid] = p_prior_cov[tid];
    __syncthreads();
    s.t3[tid] = dot_rc(s.om, s.Wep, i, j);
    if (wid == 0) LDpr = warp_gj_solve(s.S, s.t2, s.K, lane);
    __syncthreads();
    s.Em[tid] = dot_tc(s.Wep, s.t3, i, j);
    s.Om0[tid] = -0.5f * s.K[tid];
    s.S[tid] = q_trans_cov[tid];
    __syncthreads();
    if (wid == 0) LDSq = warp_gj_solve(s.S, s.t2, s.t3, lane);
    __syncthreads();
    s.S[tid] = q_emis_cov[tid];
    __syncthreads();
    if (wid == 0) LDRq = warp_gj_solve(s.S, s.t2, s.t3, lane);
    __syncthreads();

    // ---- t=0 Kalman update ----
    s.pc[0][tid] = q_prior_cov[tid];
    if (tid < 16) {
        s.pm[0][tid] = q_prior_mean[tid];
        s.y[tid] = obs[tid];
    }
    __syncthreads();
    if (wid == 0) ldqp = warp_gj_solve(s.pc[0], s.t2, s.t3, lane);
    __syncthreads();
    s.Hpc[0][tid] = dot_rc(s.Hq, s.pc[0], i, j);
    if (tid < 16) s.innov[tid] = s.y[tid] - mv(s.Hq, s.pm[0], tid) - s.dq[tid];
    __syncthreads();
    s.S[tid] = dot_rt(s.Hpc[0], s.Hq, i, j) + s.Rq[tid];
    __syncthreads();
    if (wid == 0) ldS0 = warp_gj_solve(s.S, s.Hpc[0], s.K, lane);
    __syncthreads();
    s.fcb[0][tid] = s.pc[0][tid] - dot_rc(s.K, s.Hpc[0], i, j);
    s.G[tid] = s.Om0[tid];
    s.Go[tid] = s.Em[tid];
    if (tid < 16) s.fmb[0][tid] = s.pm[0][tid] + mv(s.K, s.innov, tid);
    __syncthreads();

    // cached register rows
    float wqi[16], whi_[16], wqj[16], whj[16];
#pragma unroll
    for (int k = 0; k < 16; k++) {
        wqi[k] = s.Wq[i * 16 + k];
        whi_[k] = s.WH[i * 16 + k];
        wqj[k] = s.Wq[j * 16 + k];
        whj[k] = s.WH[j * 16 + k];
    }

    // ---- prologue: produce iter-1 inputs (parity w=1) ----
    s.M[1][tid] = dot_rowreg_col(wqi, s.fcb[0], j);
    s.U[tid] = dot_rowreg_col(whi_, s.fcb[0], j);
    if (tid < 16) {
        s.pm[1][tid] = mv(s.Wq, s.fmb[0], tid) + s.bq[tid];
        s.y[tid] = (Tn > 1) ? obs[16 + tid] : 0.f;
    }
    __syncthreads();
    s.pc[1][tid] = dot_rt(s.M[1], s.Wq, i, j) + s.Sq[tid];
    s.S[tid] = dot_rt(s.U, s.WH, i, j) + s.C2[tid];
    s.Hpc[1][tid] = dot_rt(s.U, s.Wq, i, j) + s.C1[tid];
    if (tid < 16) s.innov[tid] = s.y[tid] - mv(s.Hq, s.pm[1], tid) - s.dq[tid];
    __syncthreads();

    // thread-0 setup scalars
    double set_acc = 0.0, K0d = 0.0, ldfc0 = 0.0, LDSqd = 0.0, LDRqd = 0.0;
    if (tid == 0) {
        set_acc = -0.5 * (16.0 * LOG2PI + (double)LDpr)
                - 0.5 * (16.0 * LOG2PI + (double)LDe);
        K0d = -8.0 * LOG2PI - 0.5 * (double)LDe - 0.5 * (double)LDp + 8.0;
        ldfc0 = (double)ldqp + (double)LDRq - (double)ldS0;  // logdet(fc_0)
        LDSqd = (double)LDSq;
        LDRqd = (double)LDRq;
    }

    double accel = 0.0, d0 = 0.0;
    float lastld = 0.f;

    // ================= pipeline =================
    for (int t = 1; t < Tn; t++) {
        const int w = t & 1, r = w ^ 1;
        // --- GJ phase: warp0 GJ(S); warp5 GJ(pc); warps 1,2,3,6,7 shadow Gram(t-1);
        //     warp4 idle (protects warp0's SMSP) ---
        if (wid == 0) {
            float ld = warp_gj_solve(s.S, s.Hpc[w], s.K, lane);
            d0 += (double)ld;  // sum lds
            lastld = ld;       // lds_N
        } else if (wid == 5) {
            float ld = warp_gj_solve(s.pc[w], s.M[w], s.bA[w], lane);
            d0 += (double)ld;  // sum ldp
            lastld = ld;       // ldp_N
        } else if (wid != 4) {
            if (t >= 2) {
                // shadow for step t-1: bA=bA[r], M=M[r], fc_{t-2}=fcb[w]
                const int h = (wid < 4) ? (tid - 32) : (tid - 96);  // 0..159
                const float* bAr = s.bA[r];
                // phase1: t1, Xt=(G bA)^T, Yt=(Go bA)^T, bcov
                for (int e = h; e < 256; e += 160) {
                    int ei = e >> 4, ej = e & 15;
                    s.t1[e] = dot_rc4(s.Wp, bAr, ei, ej) - ((ei == ej) ? 1.f : 0.f);
                    s.t2[e] = dot_rc4(s.G, bAr, ej, ei);
                    s.t3[e] = dot_rc4(s.Go, bAr, ej, ei);
                    s.bcov[e] = s.fcb[w][e] - dot_rc4(bAr, s.M[r], ei, ej);
                }
                BARH();
                // phase2: Zt=(Om_p t1)^T; accel (reads old G,Go)
                for (int e = h; e < 256; e += 160) {
                    int ei = e >> 4, ej = e & 15;
                    s.OmpA[e] = dot_rc4(s.Om_p, s.t1, ej, ei);
                    accel += (double)((s.G[e] + s.Go[e] - 0.5f * s.Fm[e]) * s.bcov[e]);
                }
                BARH();
                // phase3: G' = Xt^T-form + Zt-form; Go' = Yt-form + Em
                for (int e = h; e < 256; e += 160) {
                    int ei = e >> 4, ej = e & 15;
                    float g = dot_rc4(s.t2, bAr, ei, ej) + dot_rc4(s.OmpA, s.t1, ei, ej);
                    float go = dot_rc4(s.t3, bAr, ei, ej) + s.Em[e];
                    s.G[e] = g;
                    s.Go[e] = go;
                }
            }
        }
        __syncthreads();
        // --- st1: fc, fm, stores ---
        s.fcb[w][tid] = s.pc[w][tid] - dot_rc4(s.K, s.Hpc[w], i, j);
        g_P[t][tid] = s.bA[w][tid];
        if (tid < 16) {
            s.fmb[w][tid] = s.pm[w][tid] + mv(s.K, s.innov, tid);
            g_ba[t][tid] = s.fmb[r][tid] - mv(s.bA[w], s.pm[w], tid);
        }
        __syncthreads();
        // --- st2: M', U (shared fc column), pm', y ---
        {
            float col[16];
#pragma unroll
            for (int k = 0; k < 16; k++) col[k] = s.fcb[w][k * 16 + j];
            float m = 0.f, u = 0.f;
#pragma unroll
            for (int k = 0; k < 16; k++) {
                m = fmaf(wqi[k], col[k], m);
                u = fmaf(whi_[k], col[k], u);
            }
            s.M[r][tid] = m;
            s.U[tid] = u;
        }
        if (tid < 16 && t + 1 < Tn) {
            s.pm[r][tid] = mv(s.Wq, s.fmb[w], tid) + s.bq[tid];
            s.y[tid] = obs[(t + 1) * 16 + tid];
        }
        __syncthreads();
        // --- st3: pc', S', Hpc' (float4 rows), innov' ---
        {
            const float4* m4 = reinterpret_cast<const float4*>(s.M[r] + i * 16);
            const float4* u4 = reinterpret_cast<const float4*>(s.U + i * 16);
            float4 m0 = m4[0], m1 = m4[1], m2 = m4[2], m3 = m4[3];
            float4 u0 = u4[0], u1 = u4[1], u2 = u4[2], u3 = u4[3];
            float mr[16] = {m0.x, m0.y, m0.z, m0.w, m1.x, m1.y, m1.z, m1.w,
                            m2.x, m2.y, m2.z, m2.w, m3.x, m3.y, m3.z, m3.w};
            float ur[16] = {u0.x, u0.y, u0.z, u0.w, u1.x, u1.y, u1.z, u1.w,
                            u2.x, u2.y, u2.z, u2.w, u3.x, u3.y, u3.z, u3.w};
            float pcv = 0.f, sv = 0.f, hv = 0.f;
#pragma unroll
            for (int k = 0; k < 16; k++) {
                pcv = fmaf(mr[k], wqj[k], pcv);
                sv = fmaf(ur[k], whj[k], sv);
                hv = fmaf(ur[k], wqj[k], hv);
            }
            s.pc[r][tid] = pcv + s.Sq[tid];
            s.S[tid] = sv + s.C2[tid];
            s.Hpc[r][tid] = hv + s.C1[tid];
        }
        if (tid < 16 && t + 1 < Tn)
            s.innov[tid] = s.y[tid] - mv(s.Hq, s.pm[r], tid) - s.dq[tid];
        __syncthreads();
    }

    // flush: accel term for step Tn-1 (G,Go = through Tn-2)
    if (Tn > 1) {
        const int fp = (Tn - 1) & 1, rp = fp ^ 1;
        float bc = s.fcb[rp][tid] - dot_rc4(s.bA[fp], s.M[fp], i, j);
        accel += (double)((s.G[tid] + s.Go[tid] - 0.5f * s.Fm[tid]) * bc);
    }

    // ---- epilogue ----
    g_OmP[tid] = s.Om_p[tid];
    g_om[tid] = s.om[tid];
    g_Om0[tid] = s.Om0[tid];
    {
        int fp = (Tn - 1) & 1;
        g_fcF[tid] = s.fcb[fp][tid];
        if (tid < 16) g_fmF[tid] = s.fmb[fp][tid];
    }
    double v = accel;
#pragma unroll
    for (int o = 16; o; o >>= 1) v += __shfl_xor_sync(0xffffffffu, v, o);
    if (lane == 0) s.dred[wid] = v;
    if (tid == 160) {
        s.dsc[0] = d0;              // SP = sum ldp_t
        s.dsc[1] = (double)lastld;  // ldp_N
    }
    __syncthreads();
    if (tid == 0) {
        double elem = 0.0;
#pragma unroll
        for (int w = 0; w < 8; w++) elem += s.dred[w];
        double SP = s.dsc[0], ldpN = s.dsc[1];
        double sumS = d0, ldsN = (double)lastld;
        double N = (double)(Tn - 1);
        double sumF = ldfc0 + (SP - ldpN) + (N - 1.0) * LDRqd - (sumS - ldsN);
        double FN = ldpN + LDRqd - ldsN;
        double sc = set_acc
                  + N * (K0d + 0.5 * LDSqd)
                  - 0.5 * SP
                  + 0.5 * sumF
                  + 0.5 * (16.0 * LOG2PI + FN) + 8.0
                  + elem;
        g_part[64] = sc;
    }
}

// ---------------- backward scan kernels ----------------
#define SEG 8
__global__ void __launch_bounds__(256, 1) lgq_scan1(int Tn) {
    const int b = blockIdx.x;
    const int lo = b * SEG;
    int hi = lo + SEG;
    if (hi > Tn) hi = Tn;
    __shared__ float R[256], Rn[256], bA[256];
    __shared__ float u[16], un[16], ba[16];
    const int tid = threadIdx.x;
    const int i = tid >> 4, j = tid & 15;
    R[tid] = (i == j) ? 1.f : 0.f;
    if (tid < 16) u[tid] = 0.f;
    __syncthreads();
    for (int t = hi - 1; t >= lo; t--) {
        g_Lr[t][tid] = R[tid];
        if (tid < 16) g_Lu[t][tid] = u[tid];
        if (t == 0) break;
        bA[tid] = g_P[t][tid];
        if (tid < 16) ba[tid] = g_ba[t][tid];
        __syncthreads();
        Rn[tid] = dot_rc(bA, R, i, j);
        if (tid < 16) un[tid] = ba[tid] + mv(bA, u, tid);
        __syncthreads();
        R[tid] = Rn[tid];
        if (tid < 16) u[tid] = un[tid];
        __syncthreads();
    }
    g_Sr[b][tid] = R[tid];
    if (tid < 16) g_Su[b][tid] = u[tid];
}

__global__ void __launch_bounds__(256, 1) lgq_scan2(int Tn) {
    const int nseg = (Tn + SEG - 1) / SEG;
    __shared__ float Gr[256], Gn[256], Sr[256];
    __shared__ float Gu[16], gn[16], Su[16];
    const int tid = threadIdx.x;
    const int i = tid >> 4, j = tid & 15;
    Gr[tid] = (i == j) ? 1.f : 0.f;
    if (tid < 16) Gu[tid] = 0.f;
    __syncthreads();
    for (int b = nseg - 1; b >= 0; b--) {
        g_Gr[b][tid] = Gr[tid];
        if (tid < 16) g_Gu[b][tid] = Gu[tid];
        if (b == 0) break;
        Sr[tid] = g_Sr[b][tid];
        if (tid < 16) Su[tid] = g_Su[b][tid];
        __syncthreads();
        Gn[tid] = dot_rc(Sr, Gr, i, j);
        if (tid < 16) gn[tid] = mv(Sr, Gu, tid) + Su[tid];
        __syncthreads();
        Gr[tid] = Gn[tid];
        if (tid < 16) Gu[tid] = gn[tid];
        __syncthreads();
    }
}

#define EVT 4
__global__ void __launch_bounds__(256, 1) lgq_scan3(
    const float* obs, const float* p_trans_w, const float* p_trans_b,
    const float* p_emis_w, const float* p_emis_b, const float* p_prior_mean,
    int Tn) {
    const int b = blockIdx.x;
    const int lo = b * EVT;
    int hi = lo + EVT;
    if (hi > Tn) hi = Tn;
    const int seg = lo / SEG;
    __shared__ float OmP[256], omm[256], Om0[256], Wp[256], Wep[256], fc[256], Gr[256];
    __shared__ float Lr[256], bA[256], Rf[256], Ai[256], A[256], Ao[256], AF[256], AoF[256];
    __shared__ float fm[16], Gu[16], Lu[16], bav[16], uf[16], Bv[16], Bo[16];
    __shared__ float cv[16], co[16], y[16], bp[16], ebp[16], ppm[16];
    __shared__ double dred[8];
    const int tid = threadIdx.x;
    const int i = tid >> 4, j = tid & 15;
    const int lane = tid & 31, wid = tid >> 5;

    OmP[tid] = g_OmP[tid];
    omm[tid] = g_om[tid];
    Om0[tid] = g_Om0[tid];
    Wp[tid] = p_trans_w[tid];
    Wep[tid] = p_emis_w[tid];
    fc[tid] = g_fcF[tid];
    Gr[tid] = g_Gr[seg][tid];
    if (tid < 16) {
        fm[tid] = g_fmF[tid];
        Gu[tid] = g_Gu[seg][tid];
        bp[tid] = p_trans_b[tid];
        ebp[tid] = p_emis_b[tid];
        ppm[tid] = p_prior_mean[tid];
    }
    __syncthreads();

    double acc = 0.0;
    for (int t = lo; t < hi; t++) {
        Lr[tid] = g_Lr[t][tid];
        bA[tid] = (t > 0) ? g_P[t][tid] : 0.f;
        if (tid < 16) {
            Lu[tid] = g_Lu[t][tid];
            bav[tid] = (t > 0) ? g_ba[t][tid] : 0.f;
            y[tid] = obs[t * 16 + tid];
        }
        __syncthreads();
        Rf[tid] = dot_rc(Lr, Gr, i, j);
        Ai[tid] = (t > 0) ? (dot_rc(Wp, bA, i, j) - ((i == j) ? 1.f : 0.f))
                          : ((i == j) ? 1.f : 0.f);
        if (tid < 16) {
            uf[tid] = mv(Lr, Gu, tid) + Lu[tid];
            Bv[tid] = (t > 0) ? (mv(Wp, bav, tid) + bp[tid]) : (-ppm[tid]);
        }
        __syncthreads();
        A[tid] = dot_rc(Ai, Rf, i, j);
        Ao[tid] = dot_rc(Wep, Rf, i, j);
        if (tid < 16) {
            Bv[tid] += mv(Ai, uf, tid);
            Bo[tid] = ebp[tid] - y[tid] + mv(Wep, uf, tid);
        }
        __syncthreads();
        AF[tid] = dot_rc(A, fc, i, j);
        AoF[tid] = dot_rc(Ao, fc, i, j);
        if (tid < 16) {
            cv[tid] = mv(A, fm, tid) + Bv[tid];
            co[tid] = mv(Ao, fm, tid) + Bo[tid];
        }
        __syncthreads();
        {
            const float* Om = (t == 0) ? Om0 : OmP;
            float val = Om[tid] * (dot_rc(AF, A, i, j) + cv[i] * cv[j])
                      + omm[tid] * (dot_rc(AoF, Ao, i, j) + co[i] * co[j]);
            acc += (double)val;
        }
        __syncthreads();
    }

    double v = acc;
#pragma unroll
    for (int o = 16; o; o >>= 1) v += __shfl_xor_sync(0xffffffffu, v, o);
    if (lane == 0) dred[wid] = v;
    __syncthreads();
    if (tid == 0) {
        double tot = 0.0;
#pragma unroll
        for (int w = 0; w < 8; w++) tot += dred[w];
        g_part[b] = tot;
    }
}

__global__ void lgq_fin(float* out, int Tn) {
    if (threadIdx.x == 0) {
        const int nblk = (Tn + EVT - 1) / EVT;
        double tot = g_part[64];
        for (int b = 0; b < nblk; b++) tot += g_part[b];
        out[0] = (float)tot;
    }
}

extern "C" void kernel_launch(void* const* d_in, const int* in_sizes, int n_in,
                              void* d_out, int out_size) {
    int Tn = in_sizes[0] / 16;
    if (Tn > TMAX) Tn = TMAX;
    const int nseg = (Tn + SEG - 1) / SEG;
    const int nblk = (Tn + EVT - 1) / EVT;
    lgq_fwd<<<1, 256>>>(
        (const float*)d_in[0], (const float*)d_in[1], (const float*)d_in[2],
        (const float*)d_in[3], (const float*)d_in[4], (const float*)d_in[5],
        (const float*)d_in[6], (const float*)d_in[7], (const float*)d_in[8],
        (const float*)d_in[9], (const float*)d_in[10], (const float*)d_in[11],
        (const float*)d_in[12], (const float*)d_in[13], (const float*)d_in[14],
        (const float*)d_in[15], (const float*)d_in[16], Tn);
    lgq_scan1<<<nseg, 256>>>(Tn);
    lgq_scan2<<<1, 256>>>(Tn);
    lgq_scan3<<<nblk, 256>>>(
        (const float*)d_in[0], (const float*)d_in[3], (const float*)d_in[4],
        (const float*)d_in[6], (const float*)d_in[7], (const float*)d_in[1], Tn);
    lgq_fin<<<1, 32>>>((float*)d_out, Tn);
}

// round 9
// speedup vs baseline: 1.0042x; 1.0042x over previous
#include <cuda_runtime.h>
#include <math.h>

#define TMAX 256
#define LOG2PI 1.8378770664093453

// ---------------- device scratch ----------------
__device__ float g_P[TMAX][256];
__device__ float g_ba[TMAX][16];
__device__ float g_Lr[TMAX][256];
__device__ float g_Lu[TMAX][16];
__device__ float g_Sr[32][256];
__device__ float g_Su[32][16];
__device__ float g_Gr[32][256];
__device__ float g_Gu[32][16];
__device__ float g_OmP[256], g_om[256], g_Om0[256];
__device__ float g_fcF[256], g_fmF[16];
__device__ double g_part[65];

#define BARH() asm volatile("bar.sync 5, 160;" ::: "memory")

// ---------------- dot helpers ----------------
__device__ __forceinline__ float dot_rc(const float* A, const float* B, int i, int j) {
    float s = 0.f;
#pragma unroll
    for (int k = 0; k < 16; k++) s = fmaf(A[i * 16 + k], B[k * 16 + j], s);
    return s;
}
// A-row loaded as float4 (A 16B-aligned rows), B column scalar.
__device__ __forceinline__ float dot_rc4(const float* A, const float* B, int i, int j) {
    const float4* a4 = reinterpret_cast<const float4*>(A + i * 16);
    float4 x0 = a4[0], x1 = a4[1], x2 = a4[2], x3 = a4[3];
    float s = 0.f;
    s = fmaf(x0.x, B[0 * 16 + j], s);
    s = fmaf(x0.y, B[1 * 16 + j], s);
    s = fmaf(x0.z, B[2 * 16 + j], s);
    s = fmaf(x0.w, B[3 * 16 + j], s);
    s = fmaf(x1.x, B[4 * 16 + j], s);
    s = fmaf(x1.y, B[5 * 16 + j], s);
    s = fmaf(x1.z, B[6 * 16 + j], s);
    s = fmaf(x1.w, B[7 * 16 + j], s);
    s = fmaf(x2.x, B[8 * 16 + j], s);
    s = fmaf(x2.y, B[9 * 16 + j], s);
    s = fmaf(x2.z, B[10 * 16 + j], s);
    s = fmaf(x2.w, B[11 * 16 + j], s);
    s = fmaf(x3.x, B[12 * 16 + j], s);
    s = fmaf(x3.y, B[13 * 16 + j], s);
    s = fmaf(x3.z, B[14 * 16 + j], s);
    s = fmaf(x3.w, B[15 * 16 + j], s);
    return s;
}
__device__ __forceinline__ float dot_tc(const float* A, const float* B, int i, int j) { // A^T B
    float s = 0.f;
#pragma unroll
    for (int k = 0; k < 16; k++) s = fmaf(A[k * 16 + i], B[k * 16 + j], s);
    return s;
}
__device__ __forceinline__ float dot_rt(const float* A, const float* B, int i, int j) { // A B^T
    float s = 0.f;
#pragma unroll
    for (int k = 0; k < 16; k++) s = fmaf(A[i * 16 + k], B[j * 16 + k], s);
    return s;
}
__device__ __forceinline__ float dot_rowreg_col(const float* row, const float* B, int j) {
    float s = 0.f;
#pragma unroll
    for (int k = 0; k < 16; k++) s = fmaf(row[k], B[k * 16 + j], s);
    return s;
}
__device__ __forceinline__ float mv(const float* M, const float* v, int r) {
    float s = 0.f;
#pragma unroll
    for (int k = 0; k < 16; k++) s = fmaf(M[r * 16 + k], v[k], s);
    return s;
}

// Single-warp register-resident Gauss-Jordan solve: A (16x16 SPD) X = B.
// Writes X^T (row-major) to Xt. Returns logdet(A) on all lanes.
__device__ __forceinline__ float warp_gj_solve(const float* Am, const float* Bm,
                                               float* Xt, int lane) {
    float a[16];
    {
        const float* src = (lane < 16) ? (Am + lane) : (Bm + lane - 16);
#pragma unroll
        for (int r = 0; r < 16; r++) a[r] = src[r * 16];
    }
    float mypiv = 1.f;
#pragma unroll
    for (int p = 0; p < 16; p++) {
        float f[16];
#pragma unroll
        for (int r = 0; r < 16; r++) f[r] = __shfl_sync(0xffffffffu, a[r], p);
        float x = f[p];
        if (lane == p) mypiv = x;
        float r0;
        asm("rcp.approx.f32 %0, %1;" : "=f"(r0) : "f"(x));
        float pivinv = r0 * (2.0f - x * r0);
        a[p] *= pivinv;
#pragma unroll
        for (int r = 0; r < 16; r++)
            if (r != p) a[r] = fmaf(-f[r], a[p], a[r]);
    }
    float lg = __logf(mypiv);
#pragma unroll
    for (int o = 16; o; o >>= 1) lg += __shfl_xor_sync(0xffffffffu, lg, o);
    if (lane >= 16) {
        float4* dst = reinterpret_cast<float4*>(Xt + (lane - 16) * 16);
        dst[0] = make_float4(a[0], a[1], a[2], a[3]);
        dst[1] = make_float4(a[4], a[5], a[6], a[7]);
        dst[2] = make_float4(a[8], a[9], a[10], a[11]);
        dst[3] = make_float4(a[12], a[13], a[14], a[15]);
    }
    return lg;
}

// ---------------- forward kernel ----------------
struct __align__(16) SMF {
    // all 256-float arrays first (1024B each -> rows stay 16B aligned)
    float Wq[256], Sq[256], Hq[256], Rq[256], Wp[256], Wep[256];
    float WH[256], C1[256], C2[256];
    float Om_p[256], om[256], Om0[256], Em[256], Fm[256];
    float fcb[2][256], M[2][256], pc[2][256], Hpc[2][256], bA[2][256];
    float S[256], K[256], U[256];
    float t1[256], t2[256], t3[256], OmpA[256], G[256], Go[256], bcov[256];
    float bq[16], dq[16], bp[16], ebp[16], ppm[16];
    float fmb[2][16], pm[2][16], innov[16], y[16];
    double dred[8], dsc[2];
};

__global__ void __launch_bounds__(256, 1) lgq_fwd(
    const float* obs, const float* p_prior_mean, const float* p_prior_cov,
    const float* p_trans_w, const float* p_trans_b, const float* p_trans_cov,
    const float* p_emis_w, const float* p_emis_b, const float* p_emis_cov,
    const float* q_prior_mean, const float* q_prior_cov, const float* q_trans_w,
    const float* q_trans_b, const float* q_trans_cov, const float* q_emis_w,
    const float* q_emis_b, const float* q_emis_cov, int Tn) {
    __shared__ SMF s;
    const int tid = threadIdx.x;
    const int i = tid >> 4, j = tid & 15;
    const int lane = tid & 31, wid = tid >> 5;

    // load constants
    s.Wq[tid] = q_trans_w[tid];
    s.Sq[tid] = q_trans_cov[tid];
    s.Hq[tid] = q_emis_w[tid];
    s.Rq[tid] = q_emis_cov[tid];
    s.Wp[tid] = p_trans_w[tid];
    s.Wep[tid] = p_emis_w[tid];
    if (tid < 16) {
        s.bq[tid] = q_trans_b[tid];
        s.dq[tid] = q_emis_b[tid];
        s.bp[tid] = p_trans_b[tid];
        s.ebp[tid] = p_emis_b[tid];
        s.ppm[tid] = p_prior_mean[tid];
    }
    __syncthreads();

    // derived constants
    s.WH[tid] = dot_rc(s.Hq, s.Wq, i, j);
    s.C1[tid] = dot_rc(s.Hq, s.Sq, i, j);

    // ---- setup: constant inverses / logdets ----
    float LDp = 0.f, LDe = 0.f, LDpr = 0.f, LDSq = 0.f, LDRq = 0.f, ldqp = 0.f, ldS0 = 0.f;
    s.t2[tid] = (i == j) ? 1.f : 0.f;  // identity RHS
    s.S[tid] = p_trans_cov[tid];
    __syncthreads();
    s.C2[tid] = dot_rt(s.C1, s.Hq, i, j) + s.Rq[tid];
    if (wid == 0) LDp = warp_gj_solve(s.S, s.t2, s.K, lane);
    __syncthreads();
    s.Om_p[tid] = -0.5f * s.K[tid];
    s.t3[tid] = dot_rc(s.K, s.Wp, i, j);
    __syncthreads();
    s.Fm[tid] = dot_tc(s.Wp, s.t3, i, j);
    s.S[tid] = p_emis_cov[tid];
    __syncthreads();
    if (wid == 0) LDe = warp_gj_solve(s.S, s.t2, s.K, lane);
    __syncthreads();
    s.om[tid] = -0.5f * s.K[tid];
    s.S[tid] = p_prior_cov[tid];
    __syncthreads();
    s.t3[tid] = dot_rc(s.om, s.Wep, i, j);
    if (wid == 0) LDpr = warp_gj_solve(s.S, s.t2, s.K, lane);
    __syncthreads();
    s.Em[tid] = dot_tc(s.Wep, s.t3, i, j);
    s.Om0[tid] = -0.5f * s.K[tid];
    s.S[tid] = q_trans_cov[tid];
    __syncthreads();
    if (wid == 0) LDSq = warp_gj_solve(s.S, s.t2, s.t3, lane);
    __syncthreads();
    s.S[tid] = q_emis_cov[tid];
    __syncthreads();
    if (wid == 0) LDRq = warp_gj_solve(s.S, s.t2, s.t3, lane);
    __syncthreads();

    // ---- t=0 Kalman update ----
    s.pc[0][tid] = q_prior_cov[tid];
    if (tid < 16) {
        s.pm[0][tid] = q_prior_mean[tid];
        s.y[tid] = obs[tid];
    }
    __syncthreads();
    if (wid == 0) ldqp = warp_gj_solve(s.pc[0], s.t2, s.t3, lane);
    __syncthreads();
    s.Hpc[0][tid] = dot_rc(s.Hq, s.pc[0], i, j);
    if (tid < 16) s.innov[tid] = s.y[tid] - mv(s.Hq, s.pm[0], tid) - s.dq[tid];
    __syncthreads();
    s.S[tid] = dot_rt(s.Hpc[0], s.Hq, i, j) + s.Rq[tid];
    __syncthreads();
    if (wid == 0) ldS0 = warp_gj_solve(s.S, s.Hpc[0], s.K, lane);
    __syncthreads();
    s.fcb[0][tid] = s.pc[0][tid] - dot_rc(s.K, s.Hpc[0], i, j);
    s.G[tid] = s.Om0[tid];
    s.Go[tid] = s.Em[tid];
    if (tid < 16) s.fmb[0][tid] = s.pm[0][tid] + mv(s.K, s.innov, tid);
    __syncthreads();

    // cached register rows
    float wqi[16], whi_[16], wqj[16], whj[16];
#pragma unroll
    for (int k = 0; k < 16; k++) {
        wqi[k] = s.Wq[i * 16 + k];
        whi_[k] = s.WH[i * 16 + k];
        wqj[k] = s.Wq[j * 16 + k];
        whj[k] = s.WH[j * 16 + k];
    }

    // ---- prologue: produce iter-1 inputs (parity w=1) ----
    s.M[1][tid] = dot_rowreg_col(wqi, s.fcb[0], j);
    s.U[tid] = dot_rowreg_col(whi_, s.fcb[0], j);
    if (tid < 16) {
        s.pm[1][tid] = mv(s.Wq, s.fmb[0], tid) + s.bq[tid];
        s.y[tid] = (Tn > 1) ? obs[16 + tid] : 0.f;
    }
    __syncthreads();
    s.pc[1][tid] = dot_rt(s.M[1], s.Wq, i, j) + s.Sq[tid];
    s.S[tid] = dot_rt(s.U, s.WH, i, j) + s.C2[tid];
    s.Hpc[1][tid] = dot_rt(s.U, s.Wq, i, j) + s.C1[tid];
    if (tid < 16) s.innov[tid] = s.y[tid] - mv(s.Hq, s.pm[1], tid) - s.dq[tid];
    __syncthreads();

    // thread-0 setup scalars
    double set_acc = 0.0, K0d = 0.0, ldfc0 = 0.0, LDSqd = 0.0, LDRqd = 0.0;
    if (tid == 0) {
        set_acc = -0.5 * (16.0 * LOG2PI + (double)LDpr)
                - 0.5 * (16.0 * LOG2PI + (double)LDe);
        K0d = -8.0 * LOG2PI - 0.5 * (double)LDe - 0.5 * (double)LDp + 8.0;
        ldfc0 = (double)ldqp + (double)LDRq - (double)ldS0;  // logdet(fc_0)
        LDSqd = (double)LDSq;
        LDRqd = (double)LDRq;
    }

    double accel = 0.0, d0 = 0.0;
    float lastld = 0.f;

    // ================= pipeline =================
    for (int t = 1; t < Tn; t++) {
        const int w = t & 1, r = w ^ 1;
        // --- GJ phase: warp0 GJ(S); warp5 GJ(pc); warps 1,2,3,6,7 shadow Gram(t-1);
        //     warp4 idle (protects warp0's SMSP) ---
        if (wid == 0) {
            float ld = warp_gj_solve(s.S, s.Hpc[w], s.K, lane);
            d0 += (double)ld;  // sum lds
            lastld = ld;       // lds_N
        } else if (wid == 5) {
            float ld = warp_gj_solve(s.pc[w], s.M[w], s.bA[w], lane);
            d0 += (double)ld;  // sum ldp
            lastld = ld;       // ldp_N
        } else if (wid != 4) {
            if (t >= 2) {
                // shadow for step t-1: bA=bA[r], M=M[r], fc_{t-2}=fcb[w]
                const int h = (wid < 4) ? (tid - 32) : (tid - 96);  // 0..159
                const float* bAr = s.bA[r];
                // phase1: t1, Xt=(G bA)^T, Yt=(Go bA)^T, bcov
                for (int e = h; e < 256; e += 160) {
                    int ei = e >> 4, ej = e & 15;
                    s.t1[e] = dot_rc4(s.Wp, bAr, ei, ej) - ((ei == ej) ? 1.f : 0.f);
                    s.t2[e] = dot_rc4(s.G, bAr, ej, ei);
                    s.t3[e] = dot_rc4(s.Go, bAr, ej, ei);
                    s.bcov[e] = s.fcb[w][e] - dot_rc4(bAr, s.M[r], ei, ej);
                }
                BARH();
                // phase2: Zt=(Om_p t1)^T; accel (reads old G,Go)
                for (int e = h; e < 256; e += 160) {
                    int ei = e >> 4, ej = e & 15;
                    s.OmpA[e] = dot_rc4(s.Om_p, s.t1, ej, ei);
                    accel += (double)((s.G[e] + s.Go[e] - 0.5f * s.Fm[e]) * s.bcov[e]);
                }
                BARH();
                // phase3: G' = Xt^T-form + Zt-form; Go' = Yt-form + Em
                for (int e = h; e < 256; e += 160) {
                    int ei = e >> 4, ej = e & 15;
                    float g = dot_rc4(s.t2, bAr, ei, ej) + dot_rc4(s.OmpA, s.t1, ei, ej);
                    float go = dot_rc4(s.t3, bAr, ei, ej) + s.Em[e];
                    s.G[e] = g;
                    s.Go[e] = go;
                }
            }
        }
        __syncthreads();
        // --- st1: fc, fm, stores ---
        s.fcb[w][tid] = s.pc[w][tid] - dot_rc4(s.K, s.Hpc[w], i, j);
        g_P[t][tid] = s.bA[w][tid];
        if (tid < 16) {
            s.fmb[w][tid] = s.pm[w][tid] + mv(s.K, s.innov, tid);
            g_ba[t][tid] = s.fmb[r][tid] - mv(s.bA[w], s.pm[w], tid);
        }
        __syncthreads();
        // --- st2: M', U (shared fc column), pm', y ---
        {
            float col[16];
#pragma unroll
            for (int k = 0; k < 16; k++) col[k] = s.fcb[w][k * 16 + j];
            float m = 0.f, u = 0.f;
#pragma unroll
            for (int k = 0; k < 16; k++) {
                m = fmaf(wqi[k], col[k], m);
                u = fmaf(whi_[k], col[k], u);
            }
            s.M[r][tid] = m;
            s.U[tid] = u;
        }
        if (tid < 16 && t + 1 < Tn) {
            s.pm[r][tid] = mv(s.Wq, s.fmb[w], tid) + s.bq[tid];
            s.y[tid] = obs[(t + 1) * 16 + tid];
        }
        __syncthreads();
        // --- st3: pc', S', Hpc' (float4 rows), innov' ---
        {
            const float4* m4 = reinterpret_cast<const float4*>(s.M[r] + i * 16);
            const float4* u4 = reinterpret_cast<const float4*>(s.U + i * 16);
            float4 m0 = m4[0], m1 = m4[1], m2 = m4[2], m3 = m4[3];
            float4 u0 = u4[0], u1 = u4[1], u2 = u4[2], u3 = u4[3];
            float mr[16] = {m0.x, m0.y, m0.z, m0.w, m1.x, m1.y, m1.z, m1.w,
                            m2.x, m2.y, m2.z, m2.w, m3.x, m3.y, m3.z, m3.w};
            float ur[16] = {u0.x, u0.y, u0.z, u0.w, u1.x, u1.y, u1.z, u1.w,
                            u2.x, u2.y, u2.z, u2.w, u3.x, u3.y, u3.z, u3.w};
            float pcv = 0.f, sv = 0.f, hv = 0.f;
#pragma unroll
            for (int k = 0; k < 16; k++) {
                pcv = fmaf(mr[k], wqj[k], pcv);
                sv = fmaf(ur[k], whj[k], sv);
                hv = fmaf(ur[k], wqj[k], hv);
            }
            s.pc[r][tid] = pcv + s.Sq[tid];
            s.S[tid] = sv + s.C2[tid];
            s.Hpc[r][tid] = hv + s.C1[tid];
        }
        if (tid < 16 && t + 1 < Tn)
            s.innov[tid] = s.y[tid] - mv(s.Hq, s.pm[r], tid) - s.dq[tid];
        __syncthreads();
    }

    // flush: accel term for step Tn-1 (G,Go = through Tn-2)
    if (Tn > 1) {
        const int fp = (Tn - 1) & 1, rp = fp ^ 1;
        float bc = s.fcb[rp][tid] - dot_rc4(s.bA[fp], s.M[fp], i, j);
        accel += (double)((s.G[tid] + s.Go[tid] - 0.5f * s.Fm[tid]) * bc);
    }

    // ---- epilogue ----
    g_OmP[tid] = s.Om_p[tid];
    g_om[tid] = s.om[tid];
    g_Om0[tid] = s.Om0[tid];
    {
        int fp = (Tn - 1) & 1;
        g_fcF[tid] = s.fcb[fp][tid];
        if (tid < 16) g_fmF[tid] = s.fmb[fp][tid];
    }
    double v = accel;
#pragma unroll
    for (int o = 16; o; o >>= 1) v += __shfl_xor_sync(0xffffffffu, v, o);
    if (lane == 0) s.dred[wid] = v;
    if (tid == 160) {
        s.dsc[0] = d0;              // SP = sum ldp_t
        s.dsc[1] = (double)lastld;  // ldp_N
    }
    __syncthreads();
    if (tid == 0) {
        double elem = 0.0;
#pragma unroll
        for (int w = 0; w < 8; w++) elem += s.dred[w];
        double SP = s.dsc[0], ldpN = s.dsc[1];
        double sumS = d0, ldsN = (double)lastld;
        double N = (double)(Tn - 1);
        double sumF = ldfc0 + (SP - ldpN) + (N - 1.0) * LDRqd - (sumS - ldsN);
        double FN = ldpN + LDRqd - ldsN;
        double sc = set_acc
                  + N * (K0d + 0.5 * LDSqd)
                  - 0.5 * SP
                  + 0.5 * sumF
                  + 0.5 * (16.0 * LOG2PI + FN) + 8.0
                  + elem;
        g_part[64] = sc;
    }
}

// ---------------- backward scan kernels ----------------
#define SEG 8
__global__ void __launch_bounds__(256, 1) lgq_scan1(int Tn) {
    const int b = blockIdx.x;
    const int lo = b * SEG;
    int hi = lo + SEG;
    if (hi > Tn) hi = Tn;
    __shared__ float R[256], Rn[256], bA[256];
    __shared__ float u[16], un[16], ba[16];
    const int tid = threadIdx.x;
    const int i = tid >> 4, j = tid & 15;
    R[tid] = (i == j) ? 1.f : 0.f;
    if (tid < 16) u[tid] = 0.f;
    __syncthreads();
    for (int t = hi - 1; t >= lo; t--) {
        g_Lr[t][tid] = R[tid];
        if (tid < 16) g_Lu[t][tid] = u[tid];
        if (t == 0) break;
        bA[tid] = g_P[t][tid];
        if (tid < 16) ba[tid] = g_ba[t][tid];
        __syncthreads();
        Rn[tid] = dot_rc(bA, R, i, j);
        if (tid < 16) un[tid] = ba[tid] + mv(bA, u, tid);
        __syncthreads();
        R[tid] = Rn[tid];
        if (tid < 16) u[tid] = un[tid];
        __syncthreads();
    }
    g_Sr[b][tid] = R[tid];
    if (tid < 16) g_Su[b][tid] = u[tid];
}

__global__ void __launch_bounds__(256, 1) lgq_scan2(int Tn) {
    const int nseg = (Tn + SEG - 1) / SEG;
    __shared__ float Gr[256], Gn[256], Sr[256];
    __shared__ float Gu[16], gn[16], Su[16];
    const int tid = threadIdx.x;
    const int i = tid >> 4, j = tid & 15;
    Gr[tid] = (i == j) ? 1.f : 0.f;
    if (tid < 16) Gu[tid] = 0.f;
    __syncthreads();
    for (int b = nseg - 1; b >= 0; b--) {
        g_Gr[b][tid] = Gr[tid];
        if (tid < 16) g_Gu[b][tid] = Gu[tid];
        if (b == 0) break;
        Sr[tid] = g_Sr[b][tid];
        if (tid < 16) Su[tid] = g_Su[b][tid];
        __syncthreads();
        Gn[tid] = dot_rc(Sr, Gr, i, j);
        if (tid < 16) gn[tid] = mv(Sr, Gu, tid) + Su[tid];
        __syncthreads();
        Gr[tid] = Gn[tid];
        if (tid < 16) Gu[tid] = gn[tid];
        __syncthreads();
    }
}

#define EVT 4
__global__ void __launch_bounds__(256, 1) lgq_scan3(
    const float* obs, const float* p_trans_w, const float* p_trans_b,
    const float* p_emis_w, const float* p_emis_b, const float* p_prior_mean,
    int Tn) {
    const int b = blockIdx.x;
    const int lo = b * EVT;
    int hi = lo + EVT;
    if (hi > Tn) hi = Tn;
    const int seg = lo / SEG;
    __shared__ float OmP[256], omm[256], Om0[256], Wp[256], Wep[256], fc[256], Gr[256];
    __shared__ float Lr[256], bA[256], Rf[256], Ai[256], A[256], Ao[256], AF[256], AoF[256];
    __shared__ float fm[16], Gu[16], Lu[16], bav[16], uf[16], Bv[16], Bo[16];
    __shared__ float cv[16], co[16], y[16], bp[16], ebp[16], ppm[16];
    __shared__ double dred[8];
    const int tid = threadIdx.x;
    const int i = tid >> 4, j = tid & 15;
    const int lane = tid & 31, wid = tid >> 5;

    OmP[tid] = g_OmP[tid];
    omm[tid] = g_om[tid];
    Om0[tid] = g_Om0[tid];
    Wp[tid] = p_trans_w[tid];
    Wep[tid] = p_emis_w[tid];
    fc[tid] = g_fcF[tid];
    Gr[tid] = g_Gr[seg][tid];
    if (tid < 16) {
        fm[tid] = g_fmF[tid];
        Gu[tid] = g_Gu[seg][tid];
        bp[tid] = p_trans_b[tid];
        ebp[tid] = p_emis_b[tid];
        ppm[tid] = p_prior_mean[tid];
    }
    __syncthreads();

    double acc = 0.0;
    for (int t = lo; t < hi; t++) {
        Lr[tid] = g_Lr[t][tid];
        bA[tid] = (t > 0) ? g_P[t][tid] : 0.f;
        if (tid < 16) {
            Lu[tid] = g_Lu[t][tid];
            bav[tid] = (t > 0) ? g_ba[t][tid] : 0.f;
            y[tid] = obs[t * 16 + tid];
        }
        __syncthreads();
        Rf[tid] = dot_rc(Lr, Gr, i, j);
        Ai[tid] = (t > 0) ? (dot_rc(Wp, bA, i, j) - ((i == j) ? 1.f : 0.f))
                          : ((i == j) ? 1.f : 0.f);
        if (tid < 16) {
            uf[tid] = mv(Lr, Gu, tid) + Lu[tid];
            Bv[tid] = (t > 0) ? (mv(Wp, bav, tid) + bp[tid]) : (-ppm[tid]);
        }
        __syncthreads();
        A[tid] = dot_rc(Ai, Rf, i, j);
        Ao[tid] = dot_rc(Wep, Rf, i, j);
        if (tid < 16) {
            Bv[tid] += mv(Ai, uf, tid);
            Bo[tid] = ebp[tid] - y[tid] + mv(Wep, uf, tid);
        }
        __syncthreads();
        AF[tid] = dot_rc(A, fc, i, j);
        AoF[tid] = dot_rc(Ao, fc, i, j);
        if (tid < 16) {
            cv[tid] = mv(A, fm, tid) + Bv[tid];
            co[tid] = mv(Ao, fm, tid) + Bo[tid];
        }
        __syncthreads();
        {
            const float* Om = (t == 0) ? Om0 : OmP;
            float val = Om[tid] * (dot_rc(AF, A, i, j) + cv[i] * cv[j])
                      + omm[tid] * (dot_rc(AoF, Ao, i, j) + co[i] * co[j]);
            acc += (double)val;
        }
        __syncthreads();
    }

    double v = acc;
#pragma unroll
    for (int o = 16; o; o >>= 1) v += __shfl_xor_sync(0xffffffffu, v, o);
    if (lane == 0) dred[wid] = v;
    __syncthreads();
    if (tid == 0) {
        double tot = 0.0;
#pragma unroll
        for (int w = 0; w < 8; w++) tot += dred[w];
        g_part[b] = tot;
    }
}

__global__ void lgq_fin(float* out, int Tn) {
    if (threadIdx.x == 0) {
        const int nblk = (Tn + EVT - 1) / EVT;
        double tot = g_part[64];
        for (int b = 0; b < nblk; b++) tot += g_part[b];
        out[0] = (float)tot;
    }
}

extern "C" void kernel_launch(void* const* d_in, const int* in_sizes, int n_in,
                              void* d_out, int out_size) {
    int Tn = in_sizes[0] / 16;
    if (Tn > TMAX) Tn = TMAX;
    const int nseg = (Tn + SEG - 1) / SEG;
    const int nblk = (Tn + EVT - 1) / EVT;
    lgq_fwd<<<1, 256>>>(
        (const float*)d_in[0], (const float*)d_in[1], (const float*)d_in[2],
        (const float*)d_in[3], (const float*)d_in[4], (const float*)d_in[5],
        (const float*)d_in[6], (const float*)d_in[7], (const float*)d_in[8],
        (const float*)d_in[9], (const float*)d_in[10], (const float*)d_in[11],
        (const float*)d_in[12], (const float*)d_in[13], (const float*)d_in[14],
        (const float*)d_in[15], (const float*)d_in[16], Tn);
    lgq_scan1<<<nseg, 256>>>(Tn);
    lgq_scan2<<<1, 256>>>(Tn);
    lgq_scan3<<<nblk, 256>>>(
        (const float*)d_in[0], (const float*)d_in[3], (const float*)d_in[4],
        (const float*)d_in[6], (const float*)d_in[7], (const float*)d_in[1], Tn);
    lgq_fin<<<1, 32>>>((float*)d_out, Tn);
}

// round 10
// speedup vs baseline: 3.5729x; 3.5581x over previous
#include <cuda_runtime.h>
#include <math.h>

#define TMAX 256
#define LOG2PI 1.8378770664093453

// ---------------- device scratch ----------------
__device__ float g_pA[TMAX][256], g_pC[TMAX][256], g_pJ[TMAX][256];
__device__ float g_pb[TMAX][16], g_pe[TMAX][16];
__device__ float g_XC[16][256], g_Xb[16][16];
__device__ float g_fc[TMAX][256], g_fm[TMAX][16];
__device__ float g_P[TMAX][256], g_ba[TMAX][16];
__device__ float g_bcov[TMAX][256], g_Q[TMAX][256];
__device__ float g_mP[TMAX][256], g_mQ[TMAX][256], g_mQo[TMAX][256];
__device__ float g_Gx[16][256], g_Gox[16][256];
__device__ float g_ldp[TMAX], g_lds[TMAX];
__device__ double g_accT[TMAX];
__device__ float g_Lr[TMAX][256], g_Lu[TMAX][16];
__device__ float g_Sr[32][256], g_Su[32][16];
__device__ float g_Gr[32][256], g_Gu[32][16];
__device__ float g_OmP[256], g_om[256], g_Om0[256], g_Em[256], g_Fm[256];
__device__ float g_Ac[256], g_Cc[256], g_Jc[256], g_Kc[256], g_Ec[256];
__device__ float g_cb0[16], g_e0v[16];
__device__ float g_fcF[256], g_fmF[16];
__device__ double g_sc[8];
__device__ double g_part[65];

__device__ __forceinline__ float dot_rc(const float* A, const float* B, int i, int j) {
    float s = 0.f;
#pragma unroll
    for (int k = 0; k < 16; k++) s = fmaf(A[i * 16 + k], B[k * 16 + j], s);
    return s;
}
__device__ __forceinline__ float dot_tc(const float* A, const float* B, int i, int j) {
    float s = 0.f;
#pragma unroll
    for (int k = 0; k < 16; k++) s = fmaf(A[k * 16 + i], B[k * 16 + j], s);
    return s;
}
__device__ __forceinline__ float dot_rt(const float* A, const float* B, int i, int j) {
    float s = 0.f;
#pragma unroll
    for (int k = 0; k < 16; k++) s = fmaf(A[i * 16 + k], B[j * 16 + k], s);
    return s;
}
__device__ __forceinline__ float mv(const float* M, const float* v, int r) {
    float s = 0.f;
#pragma unroll
    for (int k = 0; k < 16; k++) s = fmaf(M[r * 16 + k], v[k], s);
    return s;
}
__device__ __forceinline__ float mvT(const float* Mt, const float* v, int c) {
    float s = 0.f;
#pragma unroll
    for (int k = 0; k < 16; k++) s = fmaf(Mt[k * 16 + c], v[k], s);
    return s;
}

// Warp GJ solve A X = B; writes X^T to Xt; returns sum(log|pivot|).
__device__ __forceinline__ float warp_gj_solve(const float* Am, const float* Bm,
                                               float* Xt, int lane) {
    float a[16];
    const float* src = (lane < 16) ? (Am + lane) : (Bm + lane - 16);
#pragma unroll
    for (int r = 0; r < 16; r++) a[r] = src[r * 16];
    float mypiv = 1.f;
#pragma unroll
    for (int p = 0; p < 16; p++) {
        float f[16];
#pragma unroll
        for (int r = 0; r < 16; r++) f[r] = __shfl_sync(0xffffffffu, a[r], p);
        float x = f[p];
        if (lane == p) mypiv = x;
        float r0;
        asm("rcp.approx.f32 %0, %1;" : "=f"(r0) : "f"(x));
        float pivinv = r0 * (2.0f - x * r0);
        a[p] *= pivinv;
#pragma unroll
        for (int r = 0; r < 16; r++)
            if (r != p) a[r] = fmaf(-f[r], a[p], a[r]);
    }
    float lg = __logf(fabsf(mypiv));
#pragma unroll
    for (int o = 16; o; o >>= 1) lg += __shfl_xor_sync(0xffffffffu, lg, o);
    if (lane >= 16) {
        float4* dst = reinterpret_cast<float4*>(Xt + (lane - 16) * 16);
        dst[0] = make_float4(a[0], a[1], a[2], a[3]);
        dst[1] = make_float4(a[4], a[5], a[6], a[7]);
        dst[2] = make_float4(a[8], a[9], a[10], a[11]);
        dst[3] = make_float4(a[12], a[13], a[14], a[15]);
    }
    return lg;
}

// ================= setup =================
__global__ void __launch_bounds__(256, 1) k_setup(
    const float* obs, const float* ppm_, const float* ppc, const float* wp,
    const float* pb_, const float* ptc, const float* wep, const float* peb,
    const float* pec, const float* qpm, const float* qpc, const float* wq_,
    const float* qb, const float* qtc, const float* hq_, const float* qeb,
    const float* qec, int Tn) {
    __shared__ float Wq[256], Sq[256], Hq[256], Rq[256], Wp[256], Wep[256];
    __shared__ float Id[256], B1[256], B2[256], Sm[256], Km[256];
    __shared__ float U1[256], Sc[256], V[256], Kc[256], Ec[256], IKH[256];
    __shared__ float bq[16], dq[16], pm0[16], innov[16], y0[16], c2v[16];
    const int tid = threadIdx.x, i = tid >> 4, j = tid & 15;
    const int lane = tid & 31, wid = tid >> 5;
    Wq[tid] = wq_[tid]; Sq[tid] = qtc[tid]; Hq[tid] = hq_[tid]; Rq[tid] = qec[tid];
    Wp[tid] = wp[tid]; Wep[tid] = wep[tid]; Id[tid] = (i == j) ? 1.f : 0.f;
    if (tid < 16) { bq[tid] = qb[tid]; dq[tid] = qeb[tid]; pm0[tid] = qpm[tid]; y0[tid] = obs[tid]; }
    __syncthreads();
    float LDp = 0.f, LDe = 0.f, LDpr = 0.f, LDSq = 0.f, LDRq = 0.f, ldqp = 0.f, ldS0 = 0.f;
    Sm[tid] = ptc[tid]; __syncthreads();
    if (wid == 0) LDp = warp_gj_solve(Sm, Id, Km, lane);
    __syncthreads();
    g_OmP[tid] = -0.5f * Km[tid];
    B1[tid] = dot_rc(Km, Wp, i, j); __syncthreads();
    g_Fm[tid] = dot_tc(Wp, B1, i, j);
    Sm[tid] = pec[tid]; __syncthreads();
    if (wid == 0) LDe = warp_gj_solve(Sm, Id, Km, lane);
    __syncthreads();
    { float o_ = -0.5f * Km[tid]; g_om[tid] = o_; B2[tid] = o_; }
    __syncthreads();
    B1[tid] = dot_rc(B2, Wep, i, j); __syncthreads();
    g_Em[tid] = dot_tc(Wep, B1, i, j);
    Sm[tid] = ppc[tid]; __syncthreads();
    if (wid == 0) LDpr = warp_gj_solve(Sm, Id, Km, lane);
    __syncthreads();
    g_Om0[tid] = -0.5f * Km[tid];
    Sm[tid] = qtc[tid]; __syncthreads();
    if (wid == 0) LDSq = warp_gj_solve(Sm, Id, Km, lane);
    __syncthreads();
    Sm[tid] = qec[tid]; __syncthreads();
    if (wid == 0) LDRq = warp_gj_solve(Sm, Id, Km, lane);
    __syncthreads();
    // t=0 update
    B2[tid] = qpc[tid]; __syncthreads();
    if (wid == 0) ldqp = warp_gj_solve(B2, Id, Km, lane);
    __syncthreads();
    B1[tid] = dot_rc(Hq, B2, i, j);  // Hpc
    if (tid < 16) innov[tid] = y0[tid] - mv(Hq, pm0, tid) - dq[tid];
    __syncthreads();
    Sm[tid] = dot_rt(B1, Hq, i, j) + Rq[tid]; __syncthreads();
    if (wid == 0) ldS0 = warp_gj_solve(Sm, B1, Km, lane);
    __syncthreads();
    g_pA[0][tid] = 0.f; g_pJ[0][tid] = 0.f;
    g_pC[0][tid] = B2[tid] - dot_rc(Km, B1, i, j);
    if (tid < 16) { g_pb[0][tid] = pm0[tid] + mv(Km, innov, tid); g_pe[0][tid] = 0.f; }
    // element constants
    U1[tid] = dot_rc(Hq, Sq, i, j);
    V[tid] = dot_rc(Hq, Wq, i, j);
    __syncthreads();
    Sc[tid] = dot_rt(U1, Hq, i, j) + Rq[tid]; __syncthreads();
    if (wid == 0) warp_gj_solve(Sc, U1, Kc, lane);  // Kc = Sq Hq^T Sc^-1
    __syncthreads();
    if (wid == 0) warp_gj_solve(Sc, V, Ec, lane);   // Ec = Wq^T Hq^T Sc^-1
    __syncthreads();
    IKH[tid] = Id[tid] - dot_rc(Kc, Hq, i, j);
    if (tid < 16) c2v[tid] = mv(Hq, bq, tid) + dq[tid];
    __syncthreads();
    g_Ac[tid] = dot_rc(IKH, Wq, i, j);
    g_Cc[tid] = dot_rc(IKH, Sq, i, j);
    g_Jc[tid] = dot_rc(Ec, V, i, j);
    g_Kc[tid] = Kc[tid]; g_Ec[tid] = Ec[tid];
    if (tid < 16) {
        g_cb0[tid] = mv(IKH, bq, tid) - mv(Kc, dq, tid);
        g_e0v[tid] = mv(Ec, c2v, tid);
    }
    if (tid == 0) {
        g_sc[0] = -0.5 * (16.0 * LOG2PI + (double)LDpr) - 0.5 * (16.0 * LOG2PI + (double)LDe);
        g_sc[1] = -8.0 * LOG2PI - 0.5 * (double)LDe - 0.5 * (double)LDp + 8.0;
        g_sc[2] = (double)ldqp + (double)LDRq - (double)ldS0;
        g_sc[3] = (double)LDSq;
        g_sc[4] = (double)LDRq;
    }
}

// ================= phase A: segment-local full-element prefixes =================
__global__ void __launch_bounds__(256, 1) k_elemA(const float* obs, int Tn) {
    __shared__ float Ac[256], Cc[256], Jc[256], Kc[256], Ec[256], Id[256];
    __shared__ float A[256], C[256], J[256];
    __shared__ float IpW[256], Zt[256], ZA[256], ZC[256], JA[256], Cw[256];
    __shared__ float cb0[16], e0v[16];
    __shared__ float bv[16], ev[16], bt[16], et[16], w1[16], vJ[16], zb[16], yv[16];
    const int tid = threadIdx.x, i = tid >> 4, j = tid & 15;
    const int lane = tid & 31, wid = tid >> 5;
    const int t0 = blockIdx.x * 16;
    if (t0 >= Tn) return;
    const int tend = min(t0 + 16, Tn);
    Ac[tid] = g_Ac[tid]; Cc[tid] = g_Cc[tid]; Jc[tid] = g_Jc[tid];
    Kc[tid] = g_Kc[tid]; Ec[tid] = g_Ec[tid]; Id[tid] = (i == j) ? 1.f : 0.f;
    if (tid < 16) { cb0[tid] = g_cb0[tid]; e0v[tid] = g_e0v[tid]; }
    __syncthreads();
    if (t0 == 0) {
        A[tid] = g_pA[0][tid]; C[tid] = g_pC[0][tid]; J[tid] = g_pJ[0][tid];
        if (tid < 16) { bv[tid] = g_pb[0][tid]; ev[tid] = g_pe[0][tid]; }
    } else {
        if (tid < 16) yv[tid] = obs[t0 * 16 + tid];
        __syncthreads();
        A[tid] = Ac[tid]; C[tid] = Cc[tid]; J[tid] = Jc[tid];
        if (tid < 16) { bv[tid] = cb0[tid] + mv(Kc, yv, tid); ev[tid] = mv(Ec, yv, tid) - e0v[tid]; }
        __syncthreads();
        g_pA[t0][tid] = A[tid]; g_pC[t0][tid] = C[tid]; g_pJ[t0][tid] = J[tid];
        if (tid < 16) { g_pb[t0][tid] = bv[tid]; g_pe[t0][tid] = ev[tid]; }
    }
    __syncthreads();
    for (int t = t0 + 1; t < tend; t++) {
        if (tid < 16) yv[tid] = obs[t * 16 + tid];
        IpW[tid] = Id[tid] + dot_rc(C, Jc, i, j);
        __syncthreads();
        if (tid < 16) bt[tid] = cb0[tid] + mv(Kc, yv, tid);
        else if (tid < 32) et[tid - 16] = mv(Ec, yv, tid - 16) - e0v[tid - 16];
        __syncthreads();
        if (wid == 0) {
            warp_gj_solve(IpW, Id, Zt, lane);  // Zt = Z^T
        } else if (wid == 1) {
            if (lane < 16) w1[lane] = bv[lane] + mv(C, et, lane);
            else vJ[lane - 16] = mv(Jc, bv, lane - 16);
        } else if (wid != 4) {
            const int h = (wid < 4) ? (tid - 64) : (tid - 96);  // 0..159
            for (int e = h; e < 256; e += 160)
                JA[e] = dot_rc(Jc, A, e >> 4, e & 15);
        }
        __syncthreads();
        ZA[tid] = dot_tc(Zt, A, i, j);
        ZC[tid] = dot_tc(Zt, C, i, j);
        if (tid < 16) zb[tid] = mvT(Zt, w1, tid);
        __syncthreads();
        {
            float na = dot_rc(Ac, ZA, i, j);
            float cw = dot_rc(Ac, ZC, i, j);
            float nj = dot_tc(ZA, JA, i, j) + J[tid];
            if (tid < 16) {
                float nb = mv(Ac, zb, tid) + bt[tid];
                float ne = 0.f;
#pragma unroll
                for (int k = 0; k < 16; k++) ne = fmaf(ZA[k * 16 + tid], et[k] - vJ[k], ne);
                bv[tid] = nb; ev[tid] = ne + ev[tid];
            }
            A[tid] = na; Cw[tid] = cw; J[tid] = nj;
        }
        __syncthreads();
        {
            float nc = dot_rt(Cw, Ac, i, j) + Cc[tid];
            C[tid] = nc;
            g_pA[t][tid] = A[tid]; g_pC[t][tid] = nc; g_pJ[t][tid] = J[tid];
            if (tid < 16) { g_pb[t][tid] = bv[tid]; g_pe[t][tid] = ev[tid]; }
        }
        __syncthreads();
    }
}

// ================= phase B: cross-segment (b,C) scan =================
__global__ void __launch_bounds__(256, 1) k_elemB(int Tn) {
    __shared__ float Cst[256], Aj[256], Cj[256], Jj[256], Id[256];
    __shared__ float IpW[256], Zt[256], ZC[256], Cw[256];
    __shared__ float bst[16], bj[16], ej[16], w1[16], zb[16];
    const int tid = threadIdx.x, i = tid >> 4, j = tid & 15;
    const int lane = tid & 31, wid = tid >> 5;
    const int nseg = (Tn + 15) / 16;
    Cst[tid] = 0.f; Id[tid] = (i == j) ? 1.f : 0.f;
    if (tid < 16) bst[tid] = 0.f;
    __syncthreads();
    for (int k = 0; k < nseg; k++) {
        g_XC[k][tid] = Cst[tid];
        if (tid < 16) g_Xb[k][tid] = bst[tid];
        if (k == nseg - 1) break;
        const int tt = min(16 * k + 15, Tn - 1);
        Aj[tid] = g_pA[tt][tid]; Cj[tid] = g_pC[tt][tid]; Jj[tid] = g_pJ[tt][tid];
        if (tid < 16) { bj[tid] = g_pb[tt][tid]; ej[tid] = g_pe[tt][tid]; }
        __syncthreads();
        IpW[tid] = Id[tid] + dot_rc(Cst, Jj, i, j);
        if (tid < 16) w1[tid] = bst[tid] + mv(Cst, ej, tid);
        __syncthreads();
        if (wid == 0) warp_gj_solve(IpW, Id, Zt, lane);
        __syncthreads();
        ZC[tid] = dot_tc(Zt, Cst, i, j);
        if (tid < 16) zb[tid] = mvT(Zt, w1, tid);
        __syncthreads();
        Cw[tid] = dot_rc(Aj, ZC, i, j);
        if (tid < 16) bst[tid] = mv(Aj, zb, tid) + bj[tid];
        __syncthreads();
        Cst[tid] = dot_rt(Cw, Aj, i, j) + Cj[tid];
        __syncthreads();
    }
}

// ================= phase C: per-t fc, fm =================
__global__ void __launch_bounds__(256, 1) k_elemC(int Tn) {
    const int t = blockIdx.x;
    if (t >= Tn) return;
    const int k = t >> 4;
    __shared__ float Ci[256], Aj[256], Cj[256], Jj[256], Id[256];
    __shared__ float IpW[256], Zt[256], ZC[256], Cw[256];
    __shared__ float bi[16], bj[16], ej[16], w1[16], zb[16], fmv[16];
    const int tid = threadIdx.x, i = tid >> 4, j = tid & 15;
    const int lane = tid & 31, wid = tid >> 5;
    Ci[tid] = g_XC[k][tid];
    Aj[tid] = g_pA[t][tid]; Cj[tid] = g_pC[t][tid]; Jj[tid] = g_pJ[t][tid];
    Id[tid] = (i == j) ? 1.f : 0.f;
    if (tid < 16) { bi[tid] = g_Xb[k][tid]; bj[tid] = g_pb[t][tid]; ej[tid] = g_pe[t][tid]; }
    __syncthreads();
    IpW[tid] = Id[tid] + dot_rc(Ci, Jj, i, j);
    if (tid < 16) w1[tid] = bi[tid] + mv(Ci, ej, tid);
    __syncthreads();
    if (wid == 0) warp_gj_solve(IpW, Id, Zt, lane);
    __syncthreads();
    ZC[tid] = dot_tc(Zt, Ci, i, j);
    if (tid < 16) zb[tid] = mvT(Zt, w1, tid);
    __syncthreads();
    Cw[tid] = dot_rc(Aj, ZC, i, j);
    if (tid < 16) fmv[tid] = mv(Aj, zb, tid) + bj[tid];
    __syncthreads();
    float fcv = dot_rt(Cw, Aj, i, j) + Cj[tid];
    g_fc[t][tid] = fcv;
    if (tid < 16) g_fm[t][tid] = fmv[tid];
    if (t == Tn - 1) {
        g_fcF[tid] = fcv;
        if (tid < 16) g_fmF[tid] = fmv[tid];
    }
}

// ================= phase D: per-t backward-message quantities =================
__global__ void __launch_bounds__(256, 1) k_phaseD(
    const float* wq_, const float* qtc, const float* hq_, const float* qec,
    const float* qb, const float* wp, int Tn) {
    const int t = blockIdx.x + 1;
    if (t >= Tn) return;
    __shared__ float Wq[256], Hq[256], Wp[256], OmP[256];
    __shared__ float fc[256], M[256], pcm[256], U[256], S2[256], bA[256], scr[256];
    __shared__ float t1[256], Z1[256];
    __shared__ float fm[16], pm[16], bqv[16];
    const int tid = threadIdx.x, i = tid >> 4, j = tid & 15;
    const int lane = tid & 31, wid = tid >> 5;
    Wq[tid] = wq_[tid]; Hq[tid] = hq_[tid]; Wp[tid] = wp[tid]; OmP[tid] = g_OmP[tid];
    fc[tid] = g_fc[t - 1][tid];
    if (tid < 16) { fm[tid] = g_fm[t - 1][tid]; bqv[tid] = qb[tid]; }
    __syncthreads();
    M[tid] = dot_rc(Wq, fc, i, j);
    if (tid < 16) pm[tid] = mv(Wq, fm, tid) + bqv[tid];
    __syncthreads();
    pcm[tid] = dot_rt(M, Wq, i, j) + qtc[tid];
    __syncthreads();
    U[tid] = dot_rc(Hq, pcm, i, j);
    __syncthreads();
    S2[tid] = dot_rt(U, Hq, i, j) + qec[tid];
    __syncthreads();
    if (wid == 0) {
        float ldp = warp_gj_solve(pcm, M, bA, lane);
        if (lane == 0) g_ldp[t] = ldp;
    } else if (wid == 5) {
        float lds = warp_gj_solve(S2, U, scr, lane);
        if (lane == 0) g_lds[t] = lds;
    }
    __syncthreads();
    t1[tid] = dot_rc(Wp, bA, i, j) - ((i == j) ? 1.f : 0.f);
    g_bcov[t][tid] = fc[tid] - dot_rc(bA, M, i, j);
    g_P[t][tid] = bA[tid];
    if (tid < 16) g_ba[t][tid] = fm[tid] - mv(bA, pm, tid);
    __syncthreads();
    Z1[tid] = dot_rc(OmP, t1, i, j);
    __syncthreads();
    g_Q[t][tid] = dot_tc(t1, Z1, i, j);
}

// ================= gram scans =================
__global__ void __launch_bounds__(256, 1) k_gramA(int Tn) {
    const int k = blockIdx.x;
    const int s0 = 16 * k + 1, N = Tn - 1;
    if (s0 > N) return;
    const int send = min(16 * k + 16, N);
    __shared__ float P[256], Q[256], Qo[256], bAs[256], Qs[256], Em[256], nP[256], Y[256], Yo[256];
    const int tid = threadIdx.x, i = tid >> 4, j = tid & 15;
    Em[tid] = g_Em[tid];
    P[tid] = g_P[s0][tid]; Q[tid] = g_Q[s0][tid]; Qo[tid] = Em[tid];
    __syncthreads();
    g_mP[s0][tid] = P[tid]; g_mQ[s0][tid] = Q[tid]; g_mQo[s0][tid] = Qo[tid];
    for (int s = s0 + 1; s <= send; s++) {
        bAs[tid] = g_P[s][tid]; Qs[tid] = g_Q[s][tid];
        __syncthreads();
        nP[tid] = dot_rc(P, bAs, i, j);
        Y[tid] = dot_rc(Q, bAs, i, j);
        Yo[tid] = dot_rc(Qo, bAs, i, j);
        __syncthreads();
        float q = dot_tc(bAs, Y, i, j) + Qs[tid];
        float qo = dot_tc(bAs, Yo, i, j) + Em[tid];
        P[tid] = nP[tid]; Q[tid] = q; Qo[tid] = qo;
        g_mP[s][tid] = nP[tid]; g_mQ[s][tid] = q; g_mQo[s][tid] = qo;
        __syncthreads();
    }
}

__global__ void __launch_bounds__(256, 1) k_gramB(int Tn) {
    __shared__ float G[256], Go[256], P[256], Qp[256], Qop[256], Y[256], Yo[256];
    const int tid = threadIdx.x, i = tid >> 4, j = tid & 15;
    const int N = Tn - 1;
    if (N < 1) return;
    const int nsg = (N + 15) / 16;
    G[tid] = g_Om0[tid]; Go[tid] = g_Em[tid];
    __syncthreads();
    for (int k = 0; k < nsg; k++) {
        g_Gx[k][tid] = G[tid]; g_Gox[k][tid] = Go[tid];
        if (k == nsg - 1) break;
        const int send = min(16 * k + 16, N);
        P[tid] = g_mP[send][tid]; Qp[tid] = g_mQ[send][tid]; Qop[tid] = g_mQo[send][tid];
        __syncthreads();
        Y[tid] = dot_rc(G, P, i, j);
        Yo[tid] = dot_rc(Go, P, i, j);
        __syncthreads();
        G[tid] = dot_tc(P, Y, i, j) + Qp[tid];
        Go[tid] = dot_tc(P, Yo, i, j) + Qop[tid];
        __syncthreads();
    }
}

__global__ void __launch_bounds__(256, 1) k_gramC(int Tn) {
    const int t = blockIdx.x + 1;
    if (t >= Tn) return;
    const int s = t - 1;
    __shared__ float G[256], Go[256], P[256], Y[256], Yo[256];
    __shared__ double red[8];
    const int tid = threadIdx.x, i = tid >> 4, j = tid & 15;
    const int lane = tid & 31, wid = tid >> 5;
    if (s == 0) {
        G[tid] = g_Om0[tid]; Go[tid] = g_Em[tid];
        __syncthreads();
    } else {
        const int k = (s - 1) >> 4;
        G[tid] = g_Gx[k][tid]; Go[tid] = g_Gox[k][tid];
        P[tid] = g_mP[s][tid];
        __syncthreads();
        Y[tid] = dot_rc(G, P, i, j);
        Yo[tid] = dot_rc(Go, P, i, j);
        __syncthreads();
        G[tid] = dot_tc(P, Y, i, j) + g_mQ[s][tid];
        Go[tid] = dot_tc(P, Yo, i, j) + g_mQo[s][tid];
        __syncthreads();
    }
    double v = (double)((G[tid] + Go[tid] - 0.5f * g_Fm[tid]) * g_bcov[t][tid]);
#pragma unroll
    for (int o = 16; o; o >>= 1) v += __shfl_xor_sync(0xffffffffu, v, o);
    if (lane == 0) red[wid] = v;
    __syncthreads();
    if (tid == 0) {
        double tot = 0.0;
#pragma unroll
        for (int w = 0; w < 8; w++) tot += red[w];
        g_accT[t] = tot;
    }
}

// ================= backward scans =================
#define SEG 8
__global__ void __launch_bounds__(256, 1) lgq_scan1(int Tn) {
    const int b = blockIdx.x, lo = b * SEG;
    int hi = min(lo + SEG, Tn);
    __shared__ float R[256], Rn[256], bA[256];
    __shared__ float u[16], un[16], ba[16];
    const int tid = threadIdx.x, i = tid >> 4, j = tid & 15;
    R[tid] = (i == j) ? 1.f : 0.f;
    if (tid < 16) u[tid] = 0.f;
    __syncthreads();
    for (int t = hi - 1; t >= lo; t--) {
        g_Lr[t][tid] = R[tid];
        if (tid < 16) g_Lu[t][tid] = u[tid];
        if (t == 0) break;
        bA[tid] = g_P[t][tid];
        if (tid < 16) ba[tid] = g_ba[t][tid];
        __syncthreads();
        Rn[tid] = dot_rc(bA, R, i, j);
        if (tid < 16) un[tid] = ba[tid] + mv(bA, u, tid);
        __syncthreads();
        R[tid] = Rn[tid];
        if (tid < 16) u[tid] = un[tid];
        __syncthreads();
    }
    g_Sr[b][tid] = R[tid];
    if (tid < 16) g_Su[b][tid] = u[tid];
}

__global__ void __launch_bounds__(256, 1) lgq_scan2(int Tn) {
    const int nseg = (Tn + SEG - 1) / SEG;
    __shared__ float Gr[256], Gn[256], Sr[256];
    __shared__ float Gu[16], gn[16], Su[16];
    const int tid = threadIdx.x, i = tid >> 4, j = tid & 15;
    Gr[tid] = (i == j) ? 1.f : 0.f;
    if (tid < 16) Gu[tid] = 0.f;
    __syncthreads();
    for (int b = nseg - 1; b >= 0; b--) {
        g_Gr[b][tid] = Gr[tid];
        if (tid < 16) g_Gu[b][tid] = Gu[tid];
        if (b == 0) break;
        Sr[tid] = g_Sr[b][tid];
        if (tid < 16) Su[tid] = g_Su[b][tid];
        __syncthreads();
        Gn[tid] = dot_rc(Sr, Gr, i, j);
        if (tid < 16) gn[tid] = mv(Sr, Gu, tid) + Su[tid];
        __syncthreads();
        Gr[tid] = Gn[tid];
        if (tid < 16) Gu[tid] = gn[tid];
        __syncthreads();
    }
}

#define EVT 4
__global__ void __launch_bounds__(256, 1) lgq_scan3(
    const float* obs, const float* wp, const float* pb_, const float* wep,
    const float* peb, const float* ppm_, int Tn) {
    const int b = blockIdx.x, lo = b * EVT;
    int hi = min(lo + EVT, Tn);
    const int seg = lo / SEG;
    __shared__ float OmP[256], omm[256], Om0[256], Wp[256], Wep[256], fc[256], Gr[256];
    __shared__ float Lr[256], bA[256], Rf[256], Ai[256], A[256], Ao[256], AF[256], AoF[256];
    __shared__ float fm[16], Gu[16], Lu[16], bav[16], uf[16], Bv[16], Bo[16];
    __shared__ float cv[16], co[16], y[16], bp[16], ebp[16], ppm[16];
    __shared__ double dred[8];
    const int tid = threadIdx.x, i = tid >> 4, j = tid & 15;
    const int lane = tid & 31, wid = tid >> 5;
    OmP[tid] = g_OmP[tid]; omm[tid] = g_om[tid]; Om0[tid] = g_Om0[tid];
    Wp[tid] = wp[tid]; Wep[tid] = wep[tid];
    fc[tid] = g_fcF[tid]; Gr[tid] = g_Gr[seg][tid];
    if (tid < 16) {
        fm[tid] = g_fmF[tid]; Gu[tid] = g_Gu[seg][tid];
        bp[tid] = pb_[tid]; ebp[tid] = peb[tid]; ppm[tid] = ppm_[tid];
    }
    __syncthreads();
    double acc = 0.0;
    for (int t = lo; t < hi; t++) {
        Lr[tid] = g_Lr[t][tid];
        bA[tid] = (t > 0) ? g_P[t][tid] : 0.f;
        if (tid < 16) {
            Lu[tid] = g_Lu[t][tid];
            bav[tid] = (t > 0) ? g_ba[t][tid] : 0.f;
            y[tid] = obs[t * 16 + tid];
        }
        __syncthreads();
        Rf[tid] = dot_rc(Lr, Gr, i, j);
        Ai[tid] = (t > 0) ? (dot_rc(Wp, bA, i, j) - ((i == j) ? 1.f : 0.f))
                          : ((i == j) ? 1.f : 0.f);
        if (tid < 16) {
            uf[tid] = mv(Lr, Gu, tid) + Lu[tid];
            Bv[tid] = (t > 0) ? (mv(Wp, bav, tid) + bp[tid]) : (-ppm[tid]);
        }
        __syncthreads();
        A[tid] = dot_rc(Ai, Rf, i, j);
        Ao[tid] = dot_rc(Wep, Rf, i, j);
        if (tid < 16) {
            Bv[tid] += mv(Ai, uf, tid);
            Bo[tid] = ebp[tid] - y[tid] + mv(Wep, uf, tid);
        }
        __syncthreads();
        AF[tid] = dot_rc(A, fc, i, j);
        AoF[tid] = dot_rc(Ao, fc, i, j);
        if (tid < 16) {
            cv[tid] = mv(A, fm, tid) + Bv[tid];
            co[tid] = mv(Ao, fm, tid) + Bo[tid];
        }
        __syncthreads();
        {
            const float* Om = (t == 0) ? Om0 : OmP;
            acc += (double)(Om[tid] * (dot_rc(AF, A, i, j) + cv[i] * cv[j])
                          + omm[tid] * (dot_rc(AoF, Ao, i, j) + co[i] * co[j]));
        }
        __syncthreads();
    }
    double v = acc;
#pragma unroll
    for (int o = 16; o; o >>= 1) v += __shfl_xor_sync(0xffffffffu, v, o);
    if (lane == 0) dred[wid] = v;
    __syncthreads();
    if (tid == 0) {
        double tot = 0.0;
#pragma unroll
        for (int w = 0; w < 8; w++) tot += dred[w];
        g_part[b] = tot;
    }
}

// ================= finalize =================
__global__ void k_fin(float* out, int Tn) {
    if (threadIdx.x != 0) return;
    const int N = Tn - 1;
    double SP = 0.0, sumS = 0.0;
    for (int t = 1; t <= N; t++) { SP += (double)g_ldp[t]; sumS += (double)g_lds[t]; }
    double ldpN = (N >= 1) ? (double)g_ldp[N] : 0.0;
    double ldsN = (N >= 1) ? (double)g_lds[N] : 0.0;
    double set_acc = g_sc[0], K0d = g_sc[1], ldfc0 = g_sc[2], LDSqd = g_sc[3], LDRqd = g_sc[4];
    double Nd = (double)N;
    double sumF = ldfc0 + (SP - ldpN) + (Nd - 1.0) * LDRqd - (sumS - ldsN);
    double FN = (N >= 1) ? (ldpN + LDRqd - ldsN) : ldfc0;
    double tot = set_acc + Nd * (K0d + 0.5 * LDSqd) - 0.5 * SP + 0.5 * sumF
               + 0.5 * (16.0 * LOG2PI + FN) + 8.0;
    for (int t = 1; t <= N; t++) tot += g_accT[t];
    const int nblk = (Tn + EVT - 1) / EVT;
    for (int b = 0; b < nblk; b++) tot += g_part[b];
    out[0] = (float)tot;
}

extern "C" void kernel_launch(void* const* d_in, const int* in_sizes, int n_in,
                              void* d_out, int out_size) {
    int Tn = in_sizes[0] / 16;
    if (Tn > TMAX) Tn = TMAX;
    const float* obs = (const float*)d_in[0];
    const float* ppm_ = (const float*)d_in[1];
    const float* ppc = (const float*)d_in[2];
    const float* wp = (const float*)d_in[3];
    const float* pb_ = (const float*)d_in[4];
    const float* ptc = (const float*)d_in[5];
    const float* wep = (const float*)d_in[6];
    const float* peb = (const float*)d_in[7];
    const float* pec = (const float*)d_in[8];
    const float* qpm = (const float*)d_in[9];
    const float* qpc = (const float*)d_in[10];
    const float* wq_ = (const float*)d_in[11];
    const float* qb = (const float*)d_in[12];
    const float* qtc = (const float*)d_in[13];
    const float* hq_ = (const float*)d_in[14];
    const float* qeb = (const float*)d_in[15];
    const float* qec = (const float*)d_in[16];
    const int nsegE = (Tn + 15) / 16;
    const int nseg1 = (Tn + SEG - 1) / SEG;
    const int nblk3 = (Tn + EVT - 1) / EVT;
    k_setup<<<1, 256>>>(obs, ppm_, ppc, wp, pb_, ptc, wep, peb, pec, qpm, qpc,
                        wq_, qb, qtc, hq_, qeb, qec, Tn);
    k_elemA<<<nsegE, 256>>>(obs, Tn);
    k_elemB<<<1, 256>>>(Tn);
    k_elemC<<<Tn, 256>>>(Tn);
    if (Tn > 1) {
        k_phaseD<<<Tn - 1, 256>>>(wq_, qtc, hq_, qec, qb, wp, Tn);
        k_gramA<<<nsegE, 256>>>(Tn);
        k_gramB<<<1, 256>>>(Tn);
        k_gramC<<<Tn - 1, 256>>>(Tn);
    }
    lgq_scan1<<<nseg1, 256>>>(Tn);
    lgq_scan2<<<1, 256>>>(Tn);
    lgq_scan3<<<nblk3, 256>>>(obs, wp, pb_, wep, peb, ppm_, Tn);
    k_fin<<<1, 32>>>((float*)d_out, Tn);
}

// round 11
// speedup vs baseline: 4.1200x; 1.1531x over previous
#include <cuda_runtime.h>
#include <math.h>

#define TMAX 256
#define LOG2PI 1.8378770664093453

// ---------------- device scratch ----------------
__device__ float g_pA[TMAX][256], g_pC[TMAX][256], g_pJ[TMAX][256];
__device__ float g_pb[TMAX][16], g_pe[TMAX][16];
__device__ float g_XC[16][256], g_Xb[16][16];
__device__ float g_P[TMAX][256], g_ba[TMAX][16];
__device__ float g_bcov[TMAX][256], g_Q[TMAX][256];
__device__ float g_mP[TMAX][256], g_mQ[TMAX][256], g_mQo[TMAX][256];
__device__ float g_Gx[16][256], g_Gox[16][256];
__device__ float g_ldp[TMAX], g_lds[TMAX];
__device__ double g_accT[TMAX];
__device__ float g_Lr[TMAX][256], g_Lu[TMAX][16];
__device__ float g_Sr[32][256], g_Su[32][16];
__device__ float g_Gr[32][256], g_Gu[32][16];
__device__ float g_OmP[256], g_om[256], g_Om0[256], g_Em[256], g_Fm[256];
__device__ float g_Ac[256], g_Cc[256], g_Jc[256], g_Kc[256], g_Ec[256];
__device__ float g_cb0[16], g_e0v[16];
__device__ float g_fcF[256], g_fmF[16];
__device__ double g_sc[8];

__device__ __forceinline__ float dot_rc(const float* A, const float* B, int i, int j) {
    float s = 0.f;
#pragma unroll
    for (int k = 0; k < 16; k++) s = fmaf(A[i * 16 + k], B[k * 16 + j], s);
    return s;
}
__device__ __forceinline__ float dot_tc(const float* A, const float* B, int i, int j) {
    float s = 0.f;
#pragma unroll
    for (int k = 0; k < 16; k++) s = fmaf(A[k * 16 + i], B[k * 16 + j], s);
    return s;
}
__device__ __forceinline__ float dot_rt(const float* A, const float* B, int i, int j) {
    float s = 0.f;
#pragma unroll
    for (int k = 0; k < 16; k++) s = fmaf(A[i * 16 + k], B[j * 16 + k], s);
    return s;
}
__device__ __forceinline__ float mv(const float* M, const float* v, int r) {
    float s = 0.f;
#pragma unroll
    for (int k = 0; k < 16; k++) s = fmaf(M[r * 16 + k], v[k], s);
    return s;
}
__device__ __forceinline__ float mvT(const float* Mt, const float* v, int c) {
    float s = 0.f;
#pragma unroll
    for (int k = 0; k < 16; k++) s = fmaf(Mt[k * 16 + c], v[k], s);
    return s;
}

// Warp GJ solve A X = B; writes X^T to Xt; returns sum(log|pivot|).
__device__ __forceinline__ float warp_gj_solve(const float* Am, const float* Bm,
                                               float* Xt, int lane) {
    float a[16];
    const float* src = (lane < 16) ? (Am + lane) : (Bm + lane - 16);
#pragma unroll
    for (int r = 0; r < 16; r++) a[r] = src[r * 16];
    float mypiv = 1.f;
#pragma unroll
    for (int p = 0; p < 16; p++) {
        float f[16];
#pragma unroll
        for (int r = 0; r < 16; r++) f[r] = __shfl_sync(0xffffffffu, a[r], p);
        float x = f[p];
        if (lane == p) mypiv = x;
        float r0;
        asm("rcp.approx.f32 %0, %1;" : "=f"(r0) : "f"(x));
        float pivinv = r0 * (2.0f - x * r0);
        a[p] *= pivinv;
#pragma unroll
        for (int r = 0; r < 16; r++)
            if (r != p) a[r] = fmaf(-f[r], a[p], a[r]);
    }
    float lg = __logf(fabsf(mypiv));
#pragma unroll
    for (int o = 16; o; o >>= 1) lg += __shfl_xor_sync(0xffffffffu, lg, o);
    if (lane >= 16) {
        float4* dst = reinterpret_cast<float4*>(Xt + (lane - 16) * 16);
        dst[0] = make_float4(a[0], a[1], a[2], a[3]);
        dst[1] = make_float4(a[4], a[5], a[6], a[7]);
        dst[2] = make_float4(a[8], a[9], a[10], a[11]);
        dst[3] = make_float4(a[12], a[13], a[14], a[15]);
    }
    return lg;
}

// ================= setup =================
__global__ void __launch_bounds__(256, 1) k_setup(
    const float* obs, const float* ppm_, const float* ppc, const float* wp,
    const float* pb_, const float* ptc, const float* wep, const float* peb,
    const float* pec, const float* qpm, const float* qpc, const float* wq_,
    const float* qb, const float* qtc, const float* hq_, const float* qeb,
    const float* qec, int Tn) {
    __shared__ float Wq[256], Sq[256], Hq[256], Rq[256], Wp[256], Wep[256];
    __shared__ float Id[256], B1[256], B2[256], Sm[256], Km[256];
    __shared__ float U1[256], Sc[256], V[256], Kc[256], Ec[256], IKH[256];
    __shared__ float bq[16], dq[16], pm0[16], innov[16], y0[16], c2v[16];
    const int tid = threadIdx.x, i = tid >> 4, j = tid & 15;
    const int lane = tid & 31, wid = tid >> 5;
    Wq[tid] = wq_[tid]; Sq[tid] = qtc[tid]; Hq[tid] = hq_[tid]; Rq[tid] = qec[tid];
    Wp[tid] = wp[tid]; Wep[tid] = wep[tid]; Id[tid] = (i == j) ? 1.f : 0.f;
    if (tid < 16) { bq[tid] = qb[tid]; dq[tid] = qeb[tid]; pm0[tid] = qpm[tid]; y0[tid] = obs[tid]; }
    __syncthreads();
    float LDp = 0.f, LDe = 0.f, LDpr = 0.f, LDSq = 0.f, LDRq = 0.f, ldqp = 0.f, ldS0 = 0.f;
    Sm[tid] = ptc[tid]; __syncthreads();
    if (wid == 0) LDp = warp_gj_solve(Sm, Id, Km, lane);
    __syncthreads();
    g_OmP[tid] = -0.5f * Km[tid];
    B1[tid] = dot_rc(Km, Wp, i, j); __syncthreads();
    g_Fm[tid] = dot_tc(Wp, B1, i, j);
    Sm[tid] = pec[tid]; __syncthreads();
    if (wid == 0) LDe = warp_gj_solve(Sm, Id, Km, lane);
    __syncthreads();
    { float o_ = -0.5f * Km[tid]; g_om[tid] = o_; B2[tid] = o_; }
    __syncthreads();
    B1[tid] = dot_rc(B2, Wep, i, j); __syncthreads();
    g_Em[tid] = dot_tc(Wep, B1, i, j);
    Sm[tid] = ppc[tid]; __syncthreads();
    if (wid == 0) LDpr = warp_gj_solve(Sm, Id, Km, lane);
    __syncthreads();
    g_Om0[tid] = -0.5f * Km[tid];
    Sm[tid] = qtc[tid]; __syncthreads();
    if (wid == 0) LDSq = warp_gj_solve(Sm, Id, Km, lane);
    __syncthreads();
    Sm[tid] = qec[tid]; __syncthreads();
    if (wid == 0) LDRq = warp_gj_solve(Sm, Id, Km, lane);
    __syncthreads();
    // t=0 Kalman update
    B2[tid] = qpc[tid]; __syncthreads();
    if (wid == 0) ldqp = warp_gj_solve(B2, Id, Km, lane);
    __syncthreads();
    B1[tid] = dot_rc(Hq, B2, i, j);
    if (tid < 16) innov[tid] = y0[tid] - mv(Hq, pm0, tid) - dq[tid];
    __syncthreads();
    Sm[tid] = dot_rt(B1, Hq, i, j) + Rq[tid]; __syncthreads();
    if (wid == 0) ldS0 = warp_gj_solve(Sm, B1, Km, lane);
    __syncthreads();
    g_pA[0][tid] = 0.f; g_pJ[0][tid] = 0.f;
    g_pC[0][tid] = B2[tid] - dot_rc(Km, B1, i, j);
    if (tid < 16) { g_pb[0][tid] = pm0[tid] + mv(Km, innov, tid); g_pe[0][tid] = 0.f; }
    // element constants
    U1[tid] = dot_rc(Hq, Sq, i, j);
    V[tid] = dot_rc(Hq, Wq, i, j);
    __syncthreads();
    Sc[tid] = dot_rt(U1, Hq, i, j) + Rq[tid]; __syncthreads();
    if (wid == 0) warp_gj_solve(Sc, U1, Kc, lane);
    __syncthreads();
    if (wid == 0) warp_gj_solve(Sc, V, Ec, lane);
    __syncthreads();
    IKH[tid] = Id[tid] - dot_rc(Kc, Hq, i, j);
    if (tid < 16) c2v[tid] = mv(Hq, bq, tid) + dq[tid];
    __syncthreads();
    g_Ac[tid] = dot_rc(IKH, Wq, i, j);
    g_Cc[tid] = dot_rc(IKH, Sq, i, j);
    g_Jc[tid] = dot_rc(Ec, V, i, j);
    g_Kc[tid] = Kc[tid]; g_Ec[tid] = Ec[tid];
    if (tid < 16) {
        g_cb0[tid] = mv(IKH, bq, tid) - mv(Kc, dq, tid);
        g_e0v[tid] = mv(Ec, c2v, tid);
    }
    if (tid == 0) {
        g_sc[0] = -0.5 * (16.0 * LOG2PI + (double)LDpr) - 0.5 * (16.0 * LOG2PI + (double)LDe);
        g_sc[1] = -8.0 * LOG2PI - 0.5 * (double)LDe - 0.5 * (double)LDp + 8.0;
        g_sc[2] = (double)ldqp + (double)LDRq - (double)ldS0;
        g_sc[3] = (double)LDSq;
        g_sc[4] = (double)LDRq;
    }
}

// ================= elemA: segment-local full-element prefixes =================
__global__ void __launch_bounds__(256, 1) k_elemA(const float* obs, int Tn) {
    __shared__ float Ac[256], Cc[256], Jc[256], Kc[256], Ec[256], Id[256];
    __shared__ float A[256], C[256], J[256];
    __shared__ float IpW[256], Zt[256], ZA[256], ZC[256], JA[256], Cw[256];
    __shared__ float cb0[16], e0v[16];
    __shared__ float bv[16], ev[16], bt[16], et[16], w1[16], vJ[16], zb[16], yv[16];
    const int tid = threadIdx.x, i = tid >> 4, j = tid & 15;
    const int lane = tid & 31, wid = tid >> 5;
    const int t0 = blockIdx.x * 16;
    if (t0 >= Tn) return;
    const int tend = min(t0 + 16, Tn);
    Ac[tid] = g_Ac[tid]; Cc[tid] = g_Cc[tid]; Jc[tid] = g_Jc[tid];
    Kc[tid] = g_Kc[tid]; Ec[tid] = g_Ec[tid]; Id[tid] = (i == j) ? 1.f : 0.f;
    if (tid < 16) { cb0[tid] = g_cb0[tid]; e0v[tid] = g_e0v[tid]; }
    __syncthreads();
    if (t0 == 0) {
        A[tid] = g_pA[0][tid]; C[tid] = g_pC[0][tid]; J[tid] = g_pJ[0][tid];
        if (tid < 16) { bv[tid] = g_pb[0][tid]; ev[tid] = g_pe[0][tid]; }
    } else {
        if (tid < 16) yv[tid] = obs[t0 * 16 + tid];
        __syncthreads();
        A[tid] = Ac[tid]; C[tid] = Cc[tid]; J[tid] = Jc[tid];
        if (tid < 16) { bv[tid] = cb0[tid] + mv(Kc, yv, tid); ev[tid] = mv(Ec, yv, tid) - e0v[tid]; }
        __syncthreads();
        g_pA[t0][tid] = A[tid]; g_pC[t0][tid] = C[tid]; g_pJ[t0][tid] = J[tid];
        if (tid < 16) { g_pb[t0][tid] = bv[tid]; g_pe[t0][tid] = ev[tid]; }
    }
    __syncthreads();
    for (int t = t0 + 1; t < tend; t++) {
        if (tid < 16) yv[tid] = obs[t * 16 + tid];
        IpW[tid] = Id[tid] + dot_rc(C, Jc, i, j);
        __syncthreads();
        if (tid < 16) bt[tid] = cb0[tid] + mv(Kc, yv, tid);
        else if (tid < 32) et[tid - 16] = mv(Ec, yv, tid - 16) - e0v[tid - 16];
        __syncthreads();
        if (wid == 0) {
            warp_gj_solve(IpW, Id, Zt, lane);
        } else if (wid == 1) {
            if (lane < 16) w1[lane] = bv[lane] + mv(C, et, lane);
            else vJ[lane - 16] = mv(Jc, bv, lane - 16);
        } else if (wid != 4) {
            const int h = (wid < 4) ? (tid - 64) : (tid - 96);
            for (int e = h; e < 256; e += 160)
                JA[e] = dot_rc(Jc, A, e >> 4, e & 15);
        }
        __syncthreads();
        ZA[tid] = dot_tc(Zt, A, i, j);
        ZC[tid] = dot_tc(Zt, C, i, j);
        if (tid < 16) zb[tid] = mvT(Zt, w1, tid);
        __syncthreads();
        {
            float na = dot_rc(Ac, ZA, i, j);
            float cw = dot_rc(Ac, ZC, i, j);
            float nj = dot_tc(ZA, JA, i, j) + J[tid];
            if (tid < 16) {
                float nb = mv(Ac, zb, tid) + bt[tid];
                float ne = 0.f;
#pragma unroll
                for (int k = 0; k < 16; k++) ne = fmaf(ZA[k * 16 + tid], et[k] - vJ[k], ne);
                bv[tid] = nb; ev[tid] = ne + ev[tid];
            }
            A[tid] = na; Cw[tid] = cw; J[tid] = nj;
        }
        __syncthreads();
        {
            float nc = dot_rt(Cw, Ac, i, j) + Cc[tid];
            C[tid] = nc;
            g_pA[t][tid] = A[tid]; g_pC[t][tid] = nc; g_pJ[t][tid] = J[tid];
            if (tid < 16) { g_pb[t][tid] = bv[tid]; g_pe[t][tid] = ev[tid]; }
        }
        __syncthreads();
    }
}

// ================= elemB: cross-segment (b,C) scan =================
__global__ void __launch_bounds__(256, 1) k_elemB(int Tn) {
    __shared__ float Cst[256], Aj[256], Cj[256], Jj[256], Id[256];
    __shared__ float IpW[256], Zt[256], ZC[256], Cw[256];
    __shared__ float bst[16], bj[16], ej[16], w1[16], zb[16];
    const int tid = threadIdx.x, i = tid >> 4, j = tid & 15;
    const int lane = tid & 31, wid = tid >> 5;
    const int nseg = (Tn + 15) / 16;
    Cst[tid] = 0.f; Id[tid] = (i == j) ? 1.f : 0.f;
    if (tid < 16) bst[tid] = 0.f;
    __syncthreads();
    for (int k = 0; k < nseg; k++) {
        g_XC[k][tid] = Cst[tid];
        if (tid < 16) g_Xb[k][tid] = bst[tid];
        if (k == nseg - 1) break;
        const int tt = min(16 * k + 15, Tn - 1);
        Aj[tid] = g_pA[tt][tid]; Cj[tid] = g_pC[tt][tid]; Jj[tid] = g_pJ[tt][tid];
        if (tid < 16) { bj[tid] = g_pb[tt][tid]; ej[tid] = g_pe[tt][tid]; }
        __syncthreads();
        IpW[tid] = Id[tid] + dot_rc(Cst, Jj, i, j);
        if (tid < 16) w1[tid] = bst[tid] + mv(Cst, ej, tid);
        __syncthreads();
        if (wid == 0) warp_gj_solve(IpW, Id, Zt, lane);
        __syncthreads();
        ZC[tid] = dot_tc(Zt, Cst, i, j);
        if (tid < 16) zb[tid] = mvT(Zt, w1, tid);
        __syncthreads();
        Cw[tid] = dot_rc(Aj, ZC, i, j);
        if (tid < 16) bst[tid] = mv(Aj, zb, tid) + bj[tid];
        __syncthreads();
        Cst[tid] = dot_rt(Cw, Aj, i, j) + Cj[tid];
        __syncthreads();
    }
}

// ================= elemCD: per-t fc,fm fused with step-(t+1) backward msg =================
__global__ void __launch_bounds__(256, 1) k_elemCD(
    const float* wq_, const float* qtc, const float* hq_, const float* qec,
    const float* qb, const float* wp, int Tn) {
    const int t = blockIdx.x;
    if (t >= Tn) return;
    const int kseg = t >> 4;
    __shared__ float Ci[256], Aj[256], Cj[256], Jj[256], Id[256];
    __shared__ float IpW[256], Zt[256], ZC[256], Cw[256], fc[256];
    __shared__ float M[256], pcm[256], U[256], S2[256], bA[256], scr[256], t1[256], Z1[256];
    __shared__ float bi[16], bj[16], ej[16], w1[16], zb[16], fmv[16], pm[16], bqv[16];
    const int tid = threadIdx.x, i = tid >> 4, j = tid & 15;
    const int lane = tid & 31, wid = tid >> 5;
    Ci[tid] = g_XC[kseg][tid];
    Aj[tid] = g_pA[t][tid]; Cj[tid] = g_pC[t][tid]; Jj[tid] = g_pJ[t][tid];
    Id[tid] = (i == j) ? 1.f : 0.f;
    if (tid < 16) { bi[tid] = g_Xb[kseg][tid]; bj[tid] = g_pb[t][tid]; ej[tid] = g_pe[t][tid]; }
    __syncthreads();
    IpW[tid] = Id[tid] + dot_rc(Ci, Jj, i, j);
    if (tid < 16) w1[tid] = bi[tid] + mv(Ci, ej, tid);
    __syncthreads();
    if (wid == 0) warp_gj_solve(IpW, Id, Zt, lane);
    __syncthreads();
    ZC[tid] = dot_tc(Zt, Ci, i, j);
    if (tid < 16) zb[tid] = mvT(Zt, w1, tid);
    __syncthreads();
    Cw[tid] = dot_rc(Aj, ZC, i, j);
    if (tid < 16) fmv[tid] = mv(Aj, zb, tid) + bj[tid];
    __syncthreads();
    fc[tid] = dot_rt(Cw, Aj, i, j) + Cj[tid];
    if (t == Tn - 1) {
        g_fcF[tid] = fc[tid];
        if (tid < 16) g_fmF[tid] = fmv[tid];
        return;  // block-uniform
    }
    // ---- phaseD for step tt = t+1, using in-shared fc, fmv ----
    const int tt = t + 1;
    __syncthreads();
    {
        // reuse Aj,Cj,Jj as Wq,Hq,Wp caches
        Aj[tid] = wq_[tid];   // Wq
        Cj[tid] = hq_[tid];   // Hq
        Jj[tid] = wp[tid];    // Wp
        Id[tid] = g_OmP[tid];
        if (tid < 16) bqv[tid] = qb[tid];
    }
    __syncthreads();
    M[tid] = dot_rc(Aj, fc, i, j);
    if (tid < 16) pm[tid] = mv(Aj, fmv, tid) + bqv[tid];
    __syncthreads();
    pcm[tid] = dot_rt(M, Aj, i, j) + qtc[tid];
    __syncthreads();
    U[tid] = dot_rc(Cj, pcm, i, j);
    __syncthreads();
    S2[tid] = dot_rt(U, Cj, i, j) + qec[tid];
    __syncthreads();
    if (wid == 0) {
        float ldp = warp_gj_solve(pcm, M, bA, lane);
        if (lane == 0) g_ldp[tt] = ldp;
    } else if (wid == 5) {
        float lds = warp_gj_solve(S2, U, scr, lane);
        if (lane == 0) g_lds[tt] = lds;
    }
    __syncthreads();
    t1[tid] = dot_rc(Jj, bA, i, j) - ((i == j) ? 1.f : 0.f);
    g_bcov[tt][tid] = fc[tid] - dot_rc(bA, M, i, j);
    g_P[tt][tid] = bA[tid];
    if (tid < 16) g_ba[tt][tid] = fmv[tid] - mv(bA, pm, tid);
    __syncthreads();
    Z1[tid] = dot_rc(Id, t1, i, j);  // OmP * t1
    __syncthreads();
    g_Q[tt][tid] = dot_tc(t1, Z1, i, j);
}

// ================= par1: gramA (blocks 0..15) ∥ scan1 (blocks 16..47) =================
#define SEG 8
__global__ void __launch_bounds__(256, 1) k_par1(int Tn, int nsegE) {
    const int tid = threadIdx.x, i = tid >> 4, j = tid & 15;
    if ((int)blockIdx.x < nsegE) {
        // ---- gramA ----
        const int k = blockIdx.x;
        const int s0 = 16 * k + 1, N = Tn - 1;
        if (s0 > N) return;
        const int send = min(16 * k + 16, N);
        __shared__ float P[256], Q[256], Qo[256], bAs[256], Qs[256], Em[256], nP[256], Y[256], Yo[256];
        Em[tid] = g_Em[tid];
        P[tid] = g_P[s0][tid]; Q[tid] = g_Q[s0][tid]; Qo[tid] = Em[tid];
        __syncthreads();
        g_mP[s0][tid] = P[tid]; g_mQ[s0][tid] = Q[tid]; g_mQo[s0][tid] = Qo[tid];
        for (int s = s0 + 1; s <= send; s++) {
            bAs[tid] = g_P[s][tid]; Qs[tid] = g_Q[s][tid];
            __syncthreads();
            nP[tid] = dot_rc(P, bAs, i, j);
            Y[tid] = dot_rc(Q, bAs, i, j);
            Yo[tid] = dot_rc(Qo, bAs, i, j);
            __syncthreads();
            float q = dot_tc(bAs, Y, i, j) + Qs[tid];
            float qo = dot_tc(bAs, Yo, i, j) + Em[tid];
            P[tid] = nP[tid]; Q[tid] = q; Qo[tid] = qo;
            g_mP[s][tid] = nP[tid]; g_mQ[s][tid] = q; g_mQo[s][tid] = qo;
            __syncthreads();
        }
    } else {
        // ---- scan1 ----
        const int b = blockIdx.x - nsegE;
        const int lo = b * SEG;
        int hi = min(lo + SEG, Tn);
        if (lo >= Tn) return;
        __shared__ float R[256], Rn[256], bA[256];
        __shared__ float u[16], un[16], ba[16];
        R[tid] = (i == j) ? 1.f : 0.f;
        if (tid < 16) u[tid] = 0.f;
        __syncthreads();
        for (int t = hi - 1; t >= lo; t--) {
            g_Lr[t][tid] = R[tid];
            if (tid < 16) g_Lu[t][tid] = u[tid];
            if (t == 0) break;
            bA[tid] = g_P[t][tid];
            if (tid < 16) ba[tid] = g_ba[t][tid];
            __syncthreads();
            Rn[tid] = dot_rc(bA, R, i, j);
            if (tid < 16) un[tid] = ba[tid] + mv(bA, u, tid);
            __syncthreads();
            R[tid] = Rn[tid];
            if (tid < 16) u[tid] = un[tid];
            __syncthreads();
        }
        g_Sr[b][tid] = R[tid];
        if (tid < 16) g_Su[b][tid] = u[tid];
    }
}

// ================= par2: gramB (block 0) ∥ scan2 (block 1) =================
__global__ void __launch_bounds__(256, 1) k_par2(int Tn) {
    const int tid = threadIdx.x, i = tid >> 4, j = tid & 15;
    if (blockIdx.x == 0) {
        // ---- gramB ----
        __shared__ float G[256], Go[256], P[256], Qp[256], Qop[256], Y[256], Yo[256];
        const int N = Tn - 1;
        if (N < 1) return;
        const int nsg = (N + 15) / 16;
        G[tid] = g_Om0[tid]; Go[tid] = g_Em[tid];
        __syncthreads();
        for (int k = 0; k < nsg; k++) {
            g_Gx[k][tid] = G[tid]; g_Gox[k][tid] = Go[tid];
            if (k == nsg - 1) break;
            const int send = min(16 * k + 16, N);
            P[tid] = g_mP[send][tid]; Qp[tid] = g_mQ[send][tid]; Qop[tid] = g_mQo[send][tid];
            __syncthreads();
            Y[tid] = dot_rc(G, P, i, j);
            Yo[tid] = dot_rc(Go, P, i, j);
            __syncthreads();
            G[tid] = dot_tc(P, Y, i, j) + Qp[tid];
            Go[tid] = dot_tc(P, Yo, i, j) + Qop[tid];
            __syncthreads();
        }
    } else {
        // ---- scan2 ----
        const int nseg = (Tn + SEG - 1) / SEG;
        __shared__ float Gr[256], Gn[256], Sr[256];
        __shared__ float Gu[16], gn[16], Su[16];
        Gr[tid] = (i == j) ? 1.f : 0.f;
        if (tid < 16) Gu[tid] = 0.f;
        __syncthreads();
        for (int b = nseg - 1; b >= 0; b--) {
            g_Gr[b][tid] = Gr[tid];
            if (tid < 16) g_Gu[b][tid] = Gu[tid];
            if (b == 0) break;
            Sr[tid] = g_Sr[b][tid];
            if (tid < 16) Su[tid] = g_Su[b][tid];
            __syncthreads();
            Gn[tid] = dot_rc(Sr, Gr, i, j);
            if (tid < 16) gn[tid] = mv(Sr, Gu, tid) + Su[tid];
            __syncthreads();
            Gr[tid] = Gn[tid];
            if (tid < 16) Gu[tid] = gn[tid];
            __syncthreads();
        }
    }
}

// ================= tail: gramC + scan3 fused, one block per t =================
__global__ void __launch_bounds__(256, 1) k_tail(
    const float* obs, const float* wp, const float* pb_, const float* wep,
    const float* peb, const float* ppm_, int Tn) {
    const int t = blockIdx.x;
    if (t >= Tn) return;
    __shared__ float OmP[256], omm[256], Om0[256], Wp[256], Wep[256], fc[256], Gr[256];
    __shared__ float Lr[256], bA[256], Rf[256], Ai[256], A[256], Ao[256], AF[256], AoF[256];
    __shared__ float G[256], Go[256], P[256], Y[256], Yo[256], Fm[256];
    __shared__ float fm[16], Gu[16], Lu[16], bav[16], uf[16], Bv[16], Bo[16];
    __shared__ float cv[16], co[16], y[16], bp[16], ebp[16], ppm[16];
    __shared__ double dred[8];
    const int tid = threadIdx.x, i = tid >> 4, j = tid & 15;
    const int lane = tid & 31, wid = tid >> 5;

    OmP[tid] = g_OmP[tid]; omm[tid] = g_om[tid]; Om0[tid] = g_Om0[tid];
    Wp[tid] = wp[tid]; Wep[tid] = wep[tid]; Fm[tid] = g_Fm[tid];
    fc[tid] = g_fcF[tid]; Gr[tid] = g_Gr[t / SEG][tid];
    Lr[tid] = g_Lr[t][tid];
    bA[tid] = (t > 0) ? g_P[t][tid] : 0.f;
    if (tid < 16) {
        fm[tid] = g_fmF[tid]; Gu[tid] = g_Gu[t / SEG][tid];
        bp[tid] = pb_[tid]; ebp[tid] = peb[tid]; ppm[tid] = ppm_[tid];
        Lu[tid] = g_Lu[t][tid];
        bav[tid] = (t > 0) ? g_ba[t][tid] : 0.f;
        y[tid] = obs[t * 16 + tid];
    }
    __syncthreads();

    double acc = 0.0;
    // ---- gram term for step t (uses G state through t-1) ----
    if (t >= 1) {
        const int s = t - 1;
        if (s == 0) {
            G[tid] = Om0[tid]; Go[tid] = g_Em[tid];
            __syncthreads();
        } else {
            const int k = (s - 1) >> 4;
            G[tid] = g_Gx[k][tid]; Go[tid] = g_Gox[k][tid];
            P[tid] = g_mP[s][tid];
            __syncthreads();
            Y[tid] = dot_rc(G, P, i, j);
            Yo[tid] = dot_rc(Go, P, i, j);
            __syncthreads();
            G[tid] = dot_tc(P, Y, i, j) + g_mQ[s][tid];
            Go[tid] = dot_tc(P, Yo, i, j) + g_mQo[s][tid];
            __syncthreads();
        }
        acc += (double)((G[tid] + Go[tid] - 0.5f * Fm[tid]) * g_bcov[t][tid]);
    }
    // ---- scan3 term for step t ----
    Rf[tid] = dot_rc(Lr, Gr, i, j);
    Ai[tid] = (t > 0) ? (dot_rc(Wp, bA, i, j) - ((i == j) ? 1.f : 0.f))
                      : ((i == j) ? 1.f : 0.f);
    if (tid < 16) {
        uf[tid] = mv(Lr, Gu, tid) + Lu[tid];
        Bv[tid] = (t > 0) ? (mv(Wp, bav, tid) + bp[tid]) : (-ppm[tid]);
    }
    __syncthreads();
    A[tid] = dot_rc(Ai, Rf, i, j);
    Ao[tid] = dot_rc(Wep, Rf, i, j);
    if (tid < 16) {
        Bv[tid] += mv(Ai, uf, tid);
        Bo[tid] = ebp[tid] - y[tid] + mv(Wep, uf, tid);
    }
    __syncthreads();
    AF[tid] = dot_rc(A, fc, i, j);
    AoF[tid] = dot_rc(Ao, fc, i, j);
    if (tid < 16) {
        cv[tid] = mv(A, fm, tid) + Bv[tid];
        co[tid] = mv(Ao, fm, tid) + Bo[tid];
    }
    __syncthreads();
    {
        const float* Om = (t == 0) ? Om0 : OmP;
        acc += (double)(Om[tid] * (dot_rc(AF, A, i, j) + cv[i] * cv[j])
                      + omm[tid] * (dot_rc(AoF, Ao, i, j) + co[i] * co[j]));
    }
    double v = acc;
#pragma unroll
    for (int o = 16; o; o >>= 1) v += __shfl_xor_sync(0xffffffffu, v, o);
    if (lane == 0) dred[wid] = v;
    __syncthreads();
    if (tid == 0) {
        double tot = 0.0;
#pragma unroll
        for (int w = 0; w < 8; w++) tot += dred[w];
        g_accT[t] = tot;
    }
}

// ================= finalize =================
__global__ void k_fin(float* out, int Tn) {
    if (threadIdx.x != 0) return;
    const int N = Tn - 1;
    double SP = 0.0, sumS = 0.0;
    for (int t = 1; t <= N; t++) { SP += (double)g_ldp[t]; sumS += (double)g_lds[t]; }
    double ldpN = (N >= 1) ? (double)g_ldp[N] : 0.0;
    double ldsN = (N >= 1) ? (double)g_lds[N] : 0.0;
    double set_acc = g_sc[0], K0d = g_sc[1], ldfc0 = g_sc[2], LDSqd = g_sc[3], LDRqd = g_sc[4];
    double Nd = (double)N;
    double sumF = ldfc0 + (SP - ldpN) + (Nd - 1.0) * LDRqd - (sumS - ldsN);
    double FN = (N >= 1) ? (ldpN + LDRqd - ldsN) : ldfc0;
    double tot = set_acc + Nd * (K0d + 0.5 * LDSqd) - 0.5 * SP + 0.5 * sumF
               + 0.5 * (16.0 * LOG2PI + FN) + 8.0;
    for (int t = 0; t < Tn; t++) tot += g_accT[t];
    out[0] = (float)tot;
}

extern "C" void kernel_launch(void* const* d_in, const int* in_sizes, int n_in,
                              void* d_out, int out_size) {
    int Tn = in_sizes[0] / 16;
    if (Tn > TMAX) Tn = TMAX;
    const float* obs = (const float*)d_in[0];
    const float* ppm_ = (const float*)d_in[1];
    const float* ppc = (const float*)d_in[2];
    const float* wp = (const float*)d_in[3];
    const float* pb_ = (const float*)d_in[4];
    const float* ptc = (const float*)d_in[5];
    const float* wep = (const float*)d_in[6];
    const float* peb = (const float*)d_in[7];
    const float* pec = (const float*)d_in[8];
    const float* qpm = (const float*)d_in[9];
    const float* qpc = (const float*)d_in[10];
    const float* wq_ = (const float*)d_in[11];
    const float* qb = (const float*)d_in[12];
    const float* qtc = (const float*)d_in[13];
    const float* hq_ = (const float*)d_in[14];
    const float* qeb = (const float*)d_in[15];
    const float* qec = (const float*)d_in[16];
    const int nsegE = (Tn + 15) / 16;
    const int nseg1 = (Tn + SEG - 1) / SEG;
    k_setup<<<1, 256>>>(obs, ppm_, ppc, wp, pb_, ptc, wep, peb, pec, qpm, qpc,
                        wq_, qb, qtc, hq_, qeb, qec, Tn);
    k_elemA<<<nsegE, 256>>>(obs, Tn);
    k_elemB<<<1, 256>>>(Tn);
    k_elemCD<<<Tn, 256>>>(wq_, qtc, hq_, qec, qb, wp, Tn);
    k_par1<<<nsegE + nseg1, 256>>>(Tn, nsegE);
    k_par2<<<2, 256>>>(Tn);
    k_tail<<<Tn, 256>>>(obs, wp, pb_, wep, peb, ppm_, Tn);
    k_fin<<<1, 32>>>((float*)d_out, Tn);
}

// round 12
// speedup vs baseline: 4.7501x; 1.1529x over previous
#include <cuda_runtime.h>
#include <math.h>

#define TMAX 256
#define LOG2PI 1.8378770664093453
#define SEGA 8   // elemA segment length
#define GRP 8    // segments per group

// ---------------- device scratch ----------------
__device__ float g_pA[TMAX][256], g_pC[TMAX][256], g_pJ[TMAX][256];
__device__ float g_pb[TMAX][16], g_pe[TMAX][16];
__device__ float g_lA[32][256], g_lC[32][256], g_lJ[32][256];
__device__ float g_lb[32][16], g_le[32][16];
__device__ float g_gA[4][256], g_gC[4][256], g_gJ[4][256];
__device__ float g_gb[4][16], g_ge[4][16];
__device__ float g_xC[4][256], g_xb[4][16];
__device__ float g_P[TMAX][256], g_ba[TMAX][16];
__device__ float g_bcov[TMAX][256], g_Q[TMAX][256];
__device__ float g_mP[TMAX][256], g_mQ[TMAX][256], g_mQo[TMAX][256];
__device__ float g_Gx[16][256], g_Gox[16][256];
__device__ float g_ldp[TMAX], g_lds[TMAX];
__device__ double g_accT[TMAX];
__device__ float g_Lr[TMAX][256], g_Lu[TMAX][16];
__device__ float g_Sr[32][256], g_Su[32][16];
__device__ float g_Gr[32][256], g_Gu[32][16];
__device__ float g_OmP[256], g_om[256], g_Om0[256], g_Em[256], g_Fm[256];
__device__ float g_Ac[256], g_Cc[256], g_Jc[256], g_Kc[256], g_Ec[256];
__device__ float g_cb0[16], g_e0v[16];
__device__ float g_fcF[256], g_fmF[16];
__device__ double g_sc[8];

__device__ __forceinline__ float dot_rc(const float* A, const float* B, int i, int j) {
    float s = 0.f;
#pragma unroll
    for (int k = 0; k < 16; k++) s = fmaf(A[i * 16 + k], B[k * 16 + j], s);
    return s;
}
__device__ __forceinline__ float dot_tc(const float* A, const float* B, int i, int j) {
    float s = 0.f;
#pragma unroll
    for (int k = 0; k < 16; k++) s = fmaf(A[k * 16 + i], B[k * 16 + j], s);
    return s;
}
__device__ __forceinline__ float dot_rt(const float* A, const float* B, int i, int j) {
    float s = 0.f;
#pragma unroll
    for (int k = 0; k < 16; k++) s = fmaf(A[i * 16 + k], B[j * 16 + k], s);
    return s;
}
__device__ __forceinline__ float mv(const float* M, const float* v, int r) {
    float s = 0.f;
#pragma unroll
    for (int k = 0; k < 16; k++) s = fmaf(M[r * 16 + k], v[k], s);
    return s;
}
__device__ __forceinline__ float mvT(const float* Mt, const float* v, int c) {
    float s = 0.f;
#pragma unroll
    for (int k = 0; k < 16; k++) s = fmaf(Mt[k * 16 + c], v[k], s);
    return s;
}

// Warp GJ solve A X = B; writes X^T to Xt; returns sum(log|pivot|).
__device__ __forceinline__ float warp_gj_solve(const float* Am, const float* Bm,
                                               float* Xt, int lane) {
    float a[16];
    const float* src = (lane < 16) ? (Am + lane) : (Bm + lane - 16);
#pragma unroll
    for (int r = 0; r < 16; r++) a[r] = src[r * 16];
    float mypiv = 1.f;
#pragma unroll
    for (int p = 0; p < 16; p++) {
        float f[16];
#pragma unroll
        for (int r = 0; r < 16; r++) f[r] = __shfl_sync(0xffffffffu, a[r], p);
        float x = f[p];
        if (lane == p) mypiv = x;
        float r0;
        asm("rcp.approx.f32 %0, %1;" : "=f"(r0) : "f"(x));
        float pivinv = r0 * (2.0f - x * r0);
        a[p] *= pivinv;
#pragma unroll
        for (int r = 0; r < 16; r++)
            if (r != p) a[r] = fmaf(-f[r], a[p], a[r]);
    }
    float lg = __logf(fabsf(mypiv));
#pragma unroll
    for (int o = 16; o; o >>= 1) lg += __shfl_xor_sync(0xffffffffu, lg, o);
    if (lane >= 16) {
        float4* dst = reinterpret_cast<float4*>(Xt + (lane - 16) * 16);
        dst[0] = make_float4(a[0], a[1], a[2], a[3]);
        dst[1] = make_float4(a[4], a[5], a[6], a[7]);
        dst[2] = make_float4(a[8], a[9], a[10], a[11]);
        dst[3] = make_float4(a[12], a[13], a[14], a[15]);
    }
    return lg;
}

// Full element compose: prefix (PA,PC,PJ,Pb,Pe) ∘ next (NA,NC,NJ,Nb,Ne) -> prefix.
// Temps: IpW, Zt, ZA, ZC (also reused as Cw), JA, w1, vJ, zb. Id = identity.
__device__ __forceinline__ void compose_full(
    float* PA, float* PC, float* PJ, float* Pb, float* Pe,
    const float* NA, const float* NC, const float* NJ, const float* Nb, const float* Ne,
    float* IpW, float* Zt, float* ZA, float* ZC, float* JA,
    float* w1, float* vJ, float* zb, const float* Id,
    int tid, int i, int j, int lane, int wid) {
    IpW[tid] = Id[tid] + dot_rc(PC, NJ, i, j);
    __syncthreads();
    if (wid == 0) {
        warp_gj_solve(IpW, Id, Zt, lane);
    } else if (wid == 1) {
        if (lane < 16) w1[lane] = Pb[lane] + mv(PC, Ne, lane);
        else vJ[lane - 16] = mv(NJ, Pb, lane - 16);
    } else if (wid != 4) {
        const int h = (wid < 4) ? (tid - 64) : (tid - 96);
        for (int e = h; e < 256; e += 160)
            JA[e] = dot_rc(NJ, PA, e >> 4, e & 15);
    }
    __syncthreads();
    ZA[tid] = dot_tc(Zt, PA, i, j);
    ZC[tid] = dot_tc(Zt, PC, i, j);
    if (tid < 16) zb[tid] = mvT(Zt, w1, tid);
    __syncthreads();
    float na = dot_rc(NA, ZA, i, j);
    float cw = dot_rc(NA, ZC, i, j);
    float nj = dot_tc(ZA, JA, i, j) + PJ[tid];
    float nb = 0.f, ne = 0.f;
    if (tid < 16) {
        nb = mv(NA, zb, tid) + Nb[tid];
#pragma unroll
        for (int k = 0; k < 16; k++) ne = fmaf(ZA[k * 16 + tid], Ne[k] - vJ[k], ne);
        ne += Pe[tid];
    }
    __syncthreads();
    PA[tid] = na;
    PJ[tid] = nj;
    ZC[tid] = cw;  // reuse as Cw
    if (tid < 16) { Pb[tid] = nb; Pe[tid] = ne; }
    __syncthreads();
    PC[tid] = dot_rt(ZC, NA, i, j) + NC[tid];
    __syncthreads();
}

// ================= setup =================
__global__ void __launch_bounds__(256, 1) k_setup(
    const float* obs, const float* ppm_, const float* ppc, const float* wp,
    const float* pb_, const float* ptc, const float* wep, const float* peb,
    const float* pec, const float* qpm, const float* qpc, const float* wq_,
    const float* qb, const float* qtc, const float* hq_, const float* qeb,
    const float* qec, int Tn) {
    __shared__ float Wq[256], Sq[256], Hq[256], Rq[256], Wp[256], Wep[256];
    __shared__ float Id[256], B1[256], B2[256], Sm[256], Km[256];
    __shared__ float U1[256], Sc[256], V[256], Kc[256], Ec[256], IKH[256];
    __shared__ float bq[16], dq[16], pm0[16], innov[16], y0[16], c2v[16];
    const int tid = threadIdx.x, i = tid >> 4, j = tid & 15;
    const int lane = tid & 31, wid = tid >> 5;
    Wq[tid] = wq_[tid]; Sq[tid] = qtc[tid]; Hq[tid] = hq_[tid]; Rq[tid] = qec[tid];
    Wp[tid] = wp[tid]; Wep[tid] = wep[tid]; Id[tid] = (i == j) ? 1.f : 0.f;
    if (tid < 16) { bq[tid] = qb[tid]; dq[tid] = qeb[tid]; pm0[tid] = qpm[tid]; y0[tid] = obs[tid]; }
    __syncthreads();
    float LDp = 0.f, LDe = 0.f, LDpr = 0.f, LDSq = 0.f, LDRq = 0.f, ldqp = 0.f, ldS0 = 0.f;
    Sm[tid] = ptc[tid]; __syncthreads();
    if (wid == 0) LDp = warp_gj_solve(Sm, Id, Km, lane);
    __syncthreads();
    g_OmP[tid] = -0.5f * Km[tid];
    B1[tid] = dot_rc(Km, Wp, i, j); __syncthreads();
    g_Fm[tid] = dot_tc(Wp, B1, i, j);
    Sm[tid] = pec[tid]; __syncthreads();
    if (wid == 0) LDe = warp_gj_solve(Sm, Id, Km, lane);
    __syncthreads();
    { float o_ = -0.5f * Km[tid]; g_om[tid] = o_; B2[tid] = o_; }
    __syncthreads();
    B1[tid] = dot_rc(B2, Wep, i, j); __syncthreads();
    g_Em[tid] = dot_tc(Wep, B1, i, j);
    Sm[tid] = ppc[tid]; __syncthreads();
    if (wid == 0) LDpr = warp_gj_solve(Sm, Id, Km, lane);
    __syncthreads();
    g_Om0[tid] = -0.5f * Km[tid];
    Sm[tid] = qtc[tid]; __syncthreads();
    if (wid == 0) LDSq = warp_gj_solve(Sm, Id, Km, lane);
    __syncthreads();
    Sm[tid] = qec[tid]; __syncthreads();
    if (wid == 0) LDRq = warp_gj_solve(Sm, Id, Km, lane);
    __syncthreads();
    // t=0 Kalman update
    B2[tid] = qpc[tid]; __syncthreads();
    if (wid == 0) ldqp = warp_gj_solve(B2, Id, Km, lane);
    __syncthreads();
    B1[tid] = dot_rc(Hq, B2, i, j);
    if (tid < 16) innov[tid] = y0[tid] - mv(Hq, pm0, tid) - dq[tid];
    __syncthreads();
    Sm[tid] = dot_rt(B1, Hq, i, j) + Rq[tid]; __syncthreads();
    if (wid == 0) ldS0 = warp_gj_solve(Sm, B1, Km, lane);
    __syncthreads();
    g_pA[0][tid] = 0.f; g_pJ[0][tid] = 0.f;
    g_pC[0][tid] = B2[tid] - dot_rc(Km, B1, i, j);
    if (tid < 16) { g_pb[0][tid] = pm0[tid] + mv(Km, innov, tid); g_pe[0][tid] = 0.f; }
    // element constants
    U1[tid] = dot_rc(Hq, Sq, i, j);
    V[tid] = dot_rc(Hq, Wq, i, j);
    __syncthreads();
    Sc[tid] = dot_rt(U1, Hq, i, j) + Rq[tid]; __syncthreads();
    if (wid == 0) warp_gj_solve(Sc, U1, Kc, lane);
    __syncthreads();
    if (wid == 0) warp_gj_solve(Sc, V, Ec, lane);
    __syncthreads();
    IKH[tid] = Id[tid] - dot_rc(Kc, Hq, i, j);
    if (tid < 16) c2v[tid] = mv(Hq, bq, tid) + dq[tid];
    __syncthreads();
    g_Ac[tid] = dot_rc(IKH, Wq, i, j);
    g_Cc[tid] = dot_rc(IKH, Sq, i, j);
    g_Jc[tid] = dot_rc(Ec, V, i, j);
    g_Kc[tid] = Kc[tid]; g_Ec[tid] = Ec[tid];
    if (tid < 16) {
        g_cb0[tid] = mv(IKH, bq, tid) - mv(Kc, dq, tid);
        g_e0v[tid] = mv(Ec, c2v, tid);
    }
    if (tid == 0) {
        g_sc[0] = -0.5 * (16.0 * LOG2PI + (double)LDpr) - 0.5 * (16.0 * LOG2PI + (double)LDe);
        g_sc[1] = -8.0 * LOG2PI - 0.5 * (double)LDe - 0.5 * (double)LDp + 8.0;
        g_sc[2] = (double)ldqp + (double)LDRq - (double)ldS0;
        g_sc[3] = (double)LDSq;
        g_sc[4] = (double)LDRq;
    }
}

// ================= elemA: 8-length segment prefixes =================
__global__ void __launch_bounds__(256, 1) k_elemA(const float* obs, int Tn) {
    __shared__ float Ac[256], Cc[256], Jc[256], Kc[256], Ec[256], Id[256];
    __shared__ float A[256], C[256], J[256];
    __shared__ float IpW[256], Zt[256], ZA[256], ZC[256], JA[256];
    __shared__ float cb0[16], e0v[16];
    __shared__ float bv[16], ev[16], bt[16], et[16], w1[16], vJ[16], zb[16], yv[16];
    const int tid = threadIdx.x, i = tid >> 4, j = tid & 15;
    const int lane = tid & 31, wid = tid >> 5;
    const int t0 = blockIdx.x * SEGA;
    if (t0 >= Tn) return;
    const int tend = min(t0 + SEGA, Tn);
    Ac[tid] = g_Ac[tid]; Cc[tid] = g_Cc[tid]; Jc[tid] = g_Jc[tid];
    Kc[tid] = g_Kc[tid]; Ec[tid] = g_Ec[tid]; Id[tid] = (i == j) ? 1.f : 0.f;
    if (tid < 16) { cb0[tid] = g_cb0[tid]; e0v[tid] = g_e0v[tid]; }
    __syncthreads();
    if (t0 == 0) {
        A[tid] = g_pA[0][tid]; C[tid] = g_pC[0][tid]; J[tid] = g_pJ[0][tid];
        if (tid < 16) { bv[tid] = g_pb[0][tid]; ev[tid] = g_pe[0][tid]; }
    } else {
        if (tid < 16) yv[tid] = obs[t0 * 16 + tid];
        __syncthreads();
        A[tid] = Ac[tid]; C[tid] = Cc[tid]; J[tid] = Jc[tid];
        if (tid < 16) { bv[tid] = cb0[tid] + mv(Kc, yv, tid); ev[tid] = mv(Ec, yv, tid) - e0v[tid]; }
        __syncthreads();
        g_pA[t0][tid] = A[tid]; g_pC[t0][tid] = C[tid]; g_pJ[t0][tid] = J[tid];
        if (tid < 16) { g_pb[t0][tid] = bv[tid]; g_pe[t0][tid] = ev[tid]; }
    }
    __syncthreads();
    for (int t = t0 + 1; t < tend; t++) {
        if (tid < 16) {
            float yy = obs[t * 16 + tid];
            bt[tid] = cb0[tid] + mv(Kc, yy == yy ? (yv[tid] = yy, yv) : yv, tid);
        }
        __syncthreads();
        if (tid < 16) bt[tid] = cb0[tid] + mv(Kc, yv, tid);
        else if (tid < 32) et[tid - 16] = mv(Ec, yv, tid - 16) - e0v[tid - 16];
        __syncthreads();
        compose_full(A, C, J, bv, ev, Ac, Cc, Jc, bt, et,
                     IpW, Zt, ZA, ZC, JA, w1, vJ, zb, Id, tid, i, j, lane, wid);
        g_pA[t][tid] = A[tid]; g_pC[t][tid] = C[tid]; g_pJ[t][tid] = J[tid];
        if (tid < 16) { g_pb[t][tid] = bv[tid]; g_pe[t][tid] = ev[tid]; }
        __syncthreads();
    }
}

// ================= elemB1: per-group exclusive scan over segment totals =================
__global__ void __launch_bounds__(256, 1) k_elemB1(int Tn) {
    __shared__ float A[256], C[256], J[256], Id[256];
    __shared__ float NA[256], NC[256], NJ[256];
    __shared__ float IpW[256], Zt[256], ZA[256], ZC[256], JA[256];
    __shared__ float bv[16], ev[16], Nb[16], Ne[16], w1[16], vJ[16], zb[16];
    const int tid = threadIdx.x, i = tid >> 4, j = tid & 15;
    const int lane = tid & 31, wid = tid >> 5;
    const int nsegA = (Tn + SEGA - 1) / SEGA;
    const int g = blockIdx.x;
    const int k0 = g * GRP;
    if (k0 >= nsegA) return;
    const int kend = min(k0 + GRP, nsegA);
    Id[tid] = (i == j) ? 1.f : 0.f;
    A[tid] = Id[tid]; C[tid] = 0.f; J[tid] = 0.f;
    if (tid < 16) { bv[tid] = 0.f; ev[tid] = 0.f; }
    __syncthreads();
    for (int k = k0; k < kend; k++) {
        // store exclusive prefix
        g_lA[k][tid] = A[tid]; g_lC[k][tid] = C[tid]; g_lJ[k][tid] = J[tid];
        if (tid < 16) { g_lb[k][tid] = bv[tid]; g_le[k][tid] = ev[tid]; }
        // load segment total
        const int tl = min(k * SEGA + SEGA - 1, Tn - 1);
        NA[tid] = g_pA[tl][tid]; NC[tid] = g_pC[tl][tid]; NJ[tid] = g_pJ[tl][tid];
        if (tid < 16) { Nb[tid] = g_pb[tl][tid]; Ne[tid] = g_pe[tl][tid]; }
        __syncthreads();
        compose_full(A, C, J, bv, ev, NA, NC, NJ, Nb, Ne,
                     IpW, Zt, ZA, ZC, JA, w1, vJ, zb, Id, tid, i, j, lane, wid);
    }
    // group total
    g_gA[g][tid] = A[tid]; g_gC[g][tid] = C[tid]; g_gJ[g][tid] = J[tid];
    if (tid < 16) { g_gb[g][tid] = bv[tid]; g_ge[g][tid] = ev[tid]; }
}

// ================= elemB2: (b,C) exclusive scan over group totals =================
__global__ void __launch_bounds__(256, 1) k_elemB2(int Tn) {
    __shared__ float Cst[256], Aj[256], Cj[256], Jj[256], Id[256];
    __shared__ float IpW[256], Zt[256], ZC[256], Cw[256];
    __shared__ float bst[16], bj[16], ej[16], w1[16], zb[16];
    const int tid = threadIdx.x, i = tid >> 4, j = tid & 15;
    const int lane = tid & 31, wid = tid >> 5;
    const int nsegA = (Tn + SEGA - 1) / SEGA;
    const int ngrp = (nsegA + GRP - 1) / GRP;
    Cst[tid] = 0.f; Id[tid] = (i == j) ? 1.f : 0.f;
    if (tid < 16) bst[tid] = 0.f;
    __syncthreads();
    for (int g = 0; g < ngrp; g++) {
        g_xC[g][tid] = Cst[tid];
        if (tid < 16) g_xb[g][tid] = bst[tid];
        if (g == ngrp - 1) break;
        Aj[tid] = g_gA[g][tid]; Cj[tid] = g_gC[g][tid]; Jj[tid] = g_gJ[g][tid];
        if (tid < 16) { bj[tid] = g_gb[g][tid]; ej[tid] = g_ge[g][tid]; }
        __syncthreads();
        IpW[tid] = Id[tid] + dot_rc(Cst, Jj, i, j);
        if (tid < 16) w1[tid] = bst[tid] + mv(Cst, ej, tid);
        __syncthreads();
        if (wid == 0) warp_gj_solve(IpW, Id, Zt, lane);
        __syncthreads();
        ZC[tid] = dot_tc(Zt, Cst, i, j);
        if (tid < 16) zb[tid] = mvT(Zt, w1, tid);
        __syncthreads();
        Cw[tid] = dot_rc(Aj, ZC, i, j);
        if (tid < 16) bst[tid] = mv(Aj, zb, tid) + bj[tid];
        __syncthreads();
        Cst[tid] = dot_rt(Cw, Aj, i, j) + Cj[tid];
        __syncthreads();
    }
}

// ================= elemCD: per-t double-compose -> fc,fm; fused phaseD(t+1) =================
__global__ void __launch_bounds__(256, 1) k_elemCD(
    const float* wq_, const float* qtc, const float* hq_, const float* qec,
    const float* qb, const float* wp, int Tn) {
    const int t = blockIdx.x;
    if (t >= Tn) return;
    const int kseg = t / SEGA, grp = kseg / GRP;
    __shared__ float CX[256], EA[256], EC[256], EJ[256], Id[256];
    __shared__ float IpW[256], Zt[256], ZC[256], Cw[256], fc[256];
    __shared__ float M[256], pcm[256], U[256], S2[256], bA[256], scr[256], t1[256], Z1[256];
    __shared__ float bX[16], Eb[16], Ee[16], w1[16], zb[16], fmv[16], pm[16], bqv[16];
    const int tid = threadIdx.x, i = tid >> 4, j = tid & 15;
    const int lane = tid & 31, wid = tid >> 5;
    Id[tid] = (i == j) ? 1.f : 0.f;
    // ---- compose1: X = Gexcl(grp) ∘ Lexcl(kseg)  [(b,C) only] ----
    CX[tid] = g_xC[grp][tid];
    EA[tid] = g_lA[kseg][tid]; EC[tid] = g_lC[kseg][tid]; EJ[tid] = g_lJ[kseg][tid];
    if (tid < 16) { bX[tid] = g_xb[grp][tid]; Eb[tid] = g_lb[kseg][tid]; Ee[tid] = g_le[kseg][tid]; }
    __syncthreads();
    IpW[tid] = Id[tid] + dot_rc(CX, EJ, i, j);
    if (tid < 16) w1[tid] = bX[tid] + mv(CX, Ee, tid);
    __syncthreads();
    if (wid == 0) warp_gj_solve(IpW, Id, Zt, lane);
    __syncthreads();
    ZC[tid] = dot_tc(Zt, CX, i, j);
    if (tid < 16) zb[tid] = mvT(Zt, w1, tid);
    __syncthreads();
    Cw[tid] = dot_rc(EA, ZC, i, j);
    if (tid < 16) fmv[tid] = mv(EA, zb, tid) + Eb[tid];  // temp bX'
    __syncthreads();
    {
        float cx = dot_rt(Cw, EA, i, j) + EC[tid];
        __syncthreads();
        CX[tid] = cx;
        if (tid < 16) bX[tid] = fmv[tid];
    }
    // ---- compose2: fc/fm = X ∘ E_t ----
    EA[tid] = g_pA[t][tid]; EC[tid] = g_pC[t][tid]; EJ[tid] = g_pJ[t][tid];
    if (tid < 16) { Eb[tid] = g_pb[t][tid]; Ee[tid] = g_pe[t][tid]; }
    __syncthreads();
    IpW[tid] = Id[tid] + dot_rc(CX, EJ, i, j);
    if (tid < 16) w1[tid] = bX[tid] + mv(CX, Ee, tid);
    __syncthreads();
    if (wid == 0) warp_gj_solve(IpW, Id, Zt, lane);
    __syncthreads();
    ZC[tid] = dot_tc(Zt, CX, i, j);
    if (tid < 16) zb[tid] = mvT(Zt, w1, tid);
    __syncthreads();
    Cw[tid] = dot_rc(EA, ZC, i, j);
    if (tid < 16) fmv[tid] = mv(EA, zb, tid) + Eb[tid];
    __syncthreads();
    fc[tid] = dot_rt(Cw, EA, i, j) + EC[tid];
    if (t == Tn - 1) {
        g_fcF[tid] = fc[tid];
        if (tid < 16) g_fmF[tid] = fmv[tid];
        return;  // block-uniform
    }
    // ---- phaseD for step tt = t+1 ----
    const int tt = t + 1;
    __syncthreads();
    EA[tid] = wq_[tid];   // Wq
    EC[tid] = hq_[tid];   // Hq
    EJ[tid] = wp[tid];    // Wp
    Id[tid] = g_OmP[tid];
    if (tid < 16) bqv[tid] = qb[tid];
    __syncthreads();
    M[tid] = dot_rc(EA, fc, i, j);
    if (tid < 16) pm[tid] = mv(EA, fmv, tid) + bqv[tid];
    __syncthreads();
    pcm[tid] = dot_rt(M, EA, i, j) + qtc[tid];
    __syncthreads();
    U[tid] = dot_rc(EC, pcm, i, j);
    __syncthreads();
    S2[tid] = dot_rt(U, EC, i, j) + qec[tid];
    __syncthreads();
    if (wid == 0) {
        float ldp = warp_gj_solve(pcm, M, bA, lane);
        if (lane == 0) g_ldp[tt] = ldp;
    } else if (wid == 5) {
        float lds = warp_gj_solve(S2, U, scr, lane);
        if (lane == 0) g_lds[tt] = lds;
    }
    __syncthreads();
    t1[tid] = dot_rc(EJ, bA, i, j) - ((i == j) ? 1.f : 0.f);
    g_bcov[tt][tid] = fc[tid] - dot_rc(bA, M, i, j);
    g_P[tt][tid] = bA[tid];
    if (tid < 16) g_ba[tt][tid] = fmv[tid] - mv(bA, pm, tid);
    __syncthreads();
    Z1[tid] = dot_rc(Id, t1, i, j);  // OmP * t1
    __syncthreads();
    g_Q[tt][tid] = dot_tc(t1, Z1, i, j);
}

// ================= par1: gramA ∥ scan1 =================
#define SEG 8
__global__ void __launch_bounds__(256, 1) k_par1(int Tn, int nsegG) {
    const int tid = threadIdx.x, i = tid >> 4, j = tid & 15;
    if ((int)blockIdx.x < nsegG) {
        const int k = blockIdx.x;
        const int s0 = 16 * k + 1, N = Tn - 1;
        if (s0 > N) return;
        const int send = min(16 * k + 16, N);
        __shared__ float P[256], Q[256], Qo[256], bAs[256], Qs[256], Em[256], nP[256], Y[256], Yo[256];
        Em[tid] = g_Em[tid];
        P[tid] = g_P[s0][tid]; Q[tid] = g_Q[s0][tid]; Qo[tid] = Em[tid];
        __syncthreads();
        g_mP[s0][tid] = P[tid]; g_mQ[s0][tid] = Q[tid]; g_mQo[s0][tid] = Qo[tid];
        for (int s = s0 + 1; s <= send; s++) {
            bAs[tid] = g_P[s][tid]; Qs[tid] = g_Q[s][tid];
            __syncthreads();
            nP[tid] = dot_rc(P, bAs, i, j);
            Y[tid] = dot_rc(Q, bAs, i, j);
            Yo[tid] = dot_rc(Qo, bAs, i, j);
            __syncthreads();
            float q = dot_tc(bAs, Y, i, j) + Qs[tid];
            float qo = dot_tc(bAs, Yo, i, j) + Em[tid];
            P[tid] = nP[tid]; Q[tid] = q; Qo[tid] = qo;
            g_mP[s][tid] = nP[tid]; g_mQ[s][tid] = q; g_mQo[s][tid] = qo;
            __syncthreads();
        }
    } else {
        const int b = blockIdx.x - nsegG;
        const int lo = b * SEG;
        int hi = min(lo + SEG, Tn);
        if (lo >= Tn) return;
        __shared__ float R[256], Rn[256], bA[256];
        __shared__ float u[16], un[16], ba[16];
        R[tid] = (i == j) ? 1.f : 0.f;
        if (tid < 16) u[tid] = 0.f;
        __syncthreads();
        for (int t = hi - 1; t >= lo; t--) {
            g_Lr[t][tid] = R[tid];
            if (tid < 16) g_Lu[t][tid] = u[tid];
            if (t == 0) break;
            bA[tid] = g_P[t][tid];
            if (tid < 16) ba[tid] = g_ba[t][tid];
            __syncthreads();
            Rn[tid] = dot_rc(bA, R, i, j);
            if (tid < 16) un[tid] = ba[tid] + mv(bA, u, tid);
            __syncthreads();
            R[tid] = Rn[tid];
            if (tid < 16) u[tid] = un[tid];
            __syncthreads();
        }
        g_Sr[b][tid] = R[tid];
        if (tid < 16) g_Su[b][tid] = u[tid];
    }
}

// ================= par2: gramB ∥ scan2 =================
__global__ void __launch_bounds__(256, 1) k_par2(int Tn) {
    const int tid = threadIdx.x, i = tid >> 4, j = tid & 15;
    if (blockIdx.x == 0) {
        __shared__ float G[256], Go[256], P[256], Qp[256], Qop[256], Y[256], Yo[256];
        const int N = Tn - 1;
        if (N < 1) return;
        const int nsg = (N + 15) / 16;
        G[tid] = g_Om0[tid]; Go[tid] = g_Em[tid];
        __syncthreads();
        for (int k = 0; k < nsg; k++) {
            g_Gx[k][tid] = G[tid]; g_Gox[k][tid] = Go[tid];
            if (k == nsg - 1) break;
            const int send = min(16 * k + 16, N);
            P[tid] = g_mP[send][tid]; Qp[tid] = g_mQ[send][tid]; Qop[tid] = g_mQo[send][tid];
            __syncthreads();
            Y[tid] = dot_rc(G, P, i, j);
            Yo[tid] = dot_rc(Go, P, i, j);
            __syncthreads();
            G[tid] = dot_tc(P, Y, i, j) + Qp[tid];
            Go[tid] = dot_tc(P, Yo, i, j) + Qop[tid];
            __syncthreads();
        }
    } else {
        const int nseg = (Tn + SEG - 1) / SEG;
        __shared__ float Gr[256], Gn[256], Sr[256];
        __shared__ float Gu[16], gn[16], Su[16];
        Gr[tid] = (i == j) ? 1.f : 0.f;
        if (tid < 16) Gu[tid] = 0.f;
        __syncthreads();
        for (int b = nseg - 1; b >= 0; b--) {
            g_Gr[b][tid] = Gr[tid];
            if (tid < 16) g_Gu[b][tid] = Gu[tid];
            if (b == 0) break;
            Sr[tid] = g_Sr[b][tid];
            if (tid < 16) Su[tid] = g_Su[b][tid];
            __syncthreads();
            Gn[tid] = dot_rc(Sr, Gr, i, j);
            if (tid < 16) gn[tid] = mv(Sr, Gu, tid) + Su[tid];
            __syncthreads();
            Gr[tid] = Gn[tid];
            if (tid < 16) Gu[tid] = gn[tid];
            __syncthreads();
        }
    }
}

// ================= tail: gramC + scan3 fused =================
__global__ void __launch_bounds__(256, 1) k_tail(
    const float* obs, const float* wp, const float* pb_, const float* wep,
    const float* peb, const float* ppm_, int Tn) {
    const int t = blockIdx.x;
    if (t >= Tn) return;
    __shared__ float OmP[256], omm[256], Om0[256], Wp[256], Wep[256], fc[256], Gr[256];
    __shared__ float Lr[256], bA[256], Rf[256], Ai[256], A[256], Ao[256], AF[256], AoF[256];
    __shared__ float G[256], Go[256], P[256], Y[256], Yo[256], Fm[256];
    __shared__ float fm[16], Gu[16], Lu[16], bav[16], uf[16], Bv[16], Bo[16];
    __shared__ float cv[16], co[16], y[16], bp[16], ebp[16], ppm[16];
    __shared__ double dred[8];
    const int tid = threadIdx.x, i = tid >> 4, j = tid & 15;
    const int lane = tid & 31, wid = tid >> 5;

    OmP[tid] = g_OmP[tid]; omm[tid] = g_om[tid]; Om0[tid] = g_Om0[tid];
    Wp[tid] = wp[tid]; Wep[tid] = wep[tid]; Fm[tid] = g_Fm[tid];
    fc[tid] = g_fcF[tid]; Gr[tid] = g_Gr[t / SEG][tid];
    Lr[tid] = g_Lr[t][tid];
    bA[tid] = (t > 0) ? g_P[t][tid] : 0.f;
    if (tid < 16) {
        fm[tid] = g_fmF[tid]; Gu[tid] = g_Gu[t / SEG][tid];
        bp[tid] = pb_[tid]; ebp[tid] = peb[tid]; ppm[tid] = ppm_[tid];
        Lu[tid] = g_Lu[t][tid];
        bav[tid] = (t > 0) ? g_ba[t][tid] : 0.f;
        y[tid] = obs[t * 16 + tid];
    }
    __syncthreads();

    double acc = 0.0;
    if (t >= 1) {
        const int s = t - 1;
        if (s == 0) {
            G[tid] = Om0[tid]; Go[tid] = g_Em[tid];
            __syncthreads();
        } else {
            const int k = (s - 1) >> 4;
            G[tid] = g_Gx[k][tid]; Go[tid] = g_Gox[k][tid];
            P[tid] = g_mP[s][tid];
            __syncthreads();
            Y[tid] = dot_rc(G, P, i, j);
            Yo[tid] = dot_rc(Go, P, i, j);
            __syncthreads();
            G[tid] = dot_tc(P, Y, i, j) + g_mQ[s][tid];
            Go[tid] = dot_tc(P, Yo, i, j) + g_mQo[s][tid];
            __syncthreads();
        }
        acc += (double)((G[tid] + Go[tid] - 0.5f * Fm[tid]) * g_bcov[t][tid]);
    }
    Rf[tid] = dot_rc(Lr, Gr, i, j);
    Ai[tid] = (t > 0) ? (dot_rc(Wp, bA, i, j) - ((i == j) ? 1.f : 0.f))
                      : ((i == j) ? 1.f : 0.f);
    if (tid < 16) {
        uf[tid] = mv(Lr, Gu, tid) + Lu[tid];
        Bv[tid] = (t > 0) ? (mv(Wp, bav, tid) + bp[tid]) : (-ppm[tid]);
    }
    __syncthreads();
    A[tid] = dot_rc(Ai, Rf, i, j);
    Ao[tid] = dot_rc(Wep, Rf, i, j);
    if (tid < 16) {
        Bv[tid] += mv(Ai, uf, tid);
        Bo[tid] = ebp[tid] - y[tid] + mv(Wep, uf, tid);
    }
    __syncthreads();
    AF[tid] = dot_rc(A, fc, i, j);
    AoF[tid] = dot_rc(Ao, fc, i, j);
    if (tid < 16) {
        cv[tid] = mv(A, fm, tid) + Bv[tid];
        co[tid] = mv(Ao, fm, tid) + Bo[tid];
    }
    __syncthreads();
    {
        const float* Om = (t == 0) ? Om0 : OmP;
        acc += (double)(Om[tid] * (dot_rc(AF, A, i, j) + cv[i] * cv[j])
                      + omm[tid] * (dot_rc(AoF, Ao, i, j) + co[i] * co[j]));
    }
    double v = acc;
#pragma unroll
    for (int o = 16; o; o >>= 1) v += __shfl_xor_sync(0xffffffffu, v, o);
    if (lane == 0) dred[wid] = v;
    __syncthreads();
    if (tid == 0) {
        double tot = 0.0;
#pragma unroll
        for (int w = 0; w < 8; w++) tot += dred[w];
        g_accT[t] = tot;
    }
}

// ================= finalize =================
__global__ void k_fin(float* out, int Tn) {
    if (threadIdx.x != 0) return;
    const int N = Tn - 1;
    double SP = 0.0, sumS = 0.0;
    for (int t = 1; t <= N; t++) { SP += (double)g_ldp[t]; sumS += (double)g_lds[t]; }
    double ldpN = (N >= 1) ? (double)g_ldp[N] : 0.0;
    double ldsN = (N >= 1) ? (double)g_lds[N] : 0.0;
    double set_acc = g_sc[0], K0d = g_sc[1], ldfc0 = g_sc[2], LDSqd = g_sc[3], LDRqd = g_sc[4];
    double Nd = (double)N;
    double sumF = ldfc0 + (SP - ldpN) + (Nd - 1.0) * LDRqd - (sumS - ldsN);
    double FN = (N >= 1) ? (ldpN + LDRqd - ldsN) : ldfc0;
    double tot = set_acc + Nd * (K0d + 0.5 * LDSqd) - 0.5 * SP + 0.5 * sumF
               + 0.5 * (16.0 * LOG2PI + FN) + 8.0;
    for (int t = 0; t < Tn; t++) tot += g_accT[t];
    out[0] = (float)tot;
}

extern "C" void kernel_launch(void* const* d_in, const int* in_sizes, int n_in,
                              void* d_out, int out_size) {
    int Tn = in_sizes[0] / 16;
    if (Tn > TMAX) Tn = TMAX;
    const float* obs = (const float*)d_in[0];
    const float* ppm_ = (const float*)d_in[1];
    const float* ppc = (const float*)d_in[2];
    const float* wp = (const float*)d_in[3];
    const float* pb_ = (const float*)d_in[4];
    const float* ptc = (const float*)d_in[5];
    const float* wep = (const float*)d_in[6];
    const float* peb = (const float*)d_in[7];
    const float* pec = (const float*)d_in[8];
    const float* qpm = (const float*)d_in[9];
    const float* qpc = (const float*)d_in[10];
    const float* wq_ = (const float*)d_in[11];
    const float* qb = (const float*)d_in[12];
    const float* qtc = (const float*)d_in[13];
    const float* hq_ = (const float*)d_in[14];
    const float* qeb = (const float*)d_in[15];
    const float* qec = (const float*)d_in[16];
    const int nsegA = (Tn + SEGA - 1) / SEGA;
    const int ngrp = (nsegA + GRP - 1) / GRP;
    const int nsegG = (Tn + 15) / 16;
    const int nseg1 = (Tn + SEG - 1) / SEG;
    k_setup<<<1, 256>>>(obs, ppm_, ppc, wp, pb_, ptc, wep, peb, pec, qpm, qpc,
                        wq_, qb, qtc, hq_, qeb, qec, Tn);
    k_elemA<<<nsegA, 256>>>(obs, Tn);
    k_elemB1<<<ngrp, 256>>>(Tn);
    k_elemB2<<<1, 256>>>(Tn);
    k_elemCD<<<Tn, 256>>>(wq_, qtc, hq_, qec, qb, wp, Tn);
    k_par1<<<nsegG + nseg1, 256>>>(Tn, nsegG);
    k_par2<<<2, 256>>>(Tn);
    k_tail<<<Tn, 256>>>(obs, wp, pb_, wep, peb, ppm_, Tn);
    k_fin<<<1, 32>>>((float*)d_out, Tn);
}

// round 13
// speedup vs baseline: 5.1288x; 1.0797x over previous
#include <cuda_runtime.h>
#include <math.h>

#define TMAX 256
#define LOG2PI 1.8378770664093453
#define SEGA 8   // elemA segment length
#define GRP 8    // segments per group

// ---------------- device scratch ----------------
__device__ float g_pA[TMAX][256], g_pC[TMAX][256], g_pJ[TMAX][256];
__device__ float g_pb[TMAX][16], g_pe[TMAX][16];
__device__ float g_lA[32][256], g_lC[32][256], g_lJ[32][256];
__device__ float g_lb[32][16], g_le[32][16];
__device__ float g_gA[4][256], g_gC[4][256], g_gJ[4][256];
__device__ float g_gb[4][16], g_ge[4][16];
__device__ float g_P[TMAX][256], g_ba[TMAX][16];
__device__ float g_bcov[TMAX][256], g_Q[TMAX][256];
__device__ float g_mP[TMAX][256], g_mQ[TMAX][256], g_mQo[TMAX][256];
__device__ float g_Gx[16][256], g_Gox[16][256];
__device__ float g_ldp[TMAX], g_lds[TMAX];
__device__ double g_accT[TMAX];
__device__ float g_Lr[TMAX][256], g_Lu[TMAX][16];
__device__ float g_Sr[32][256], g_Su[32][16];
__device__ float g_Gr[32][256], g_Gu[32][16];
__device__ float g_OmP[256], g_om[256], g_Om0[256], g_Em[256], g_Fm[256];
__device__ float g_Ac[256], g_Cc[256], g_Jc[256], g_Kc[256], g_Ec[256];
__device__ float g_cb0[16], g_e0v[16];
__device__ float g_fcF[256], g_fmF[16];
__device__ double g_sc[8];

__device__ __forceinline__ float dot_rc(const float* A, const float* B, int i, int j) {
    float s = 0.f;
#pragma unroll
    for (int k = 0; k < 16; k++) s = fmaf(A[i * 16 + k], B[k * 16 + j], s);
    return s;
}
__device__ __forceinline__ float dot_tc(const float* A, const float* B, int i, int j) {
    float s = 0.f;
#pragma unroll
    for (int k = 0; k < 16; k++) s = fmaf(A[k * 16 + i], B[k * 16 + j], s);
    return s;
}
__device__ __forceinline__ float dot_rt(const float* A, const float* B, int i, int j) {
    float s = 0.f;
#pragma unroll
    for (int k = 0; k < 16; k++) s = fmaf(A[i * 16 + k], B[j * 16 + k], s);
    return s;
}
__device__ __forceinline__ float mv(const float* M, const float* v, int r) {
    float s = 0.f;
#pragma unroll
    for (int k = 0; k < 16; k++) s = fmaf(M[r * 16 + k], v[k], s);
    return s;
}
__device__ __forceinline__ float mvT(const float* Mt, const float* v, int c) {
    float s = 0.f;
#pragma unroll
    for (int k = 0; k < 16; k++) s = fmaf(Mt[k * 16 + c], v[k], s);
    return s;
}

// Warp GJ solve A X = B; writes X^T to Xt; returns sum(log|pivot|).
__device__ __forceinline__ float warp_gj_solve(const float* Am, const float* Bm,
                                               float* Xt, int lane) {
    float a[16];
    const float* src = (lane < 16) ? (Am + lane) : (Bm + lane - 16);
#pragma unroll
    for (int r = 0; r < 16; r++) a[r] = src[r * 16];
    float mypiv = 1.f;
#pragma unroll
    for (int p = 0; p < 16; p++) {
        float f[16];
#pragma unroll
        for (int r = 0; r < 16; r++) f[r] = __shfl_sync(0xffffffffu, a[r], p);
        float x = f[p];
        if (lane == p) mypiv = x;
        float r0;
        asm("rcp.approx.f32 %0, %1;" : "=f"(r0) : "f"(x));
        float pivinv = r0 * (2.0f - x * r0);
        a[p] *= pivinv;
#pragma unroll
        for (int r = 0; r < 16; r++)
            if (r != p) a[r] = fmaf(-f[r], a[p], a[r]);
    }
    float lg = __logf(fabsf(mypiv));
#pragma unroll
    for (int o = 16; o; o >>= 1) lg += __shfl_xor_sync(0xffffffffu, lg, o);
    if (lane >= 16) {
        float4* dst = reinterpret_cast<float4*>(Xt + (lane - 16) * 16);
        dst[0] = make_float4(a[0], a[1], a[2], a[3]);
        dst[1] = make_float4(a[4], a[5], a[6], a[7]);
        dst[2] = make_float4(a[8], a[9], a[10], a[11]);
        dst[3] = make_float4(a[12], a[13], a[14], a[15]);
    }
    return lg;
}

// Full element compose: prefix (PA,PC,PJ,Pb,Pe) ∘ next (NA,NC,NJ,Nb,Ne) -> prefix.
__device__ __forceinline__ void compose_full(
    float* PA, float* PC, float* PJ, float* Pb, float* Pe,
    const float* NA, const float* NC, const float* NJ, const float* Nb, const float* Ne,
    float* IpW, float* Zt, float* ZA, float* ZC, float* JA,
    float* w1, float* vJ, float* zb, const float* Id,
    int tid, int i, int j, int lane, int wid) {
    IpW[tid] = Id[tid] + dot_rc(PC, NJ, i, j);
    __syncthreads();
    if (wid == 0) {
        warp_gj_solve(IpW, Id, Zt, lane);
    } else if (wid == 1) {
        if (lane < 16) w1[lane] = Pb[lane] + mv(PC, Ne, lane);
        else vJ[lane - 16] = mv(NJ, Pb, lane - 16);
    } else if (wid != 4) {
        const int h = (wid < 4) ? (tid - 64) : (tid - 96);
        for (int e = h; e < 256; e += 160)
            JA[e] = dot_rc(NJ, PA, e >> 4, e & 15);
    }
    __syncthreads();
    ZA[tid] = dot_tc(Zt, PA, i, j);
    ZC[tid] = dot_tc(Zt, PC, i, j);
    if (tid < 16) zb[tid] = mvT(Zt, w1, tid);
    __syncthreads();
    float na = dot_rc(NA, ZA, i, j);
    float cw = dot_rc(NA, ZC, i, j);
    float nj = dot_tc(ZA, JA, i, j) + PJ[tid];
    float nb = 0.f, ne = 0.f;
    if (tid < 16) {
        nb = mv(NA, zb, tid) + Nb[tid];
#pragma unroll
        for (int k = 0; k < 16; k++) ne = fmaf(ZA[k * 16 + tid], Ne[k] - vJ[k], ne);
        ne += Pe[tid];
    }
    __syncthreads();
    PA[tid] = na;
    PJ[tid] = nj;
    ZC[tid] = cw;  // reuse as Cw
    if (tid < 16) { Pb[tid] = nb; Pe[tid] = ne; }
    __syncthreads();
    PC[tid] = dot_rt(ZC, NA, i, j) + NC[tid];
    __syncthreads();
}

// Light (b,C) compose: state (Cst,bst) ∘ next full element (from global) -> state.
__device__ __forceinline__ void light_compose(
    float* Cst, float* bst,
    const float* gA, const float* gC, const float* gJ,
    const float* gb, const float* ge,
    float* NA, float* NC, float* NJ, float* Nb, float* Ne,
    float* IpW, float* Zt, float* ZC, float* Cw, float* w1, float* zb,
    const float* Id, int tid, int i, int j, int lane, int wid) {
    NA[tid] = gA[tid]; NC[tid] = gC[tid]; NJ[tid] = gJ[tid];
    if (tid < 16) { Nb[tid] = gb[tid]; Ne[tid] = ge[tid]; }
    __syncthreads();
    IpW[tid] = Id[tid] + dot_rc(Cst, NJ, i, j);
    if (tid < 16) w1[tid] = bst[tid] + mv(Cst, Ne, tid);
    __syncthreads();
    if (wid == 0) warp_gj_solve(IpW, Id, Zt, lane);
    __syncthreads();
    ZC[tid] = dot_tc(Zt, Cst, i, j);
    if (tid < 16) zb[tid] = mvT(Zt, w1, tid);
    __syncthreads();
    Cw[tid] = dot_rc(NA, ZC, i, j);
    if (tid < 16) bst[tid] = mv(NA, zb, tid) + Nb[tid];
    __syncthreads();
    Cst[tid] = dot_rt(Cw, NA, i, j) + NC[tid];
    __syncthreads();
}

// ================= setup (parallel GJs) =================
__global__ void __launch_bounds__(256, 1) k_setup(
    const float* obs, const float* ppm_, const float* ppc, const float* wp,
    const float* pb_, const float* ptc, const float* wep, const float* peb,
    const float* pec, const float* qpm, const float* qpc, const float* wq_,
    const float* qb, const float* qtc, const float* hq_, const float* qeb,
    const float* qec, int Tn) {
    __shared__ float Wq[256], Sq[256], Hq[256], Rq[256], Wp[256], Wep[256], Id[256];
    __shared__ float MI[6][256], VI[6][256];
    __shared__ float Hpc[256], U1[256], V[256], S[256], Sc[256];
    __shared__ float Km[256], Kc[256], Ec[256], IKH[256], B1[256], t3[256];
    __shared__ float ldsh[8];
    __shared__ float bq[16], dq[16], pm0[16], innov[16], y0[16], c2v[16];
    const int tid = threadIdx.x, i = tid >> 4, j = tid & 15;
    const int lane = tid & 31, wid = tid >> 5;
    Wq[tid] = wq_[tid]; Sq[tid] = qtc[tid]; Hq[tid] = hq_[tid]; Rq[tid] = qec[tid];
    Wp[tid] = wp[tid]; Wep[tid] = wep[tid]; Id[tid] = (i == j) ? 1.f : 0.f;
    MI[0][tid] = ptc[tid]; MI[1][tid] = pec[tid]; MI[2][tid] = ppc[tid];
    MI[3][tid] = qtc[tid]; MI[4][tid] = qec[tid]; MI[5][tid] = qpc[tid];
    if (tid < 16) { bq[tid] = qb[tid]; dq[tid] = qeb[tid]; pm0[tid] = qpm[tid]; y0[tid] = obs[tid]; }
    __syncthreads();
    // 6 concurrent inverses
    if (wid < 6) {
        float ld = warp_gj_solve(MI[wid], Id, VI[wid], lane);
        if (lane == 0) ldsh[wid] = ld;
    }
    __syncthreads();
    // stage A
    g_OmP[tid] = -0.5f * VI[0][tid];
    g_om[tid] = -0.5f * VI[1][tid];
    g_Om0[tid] = -0.5f * VI[2][tid];
    B1[tid] = dot_rc(VI[0], Wp, i, j);           // invP · Wp
    t3[tid] = -0.5f * dot_rc(VI[1], Wep, i, j);  // om · Wep
    Hpc[tid] = dot_rc(Hq, MI[5], i, j);          // Hq · qpc
    U1[tid] = dot_rc(Hq, Sq, i, j);
    V[tid] = dot_rc(Hq, Wq, i, j);
    if (tid < 16) innov[tid] = y0[tid] - mv(Hq, pm0, tid) - dq[tid];
    __syncthreads();
    // stage B
    g_Fm[tid] = dot_tc(Wp, B1, i, j);
    g_Em[tid] = dot_tc(Wep, t3, i, j);
    S[tid] = dot_rt(Hpc, Hq, i, j) + Rq[tid];
    Sc[tid] = dot_rt(U1, Hq, i, j) + Rq[tid];
    __syncthreads();
    // 3 concurrent GJs
    if (wid == 0) {
        float ld = warp_gj_solve(S, Hpc, Km, lane);
        if (lane == 0) ldsh[6] = ld;
    } else if (wid == 2) {
        warp_gj_solve(Sc, U1, Kc, lane);
    } else if (wid == 5) {
        warp_gj_solve(Sc, V, Ec, lane);
    }
    __syncthreads();
    // stage C
    g_pA[0][tid] = 0.f; g_pJ[0][tid] = 0.f;
    g_pC[0][tid] = MI[5][tid] - dot_rc(Km, Hpc, i, j);
    IKH[tid] = Id[tid] - dot_rc(Kc, Hq, i, j);
    if (tid < 16) {
        c2v[tid] = mv(Hq, bq, tid) + dq[tid];
        g_pb[0][tid] = pm0[tid] + mv(Km, innov, tid);
        g_pe[0][tid] = 0.f;
    }
    __syncthreads();
    // stage D
    g_Ac[tid] = dot_rc(IKH, Wq, i, j);
    g_Cc[tid] = dot_rc(IKH, Sq, i, j);
    g_Jc[tid] = dot_rc(Ec, V, i, j);
    g_Kc[tid] = Kc[tid]; g_Ec[tid] = Ec[tid];
    if (tid < 16) {
        g_cb0[tid] = mv(IKH, bq, tid) - mv(Kc, dq, tid);
        g_e0v[tid] = mv(Ec, c2v, tid);
    }
    if (tid == 0) {
        double LDp = ldsh[0], LDe = ldsh[1], LDpr = ldsh[2];
        double LDSq = ldsh[3], LDRq = ldsh[4], ldqp = ldsh[5], ldS0 = ldsh[6];
        g_sc[0] = -0.5 * (16.0 * LOG2PI + LDpr) - 0.5 * (16.0 * LOG2PI + LDe);
        g_sc[1] = -8.0 * LOG2PI - 0.5 * LDe - 0.5 * LDp + 8.0;
        g_sc[2] = ldqp + LDRq - ldS0;
        g_sc[3] = LDSq;
        g_sc[4] = LDRq;
    }
}

// ================= elemA: 8-length segment prefixes =================
__global__ void __launch_bounds__(256, 1) k_elemA(const float* obs, int Tn) {
    __shared__ float Ac[256], Cc[256], Jc[256], Kc[256], Ec[256], Id[256];
    __shared__ float A[256], C[256], J[256];
    __shared__ float IpW[256], Zt[256], ZA[256], ZC[256], JA[256];
    __shared__ float cb0[16], e0v[16];
    __shared__ float bv[16], ev[16], bt[16], et[16], w1[16], vJ[16], zb[16], yv[16];
    const int tid = threadIdx.x, i = tid >> 4, j = tid & 15;
    const int lane = tid & 31, wid = tid >> 5;
    const int t0 = blockIdx.x * SEGA;
    if (t0 >= Tn) return;
    const int tend = min(t0 + SEGA, Tn);
    Ac[tid] = g_Ac[tid]; Cc[tid] = g_Cc[tid]; Jc[tid] = g_Jc[tid];
    Kc[tid] = g_Kc[tid]; Ec[tid] = g_Ec[tid]; Id[tid] = (i == j) ? 1.f : 0.f;
    if (tid < 16) { cb0[tid] = g_cb0[tid]; e0v[tid] = g_e0v[tid]; }
    __syncthreads();
    if (t0 == 0) {
        A[tid] = g_pA[0][tid]; C[tid] = g_pC[0][tid]; J[tid] = g_pJ[0][tid];
        if (tid < 16) { bv[tid] = g_pb[0][tid]; ev[tid] = g_pe[0][tid]; }
    } else {
        if (tid < 16) yv[tid] = obs[t0 * 16 + tid];
        __syncthreads();
        A[tid] = Ac[tid]; C[tid] = Cc[tid]; J[tid] = Jc[tid];
        if (tid < 16) { bv[tid] = cb0[tid] + mv(Kc, yv, tid); ev[tid] = mv(Ec, yv, tid) - e0v[tid]; }
        __syncthreads();
        g_pA[t0][tid] = A[tid]; g_pC[t0][tid] = C[tid]; g_pJ[t0][tid] = J[tid];
        if (tid < 16) { g_pb[t0][tid] = bv[tid]; g_pe[t0][tid] = ev[tid]; }
    }
    __syncthreads();
    for (int t = t0 + 1; t < tend; t++) {
        if (tid < 16) yv[tid] = obs[t * 16 + tid];
        __syncthreads();
        if (tid < 16) bt[tid] = cb0[tid] + mv(Kc, yv, tid);
        else if (tid < 32) et[tid - 16] = mv(Ec, yv, tid - 16) - e0v[tid - 16];
        __syncthreads();
        compose_full(A, C, J, bv, ev, Ac, Cc, Jc, bt, et,
                     IpW, Zt, ZA, ZC, JA, w1, vJ, zb, Id, tid, i, j, lane, wid);
        g_pA[t][tid] = A[tid]; g_pC[t][tid] = C[tid]; g_pJ[t][tid] = J[tid];
        if (tid < 16) { g_pb[t][tid] = bv[tid]; g_pe[t][tid] = ev[tid]; }
        __syncthreads();
    }
}

// ================= elemB1: per-group exclusive scan over segment totals =================
__global__ void __launch_bounds__(256, 1) k_elemB1(int Tn) {
    __shared__ float A[256], C[256], J[256], Id[256];
    __shared__ float NA[256], NC[256], NJ[256];
    __shared__ float IpW[256], Zt[256], ZA[256], ZC[256], JA[256];
    __shared__ float bv[16], ev[16], Nb[16], Ne[16], w1[16], vJ[16], zb[16];
    const int tid = threadIdx.x, i = tid >> 4, j = tid & 15;
    const int lane = tid & 31, wid = tid >> 5;
    const int nsegA = (Tn + SEGA - 1) / SEGA;
    const int g = blockIdx.x;
    const int k0 = g * GRP;
    if (k0 >= nsegA) return;
    const int kend = min(k0 + GRP, nsegA);
    Id[tid] = (i == j) ? 1.f : 0.f;
    A[tid] = Id[tid]; C[tid] = 0.f; J[tid] = 0.f;
    if (tid < 16) { bv[tid] = 0.f; ev[tid] = 0.f; }
    __syncthreads();
    for (int k = k0; k < kend; k++) {
        g_lA[k][tid] = A[tid]; g_lC[k][tid] = C[tid]; g_lJ[k][tid] = J[tid];
        if (tid < 16) { g_lb[k][tid] = bv[tid]; g_le[k][tid] = ev[tid]; }
        const int tl = min(k * SEGA + SEGA - 1, Tn - 1);
        NA[tid] = g_pA[tl][tid]; NC[tid] = g_pC[tl][tid]; NJ[tid] = g_pJ[tl][tid];
        if (tid < 16) { Nb[tid] = g_pb[tl][tid]; Ne[tid] = g_pe[tl][tid]; }
        __syncthreads();
        compose_full(A, C, J, bv, ev, NA, NC, NJ, Nb, Ne,
                     IpW, Zt, ZA, ZC, JA, w1, vJ, zb, Id, tid, i, j, lane, wid);
    }
    g_gA[g][tid] = A[tid]; g_gC[g][tid] = C[tid]; g_gJ[g][tid] = J[tid];
    if (tid < 16) { g_gb[g][tid] = bv[tid]; g_ge[g][tid] = ev[tid]; }
}

// ================= elemCD: per-t multi-compose -> fc,fm; fused phaseD(t+1) =================
__global__ void __launch_bounds__(256, 1) k_elemCD(
    const float* wq_, const float* qtc, const float* hq_, const float* qec,
    const float* qb, const float* wp, int Tn) {
    const int t = blockIdx.x;
    if (t >= Tn) return;
    const int kseg = t / SEGA, grp = kseg / GRP;
    __shared__ float Cst[256], Id[256];
    __shared__ float NA[256], NC[256], NJ[256];
    __shared__ float IpW[256], Zt[256], ZC[256], Cw[256], fc[256];
    __shared__ float M[256], pcm[256], U[256], S2[256], bA[256], scr[256], t1[256], Z1[256];
    __shared__ float bst[16], Nb[16], Ne[16], w1[16], zb[16], fmv[16], pm[16], bqv[16];
    const int tid = threadIdx.x, i = tid >> 4, j = tid & 15;
    const int lane = tid & 31, wid = tid >> 5;
    Id[tid] = (i == j) ? 1.f : 0.f;
    Cst[tid] = 0.f;
    if (tid < 16) bst[tid] = 0.f;
    __syncthreads();
    // group-level exclusive prefix (grp <= 3 composes)
    for (int g = 0; g < grp; g++)
        light_compose(Cst, bst, g_gA[g], g_gC[g], g_gJ[g], g_gb[g], g_ge[g],
                      NA, NC, NJ, Nb, Ne, IpW, Zt, ZC, Cw, w1, zb, Id,
                      tid, i, j, lane, wid);
    // segment-exclusive within group
    light_compose(Cst, bst, g_lA[kseg], g_lC[kseg], g_lJ[kseg], g_lb[kseg], g_le[kseg],
                  NA, NC, NJ, Nb, Ne, IpW, Zt, ZC, Cw, w1, zb, Id,
                  tid, i, j, lane, wid);
    // within-segment inclusive element E_t
    light_compose(Cst, bst, g_pA[t], g_pC[t], g_pJ[t], g_pb[t], g_pe[t],
                  NA, NC, NJ, Nb, Ne, IpW, Zt, ZC, Cw, w1, zb, Id,
                  tid, i, j, lane, wid);
    fc[tid] = Cst[tid];
    if (tid < 16) fmv[tid] = bst[tid];
    __syncthreads();
    if (t == Tn - 1) {
        g_fcF[tid] = fc[tid];
        if (tid < 16) g_fmF[tid] = fmv[tid];
        return;  // block-uniform
    }
    // ---- phaseD for step tt = t+1 ----
    const int tt = t + 1;
    NA[tid] = wq_[tid];   // Wq
    NC[tid] = hq_[tid];   // Hq
    NJ[tid] = wp[tid];    // Wp
    Id[tid] = g_OmP[tid];
    if (tid < 16) bqv[tid] = qb[tid];
    __syncthreads();
    M[tid] = dot_rc(NA, fc, i, j);
    if (tid < 16) pm[tid] = mv(NA, fmv, tid) + bqv[tid];
    __syncthreads();
    pcm[tid] = dot_rt(M, NA, i, j) + qtc[tid];
    __syncthreads();
    U[tid] = dot_rc(NC, pcm, i, j);
    __syncthreads();
    S2[tid] = dot_rt(U, NC, i, j) + qec[tid];
    __syncthreads();
    if (wid == 0) {
        float ldp = warp_gj_solve(pcm, M, bA, lane);
        if (lane == 0) g_ldp[tt] = ldp;
    } else if (wid == 5) {
        float lds = warp_gj_solve(S2, U, scr, lane);
        if (lane == 0) g_lds[tt] = lds;
    }
    __syncthreads();
    t1[tid] = dot_rc(NJ, bA, i, j) - ((i == j) ? 1.f : 0.f);
    g_bcov[tt][tid] = fc[tid] - dot_rc(bA, M, i, j);
    g_P[tt][tid] = bA[tid];
    if (tid < 16) g_ba[tt][tid] = fmv[tid] - mv(bA, pm, tid);
    __syncthreads();
    Z1[tid] = dot_rc(Id, t1, i, j);  // OmP * t1
    __syncthreads();
    g_Q[tt][tid] = dot_tc(t1, Z1, i, j);
}

// ================= par1: gramA ∥ scan1 =================
#define SEG 8
__global__ void __launch_bounds__(256, 1) k_par1(int Tn, int nsegG) {
    const int tid = threadIdx.x, i = tid >> 4, j = tid & 15;
    if ((int)blockIdx.x < nsegG) {
        const int k = blockIdx.x;
        const int s0 = 16 * k + 1, N = Tn - 1;
        if (s0 > N) return;
        const int send = min(16 * k + 16, N);
        __shared__ float P[256], Q[256], Qo[256], bAs[256], Qs[256], Em[256], nP[256], Y[256], Yo[256];
        Em[tid] = g_Em[tid];
        P[tid] = g_P[s0][tid]; Q[tid] = g_Q[s0][tid]; Qo[tid] = Em[tid];
        __syncthreads();
        g_mP[s0][tid] = P[tid]; g_mQ[s0][tid] = Q[tid]; g_mQo[s0][tid] = Qo[tid];
        for (int s = s0 + 1; s <= send; s++) {
            bAs[tid] = g_P[s][tid]; Qs[tid] = g_Q[s][tid];
            __syncthreads();
            nP[tid] = dot_rc(P, bAs, i, j);
            Y[tid] = dot_rc(Q, bAs, i, j);
            Yo[tid] = dot_rc(Qo, bAs, i, j);
            __syncthreads();
            float q = dot_tc(bAs, Y, i, j) + Qs[tid];
            float qo = dot_tc(bAs, Yo, i, j) + Em[tid];
            P[tid] = nP[tid]; Q[tid] = q; Qo[tid] = qo;
            g_mP[s][tid] = nP[tid]; g_mQ[s][tid] = q; g_mQo[s][tid] = qo;
            __syncthreads();
        }
    } else {
        const int b = blockIdx.x - nsegG;
        const int lo = b * SEG;
        int hi = min(lo + SEG, Tn);
        if (lo >= Tn) return;
        __shared__ float R[256], Rn[256], bA[256];
        __shared__ float u[16], un[16], ba[16];
        R[tid] = (i == j) ? 1.f : 0.f;
        if (tid < 16) u[tid] = 0.f;
        __syncthreads();
        for (int t = hi - 1; t >= lo; t--) {
            g_Lr[t][tid] = R[tid];
            if (tid < 16) g_Lu[t][tid] = u[tid];
            if (t == 0) break;
            bA[tid] = g_P[t][tid];
            if (tid < 16) ba[tid] = g_ba[t][tid];
            __syncthreads();
            Rn[tid] = dot_rc(bA, R, i, j);
            if (tid < 16) un[tid] = ba[tid] + mv(bA, u, tid);
            __syncthreads();
            R[tid] = Rn[tid];
            if (tid < 16) u[tid] = un[tid];
            __syncthreads();
        }
        g_Sr[b][tid] = R[tid];
        if (tid < 16) g_Su[b][tid] = u[tid];
    }
}

// ================= par2: gramB ∥ scan2 =================
__global__ void __launch_bounds__(256, 1) k_par2(int Tn) {
    const int tid = threadIdx.x, i = tid >> 4, j = tid & 15;
    if (blockIdx.x == 0) {
        __shared__ float G[256], Go[256], P[256], Qp[256], Qop[256], Y[256], Yo[256];
        const int N = Tn - 1;
        if (N < 1) return;
        const int nsg = (N + 15) / 16;
        G[tid] = g_Om0[tid]; Go[tid] = g_Em[tid];
        __syncthreads();
        for (int k = 0; k < nsg; k++) {
            g_Gx[k][tid] = G[tid]; g_Gox[k][tid] = Go[tid];
            if (k == nsg - 1) break;
            const int send = min(16 * k + 16, N);
            P[tid] = g_mP[send][tid]; Qp[tid] = g_mQ[send][tid]; Qop[tid] = g_mQo[send][tid];
            __syncthreads();
            Y[tid] = dot_rc(G, P, i, j);
            Yo[tid] = dot_rc(Go, P, i, j);
            __syncthreads();
            G[tid] = dot_tc(P, Y, i, j) + Qp[tid];
            Go[tid] = dot_tc(P, Yo, i, j) + Qop[tid];
            __syncthreads();
        }
    } else {
        const int nseg = (Tn + SEG - 1) / SEG;
        __shared__ float Gr[256], Gn[256], Sr[256];
        __shared__ float Gu[16], gn[16], Su[16];
        Gr[tid] = (i == j) ? 1.f : 0.f;
        if (tid < 16) Gu[tid] = 0.f;
        __syncthreads();
        for (int b = nseg - 1; b >= 0; b--) {
            g_Gr[b][tid] = Gr[tid];
            if (tid < 16) g_Gu[b][tid] = Gu[tid];
            if (b == 0) break;
            Sr[tid] = g_Sr[b][tid];
            if (tid < 16) Su[tid] = g_Su[b][tid];
            __syncthreads();
            Gn[tid] = dot_rc(Sr, Gr, i, j);
            if (tid < 16) gn[tid] = mv(Sr, Gu, tid) + Su[tid];
            __syncthreads();
            Gr[tid] = Gn[tid];
            if (tid < 16) Gu[tid] = gn[tid];
            __syncthreads();
        }
    }
}

// ================= tail: gramC + scan3 fused =================
__global__ void __launch_bounds__(256, 1) k_tail(
    const float* obs, const float* wp, const float* pb_, const float* wep,
    const float* peb, const float* ppm_, int Tn) {
    const int t = blockIdx.x;
    if (t >= Tn) return;
    __shared__ float OmP[256], omm[256], Om0[256], Wp[256], Wep[256], fc[256], Gr[256];
    __shared__ float Lr[256], bA[256], Rf[256], Ai[256], A[256], Ao[256], AF[256], AoF[256];
    __shared__ float G[256], Go[256], P[256], Y[256], Yo[256], Fm[256];
    __shared__ float fm[16], Gu[16], Lu[16], bav[16], uf[16], Bv[16], Bo[16];
    __shared__ float cv[16], co[16], y[16], bp[16], ebp[16], ppm[16];
    __shared__ double dred[8];
    const int tid = threadIdx.x, i = tid >> 4, j = tid & 15;
    const int lane = tid & 31, wid = tid >> 5;

    OmP[tid] = g_OmP[tid]; omm[tid] = g_om[tid]; Om0[tid] = g_Om0[tid];
    Wp[tid] = wp[tid]; Wep[tid] = wep[tid]; Fm[tid] = g_Fm[tid];
    fc[tid] = g_fcF[tid]; Gr[tid] = g_Gr[t / SEG][tid];
    Lr[tid] = g_Lr[t][tid];
    bA[tid] = (t > 0) ? g_P[t][tid] : 0.f;
    if (tid < 16) {
        fm[tid] = g_fmF[tid]; Gu[tid] = g_Gu[t / SEG][tid];
        bp[tid] = pb_[tid]; ebp[tid] = peb[tid]; ppm[tid] = ppm_[tid];
        Lu[tid] = g_Lu[t][tid];
        bav[tid] = (t > 0) ? g_ba[t][tid] : 0.f;
        y[tid] = obs[t * 16 + tid];
    }
    __syncthreads();

    double acc = 0.0;
    if (t >= 1) {
        const int s = t - 1;
        if (s == 0) {
            G[tid] = Om0[tid]; Go[tid] = g_Em[tid];
            __syncthreads();
        } else {
            const int k = (s - 1) >> 4;
            G[tid] = g_Gx[k][tid]; Go[tid] = g_Gox[k][tid];
            P[tid] = g_mP[s][tid];
            __syncthreads();
            Y[tid] = dot_rc(G, P, i, j);
            Yo[tid] = dot_rc(Go, P, i, j);
            __syncthreads();
            G[tid] = dot_tc(P, Y, i, j) + g_mQ[s][tid];
            Go[tid] = dot_tc(P, Yo, i, j) + g_mQo[s][tid];
            __syncthreads();
        }
        acc += (double)((G[tid] + Go[tid] - 0.5f * Fm[tid]) * g_bcov[t][tid]);
    }
    Rf[tid] = dot_rc(Lr, Gr, i, j);
    Ai[tid] = (t > 0) ? (dot_rc(Wp, bA, i, j) - ((i == j) ? 1.f : 0.f))
                      : ((i == j) ? 1.f : 0.f);
    if (tid < 16) {
        uf[tid] = mv(Lr, Gu, tid) + Lu[tid];
        Bv[tid] = (t > 0) ? (mv(Wp, bav, tid) + bp[tid]) : (-ppm[tid]);
    }
    __syncthreads();
    A[tid] = dot_rc(Ai, Rf, i, j);
    Ao[tid] = dot_rc(Wep, Rf, i, j);
    if (tid < 16) {
        Bv[tid] += mv(Ai, uf, tid);
        Bo[tid] = ebp[tid] - y[tid] + mv(Wep, uf, tid);
    }
    __syncthreads();
    AF[tid] = dot_rc(A, fc, i, j);
    AoF[tid] = dot_rc(Ao, fc, i, j);
    if (tid < 16) {
        cv[tid] = mv(A, fm, tid) + Bv[tid];
        co[tid] = mv(Ao, fm, tid) + Bo[tid];
    }
    __syncthreads();
    {
        const float* Om = (t == 0) ? Om0 : OmP;
        acc += (double)(Om[tid] * (dot_rc(AF, A, i, j) + cv[i] * cv[j])
                      + omm[tid] * (dot_rc(AoF, Ao, i, j) + co[i] * co[j]));
    }
    double v = acc;
#pragma unroll
    for (int o = 16; o; o >>= 1) v += __shfl_xor_sync(0xffffffffu, v, o);
    if (lane == 0) dred[wid] = v;
    __syncthreads();
    if (tid == 0) {
        double tot = 0.0;
#pragma unroll
        for (int w = 0; w < 8; w++) tot += dred[w];
        g_accT[t] = tot;
    }
}

// ================= finalize =================
__global__ void k_fin(float* out, int Tn) {
    if (threadIdx.x != 0) return;
    const int N = Tn - 1;
    double SP = 0.0, sumS = 0.0;
    for (int t = 1; t <= N; t++) { SP += (double)g_ldp[t]; sumS += (double)g_lds[t]; }
    double ldpN = (N >= 1) ? (double)g_ldp[N] : 0.0;
    double ldsN = (N >= 1) ? (double)g_lds[N] : 0.0;
    double set_acc = g_sc[0], K0d = g_sc[1], ldfc0 = g_sc[2], LDSqd = g_sc[3], LDRqd = g_sc[4];
    double Nd = (double)N;
    double sumF = ldfc0 + (SP - ldpN) + (Nd - 1.0) * LDRqd - (sumS - ldsN);
    double FN = (N >= 1) ? (ldpN + LDRqd - ldsN) : ldfc0;
    double tot = set_acc + Nd * (K0d + 0.5 * LDSqd) - 0.5 * SP + 0.5 * sumF
               + 0.5 * (16.0 * LOG2PI + FN) + 8.0;
    for (int t = 0; t < Tn; t++) tot += g_accT[t];
    out[0] = (float)tot;
}

extern "C" void kernel_launch(void* const* d_in, const int* in_sizes, int n_in,
                              void* d_out, int out_size) {
    int Tn = in_sizes[0] / 16;
    if (Tn > TMAX) Tn = TMAX;
    const float* obs = (const float*)d_in[0];
    const float* ppm_ = (const float*)d_in[1];
    const float* ppc = (const float*)d_in[2];
    const float* wp = (const float*)d_in[3];
    const float* pb_ = (const float*)d_in[4];
    const float* ptc = (const float*)d_in[5];
    const float* wep = (const float*)d_in[6];
    const float* peb = (const float*)d_in[7];
    const float* pec = (const float*)d_in[8];
    const float* qpm = (const float*)d_in[9];
    const float* qpc = (const float*)d_in[10];
    const float* wq_ = (const float*)d_in[11];
    const float* qb = (const float*)d_in[12];
    const float* qtc = (const float*)d_in[13];
    const float* hq_ = (const float*)d_in[14];
    const float* qeb = (const float*)d_in[15];
    const float* qec = (const float*)d_in[16];
    const int nsegA = (Tn + SEGA - 1) / SEGA;
    const int ngrp = (nsegA + GRP - 1) / GRP;
    const int nsegG = (Tn + 15) / 16;
    const int nseg1 = (Tn + SEG - 1) / SEG;
    k_setup<<<1, 256>>>(obs, ppm_, ppc, wp, pb_, ptc, wep, peb, pec, qpm, qpc,
                        wq_, qb, qtc, hq_, qeb, qec, Tn);
    k_elemA<<<nsegA, 256>>>(obs, Tn);
    k_elemB1<<<ngrp, 256>>>(Tn);
    k_elemCD<<<Tn, 256>>>(wq_, qtc, hq_, qec, qb, wp, Tn);
    k_par1<<<nsegG + nseg1, 256>>>(Tn, nsegG);
    k_par2<<<2, 256>>>(Tn);
    k_tail<<<Tn, 256>>>(obs, wp, pb_, wep, peb, ppm_, Tn);
    k_fin<<<1, 32>>>((float*)d_out, Tn);
}

// round 14
// speedup vs baseline: 6.3025x; 1.2288x over previous
#include <cuda_runtime.h>
#include <math.h>

#define TMAX 256
#define LOG2PI 1.8378770664093453
#define SEGA 8
#define GRP 8

// ---------------- device scratch ----------------
__device__ float g_pA[TMAX][256], g_pC[TMAX][256], g_pJ[TMAX][256];
__device__ float g_pb[TMAX][16], g_pe[TMAX][16];
__device__ float g_lA[32][256], g_lC[32][256], g_lJ[32][256];
__device__ float g_lb[32][16], g_le[32][16];
__device__ float g_gA[4][256], g_gC[4][256], g_gJ[4][256];
__device__ float g_gb[4][16], g_ge[4][16];
__device__ float g_P[TMAX][256], g_ba[TMAX][16];
__device__ float g_bcov[TMAX][256], g_Q[TMAX][256];
__device__ float g_mP[TMAX][256], g_mQ[TMAX][256], g_mQo[TMAX][256];
__device__ float g_Gx[16][256], g_Gox[16][256];
__device__ float g_ldp[TMAX], g_lds[TMAX];
__device__ double g_accT[TMAX];
__device__ float g_Lr[TMAX][256], g_Lu[TMAX][16];
__device__ float g_Sr[32][256], g_Su[32][16];
__device__ float g_Gr[32][256], g_Gu[32][16];
__device__ float g_OmP[256], g_om[256], g_Om0[256], g_Em[256], g_Fm[256];
__device__ float g_Ac[256], g_Cc[256], g_Jc[256], g_Kc[256], g_Ec[256];
__device__ float g_cb0[16], g_e0v[16];
__device__ float g_fcF[256], g_fmF[16];
__device__ double g_sc[8];

__device__ __forceinline__ float dot_rc(const float* A, const float* B, int i, int j) {
    float s = 0.f;
#pragma unroll
    for (int k = 0; k < 16; k++) s = fmaf(A[i * 16 + k], B[k * 16 + j], s);
    return s;
}
__device__ __forceinline__ float dot_tc(const float* A, const float* B, int i, int j) {
    float s = 0.f;
#pragma unroll
    for (int k = 0; k < 16; k++) s = fmaf(A[k * 16 + i], B[k * 16 + j], s);
    return s;
}
__device__ __forceinline__ float dot_rt(const float* A, const float* B, int i, int j) {
    float s = 0.f;
#pragma unroll
    for (int k = 0; k < 16; k++) s = fmaf(A[i * 16 + k], B[j * 16 + k], s);
    return s;
}
__device__ __forceinline__ float mv(const float* M, const float* v, int r) {
    float s = 0.f;
#pragma unroll
    for (int k = 0; k < 16; k++) s = fmaf(M[r * 16 + k], v[k], s);
    return s;
}

// Warp GJ solve A X = B (16x16, 16 RHS cols); writes X^T to Xt; returns sum(log|piv|).
__device__ __forceinline__ float warp_gj_solve(const float* Am, const float* Bm,
                                               float* Xt, int lane) {
    float a[16];
    const float* src = (lane < 16) ? (Am + lane) : (Bm + lane - 16);
#pragma unroll
    for (int r = 0; r < 16; r++) a[r] = src[r * 16];
    float mypiv = 1.f;
#pragma unroll
    for (int p = 0; p < 16; p++) {
        float f[16];
#pragma unroll
        for (int r = 0; r < 16; r++) f[r] = __shfl_sync(0xffffffffu, a[r], p);
        float x = f[p];
        if (lane == p) mypiv = x;
        float r0;
        asm("rcp.approx.f32 %0, %1;" : "=f"(r0) : "f"(x));
        float pivinv = r0 * (2.0f - x * r0);
        a[p] *= pivinv;
#pragma unroll
        for (int r = 0; r < 16; r++)
            if (r != p) a[r] = fmaf(-f[r], a[p], a[r]);
    }
    float lg = __logf(fabsf(mypiv));
#pragma unroll
    for (int o = 16; o; o >>= 1) lg += __shfl_xor_sync(0xffffffffu, lg, o);
    if (lane >= 16) {
        float4* dst = reinterpret_cast<float4*>(Xt + (lane - 16) * 16);
        dst[0] = make_float4(a[0], a[1], a[2], a[3]);
        dst[1] = make_float4(a[4], a[5], a[6], a[7]);
        dst[2] = make_float4(a[8], a[9], a[10], a[11]);
        dst[3] = make_float4(a[12], a[13], a[14], a[15]);
    }
    return lg;
}

// Warp GJ vector solve A x = b; writes x to xout (lane 16 stores).
__device__ __forceinline__ void warp_gj_vecsolve(const float* Am, const float* bv,
                                                 float* xout, int lane) {
    float a[16];
    if (lane < 16) {
#pragma unroll
        for (int r = 0; r < 16; r++) a[r] = Am[r * 16 + lane];
    } else {
#pragma unroll
        for (int r = 0; r < 16; r++) a[r] = bv[r];
    }
#pragma unroll
    for (int p = 0; p < 16; p++) {
        float f[16];
#pragma unroll
        for (int r = 0; r < 16; r++) f[r] = __shfl_sync(0xffffffffu, a[r], p);
        float x = f[p];
        float r0;
        asm("rcp.approx.f32 %0, %1;" : "=f"(r0) : "f"(x));
        float pivinv = r0 * (2.0f - x * r0);
        a[p] *= pivinv;
#pragma unroll
        for (int r = 0; r < 16; r++)
            if (r != p) a[r] = fmaf(-f[r], a[p], a[r]);
    }
    if (lane == 16) {
        float4* dst = reinterpret_cast<float4*>(xout);
        dst[0] = make_float4(a[0], a[1], a[2], a[3]);
        dst[1] = make_float4(a[4], a[5], a[6], a[7]);
        dst[2] = make_float4(a[8], a[9], a[10], a[11]);
        dst[3] = make_float4(a[12], a[13], a[14], a[15]);
    }
}

// Full element compose v2 (multi-RHS GJ): prefix ∘ next -> prefix.
// Temps: IpW, ZAt, ZCt, JA (ZCt reused as Cw), w1, vJ, zb.
__device__ __forceinline__ void compose_full(
    float* PA, float* PC, float* PJ, float* Pb, float* Pe,
    const float* NA, const float* NC, const float* NJ, const float* Nb, const float* Ne,
    float* IpW, float* ZAt, float* ZCt, float* JA,
    float* w1, float* vJ, float* zb, const float* Id,
    int tid, int i, int j, int lane, int wid) {
    IpW[tid] = Id[tid] + dot_rc(PC, NJ, i, j);
    if (tid < 16) w1[tid] = Pb[tid] + mv(PC, Ne, tid);
    else if (tid < 32) vJ[tid - 16] = mv(NJ, Pb, tid - 16);
    __syncthreads();
    if (wid == 0) {
        warp_gj_solve(IpW, PA, ZAt, lane);       // ZAt = (Z·PA)^T
    } else if (wid == 5) {
        warp_gj_solve(IpW, PC, ZCt, lane);       // ZCt = (Z·PC)^T
    } else if (wid == 2) {
        warp_gj_vecsolve(IpW, w1, zb, lane);     // zb = Z·w1
    } else if (wid != 4) {
        const int h = (wid == 1) ? (tid - 32) : (wid == 3) ? (tid - 64) : (tid - 128);
        JA[h] = dot_rc(NJ, PA, h >> 4, h & 15);
        JA[h + 128] = dot_rc(NJ, PA, (h + 128) >> 4, (h + 128) & 15);
    }
    __syncthreads();
    {
        float na = dot_rt(NA, ZAt, i, j);
        float cw = dot_rt(NA, ZCt, i, j);
        float nj = dot_rc(ZAt, JA, i, j) + PJ[tid];
        float nb = 0.f, ne = 0.f;
        if (tid < 16) {
            nb = mv(NA, zb, tid) + Nb[tid];
#pragma unroll
            for (int k = 0; k < 16; k++) ne = fmaf(ZAt[tid * 16 + k], Ne[k] - vJ[k], ne);
            ne += Pe[tid];
        }
        PA[tid] = na;
        PJ[tid] = nj;
        ZCt[tid] = cw;  // reuse as Cw
        if (tid < 16) { Pb[tid] = nb; Pe[tid] = ne; }
    }
    __syncthreads();
    PC[tid] = dot_rt(ZCt, NA, i, j) + NC[tid];
    __syncthreads();
}

// Light (b,C) compose v2: state (Cst,bst) ∘ element (global) -> state.
__device__ __forceinline__ void light_compose(
    float* Cst, float* bst,
    const float* gA, const float* gC, const float* gJ,
    const float* gb, const float* ge,
    float* NA, float* NJ, float* IpW, float* ZCt, float* zb,
    float* Nb2, float* w1, const float* Id,
    int tid, int i, int j, int lane, int wid) {
    NA[tid] = gA[tid]; NJ[tid] = gJ[tid];
    if (tid < 16) Nb2[tid] = gb[tid];
    else if (tid < 32) w1[tid - 16] = ge[tid - 16];  // stage Ne in w1 temporarily? no:
    __syncthreads();
    // w1 currently holds ge; compute IpW and true w1
    IpW[tid] = Id[tid] + dot_rc(Cst, NJ, i, j);
    if (tid < 16) {
        float s = bst[tid];
#pragma unroll
        for (int k = 0; k < 16; k++) s = fmaf(Cst[tid * 16 + k], w1[k], s);
        zb[tid] = s;  // zb temporarily = w1 (true)
    }
    __syncthreads();
    if (wid == 0) warp_gj_solve(IpW, Cst, ZCt, lane);       // ZCt = (Z·Cst)^T
    else if (wid == 2) warp_gj_vecsolve(IpW, zb, w1, lane); // w1 = Z·w1true
    __syncthreads();
    {
        float cw = dot_rt(NA, ZCt, i, j);
        float nb = 0.f;
        if (tid < 16) nb = mv(NA, w1, tid) + Nb2[tid];
        ZCt[tid] = cw;
        if (tid < 16) bst[tid] = nb;
    }
    __syncthreads();
    Cst[tid] = dot_rt(ZCt, NA, i, j) + gC[tid];
    __syncthreads();
}

// ================= setup (parallel GJs) =================
__global__ void __launch_bounds__(256, 1) k_setup(
    const float* obs, const float* ppm_, const float* ppc, const float* wp,
    const float* pb_, const float* ptc, const float* wep, const float* peb,
    const float* pec, const float* qpm, const float* qpc, const float* wq_,
    const float* qb, const float* qtc, const float* hq_, const float* qeb,
    const float* qec, int Tn) {
    __shared__ float Wq[256], Sq[256], Hq[256], Rq[256], Wp[256], Wep[256], Id[256];
    __shared__ float MI[6][256], VI[6][256];
    __shared__ float Hpc[256], U1[256], V[256], S[256], Sc[256];
    __shared__ float Km[256], Kc[256], Ec[256], IKH[256], B1[256], t3[256];
    __shared__ float ldsh[8];
    __shared__ float bq[16], dq[16], pm0[16], innov[16], y0[16], c2v[16];
    const int tid = threadIdx.x, i = tid >> 4, j = tid & 15;
    const int lane = tid & 31, wid = tid >> 5;
    Wq[tid] = wq_[tid]; Sq[tid] = qtc[tid]; Hq[tid] = hq_[tid]; Rq[tid] = qec[tid];
    Wp[tid] = wp[tid]; Wep[tid] = wep[tid]; Id[tid] = (i == j) ? 1.f : 0.f;
    MI[0][tid] = ptc[tid]; MI[1][tid] = pec[tid]; MI[2][tid] = ppc[tid];
    MI[3][tid] = qtc[tid]; MI[4][tid] = qec[tid]; MI[5][tid] = qpc[tid];
    if (tid < 16) { bq[tid] = qb[tid]; dq[tid] = qeb[tid]; pm0[tid] = qpm[tid]; y0[tid] = obs[tid]; }
    __syncthreads();
    if (wid < 6) {
        float ld = warp_gj_solve(MI[wid], Id, VI[wid], lane);
        if (lane == 0) ldsh[wid] = ld;
    }
    __syncthreads();
    g_OmP[tid] = -0.5f * VI[0][tid];
    g_om[tid] = -0.5f * VI[1][tid];
    g_Om0[tid] = -0.5f * VI[2][tid];
    B1[tid] = dot_rc(VI[0], Wp, i, j);
    t3[tid] = -0.5f * dot_rc(VI[1], Wep, i, j);
    Hpc[tid] = dot_rc(Hq, MI[5], i, j);
    U1[tid] = dot_rc(Hq, Sq, i, j);
    V[tid] = dot_rc(Hq, Wq, i, j);
    if (tid < 16) innov[tid] = y0[tid] - mv(Hq, pm0, tid) - dq[tid];
    __syncthreads();
    g_Fm[tid] = dot_tc(Wp, B1, i, j);
    g_Em[tid] = dot_tc(Wep, t3, i, j);
    S[tid] = dot_rt(Hpc, Hq, i, j) + Rq[tid];
    Sc[tid] = dot_rt(U1, Hq, i, j) + Rq[tid];
    __syncthreads();
    if (wid == 0) {
        float ld = warp_gj_solve(S, Hpc, Km, lane);
        if (lane == 0) ldsh[6] = ld;
    } else if (wid == 2) {
        warp_gj_solve(Sc, U1, Kc, lane);
    } else if (wid == 5) {
        warp_gj_solve(Sc, V, Ec, lane);
    }
    __syncthreads();
    g_pA[0][tid] = 0.f; g_pJ[0][tid] = 0.f;
    g_pC[0][tid] = MI[5][tid] - dot_rc(Km, Hpc, i, j);
    IKH[tid] = Id[tid] - dot_rc(Kc, Hq, i, j);
    if (tid < 16) {
        c2v[tid] = mv(Hq, bq, tid) + dq[tid];
        g_pb[0][tid] = pm0[tid] + mv(Km, innov, tid);
        g_pe[0][tid] = 0.f;
    }
    __syncthreads();
    g_Ac[tid] = dot_rc(IKH, Wq, i, j);
    g_Cc[tid] = dot_rc(IKH, Sq, i, j);
    g_Jc[tid] = dot_rc(Ec, V, i, j);
    g_Kc[tid] = Kc[tid]; g_Ec[tid] = Ec[tid];
    if (tid < 16) {
        g_cb0[tid] = mv(IKH, bq, tid) - mv(Kc, dq, tid);
        g_e0v[tid] = mv(Ec, c2v, tid);
    }
    if (tid == 0) {
        double LDp = ldsh[0], LDe = ldsh[1], LDpr = ldsh[2];
        double LDSq = ldsh[3], LDRq = ldsh[4], ldqp = ldsh[5], ldS0 = ldsh[6];
        g_sc[0] = -0.5 * (16.0 * LOG2PI + LDpr) - 0.5 * (16.0 * LOG2PI + LDe);
        g_sc[1] = -8.0 * LOG2PI - 0.5 * LDe - 0.5 * LDp + 8.0;
        g_sc[2] = ldqp + LDRq - ldS0;
        g_sc[3] = LDSq;
        g_sc[4] = LDRq;
    }
}

// ================= elemA =================
__global__ void __launch_bounds__(256, 1) k_elemA(const float* obs, int Tn) {
    __shared__ float Ac[256], Cc[256], Jc[256], Kc[256], Ec[256], Id[256];
    __shared__ float A[256], C[256], J[256];
    __shared__ float IpW[256], ZAt[256], ZCt[256], JA[256];
    __shared__ float cb0[16], e0v[16];
    __shared__ float bv[16], ev[16], bt[16], et[16], w1[16], vJ[16], zb[16], yv[16];
    const int tid = threadIdx.x, i = tid >> 4, j = tid & 15;
    const int lane = tid & 31, wid = tid >> 5;
    const int t0 = blockIdx.x * SEGA;
    if (t0 >= Tn) return;
    const int tend = min(t0 + SEGA, Tn);
    Ac[tid] = g_Ac[tid]; Cc[tid] = g_Cc[tid]; Jc[tid] = g_Jc[tid];
    Kc[tid] = g_Kc[tid]; Ec[tid] = g_Ec[tid]; Id[tid] = (i == j) ? 1.f : 0.f;
    if (tid < 16) { cb0[tid] = g_cb0[tid]; e0v[tid] = g_e0v[tid]; }
    __syncthreads();
    if (t0 == 0) {
        A[tid] = g_pA[0][tid]; C[tid] = g_pC[0][tid]; J[tid] = g_pJ[0][tid];
        if (tid < 16) { bv[tid] = g_pb[0][tid]; ev[tid] = g_pe[0][tid]; }
    } else {
        if (tid < 16) yv[tid] = obs[t0 * 16 + tid];
        __syncthreads();
        A[tid] = Ac[tid]; C[tid] = Cc[tid]; J[tid] = Jc[tid];
        if (tid < 16) { bv[tid] = cb0[tid] + mv(Kc, yv, tid); ev[tid] = mv(Ec, yv, tid) - e0v[tid]; }
        __syncthreads();
        g_pA[t0][tid] = A[tid]; g_pC[t0][tid] = C[tid]; g_pJ[t0][tid] = J[tid];
        if (tid < 16) { g_pb[t0][tid] = bv[tid]; g_pe[t0][tid] = ev[tid]; }
    }
    __syncthreads();
    for (int t = t0 + 1; t < tend; t++) {
        if (tid < 16) yv[tid] = obs[t * 16 + tid];
        __syncthreads();
        if (tid < 16) bt[tid] = cb0[tid] + mv(Kc, yv, tid);
        else if (tid < 32) et[tid - 16] = mv(Ec, yv, tid - 16) - e0v[tid - 16];
        __syncthreads();
        compose_full(A, C, J, bv, ev, Ac, Cc, Jc, bt, et,
                     IpW, ZAt, ZCt, JA, w1, vJ, zb, Id, tid, i, j, lane, wid);
        g_pA[t][tid] = A[tid]; g_pC[t][tid] = C[tid]; g_pJ[t][tid] = J[tid];
        if (tid < 16) { g_pb[t][tid] = bv[tid]; g_pe[t][tid] = ev[tid]; }
        __syncthreads();
    }
}

// ================= elemB1 =================
__global__ void __launch_bounds__(256, 1) k_elemB1(int Tn) {
    __shared__ float A[256], C[256], J[256], Id[256];
    __shared__ float NA[256], NC[256], NJ[256];
    __shared__ float IpW[256], ZAt[256], ZCt[256], JA[256];
    __shared__ float bv[16], ev[16], Nb[16], Ne[16], w1[16], vJ[16], zb[16];
    const int tid = threadIdx.x, i = tid >> 4, j = tid & 15;
    const int lane = tid & 31, wid = tid >> 5;
    const int nsegA = (Tn + SEGA - 1) / SEGA;
    const int g = blockIdx.x;
    const int k0 = g * GRP;
    if (k0 >= nsegA) return;
    const int kend = min(k0 + GRP, nsegA);
    Id[tid] = (i == j) ? 1.f : 0.f;
    A[tid] = Id[tid]; C[tid] = 0.f; J[tid] = 0.f;
    if (tid < 16) { bv[tid] = 0.f; ev[tid] = 0.f; }
    __syncthreads();
    for (int k = k0; k < kend; k++) {
        g_lA[k][tid] = A[tid]; g_lC[k][tid] = C[tid]; g_lJ[k][tid] = J[tid];
        if (tid < 16) { g_lb[k][tid] = bv[tid]; g_le[k][tid] = ev[tid]; }
        const int tl = min(k * SEGA + SEGA - 1, Tn - 1);
        NA[tid] = g_pA[tl][tid]; NC[tid] = g_pC[tl][tid]; NJ[tid] = g_pJ[tl][tid];
        if (tid < 16) { Nb[tid] = g_pb[tl][tid]; Ne[tid] = g_pe[tl][tid]; }
        __syncthreads();
        compose_full(A, C, J, bv, ev, NA, NC, NJ, Nb, Ne,
                     IpW, ZAt, ZCt, JA, w1, vJ, zb, Id, tid, i, j, lane, wid);
    }
    g_gA[g][tid] = A[tid]; g_gC[g][tid] = C[tid]; g_gJ[g][tid] = J[tid];
    if (tid < 16) { g_gb[g][tid] = bv[tid]; g_ge[g][tid] = ev[tid]; }
}

// ================= elemCD =================
__global__ void __launch_bounds__(256, 1) k_elemCD(
    const float* wq_, const float* qtc, const float* hq_, const float* qec,
    const float* qb, const float* wp, int Tn) {
    const int t = blockIdx.x;
    if (t >= Tn) return;
    const int kseg = t / SEGA, grp = kseg / GRP;
    __shared__ float Cst[256], Id[256];
    __shared__ float NA[256], NJ[256];
    __shared__ float IpW[256], ZCt[256], fc[256];
    __shared__ float M[256], pcm[256], U[256], S2[256], bA[256], scr[256], t1[256], Z1[256];
    __shared__ float bst[16], Nb2[16], w1[16], zb[16], fmv[16], pm[16], bqv[16];
    const int tid = threadIdx.x, i = tid >> 4, j = tid & 15;
    const int lane = tid & 31, wid = tid >> 5;
    Id[tid] = (i == j) ? 1.f : 0.f;
    Cst[tid] = 0.f;
    if (tid < 16) bst[tid] = 0.f;
    __syncthreads();
    for (int g = 0; g < grp; g++)
        light_compose(Cst, bst, g_gA[g], g_gC[g], g_gJ[g], g_gb[g], g_ge[g],
                      NA, NJ, IpW, ZCt, zb, Nb2, w1, Id, tid, i, j, lane, wid);
    light_compose(Cst, bst, g_lA[kseg], g_lC[kseg], g_lJ[kseg], g_lb[kseg], g_le[kseg],
                  NA, NJ, IpW, ZCt, zb, Nb2, w1, Id, tid, i, j, lane, wid);
    light_compose(Cst, bst, g_pA[t], g_pC[t], g_pJ[t], g_pb[t], g_pe[t],
                  NA, NJ, IpW, ZCt, zb, Nb2, w1, Id, tid, i, j, lane, wid);
    fc[tid] = Cst[tid];
    if (tid < 16) fmv[tid] = bst[tid];
    __syncthreads();
    if (t == Tn - 1) {
        g_fcF[tid] = fc[tid];
        if (tid < 16) g_fmF[tid] = fmv[tid];
        return;  // block-uniform
    }
    // ---- phaseD for step tt = t+1 ----
    const int tt = t + 1;
    NA[tid] = wq_[tid];   // Wq
    NJ[tid] = wp[tid];    // Wp
    ZCt[tid] = hq_[tid];  // Hq
    Id[tid] = g_OmP[tid];
    if (tid < 16) bqv[tid] = qb[tid];
    __syncthreads();
    M[tid] = dot_rc(NA, fc, i, j);
    if (tid < 16) pm[tid] = mv(NA, fmv, tid) + bqv[tid];
    __syncthreads();
    pcm[tid] = dot_rt(M, NA, i, j) + qtc[tid];
    __syncthreads();
    U[tid] = dot_rc(ZCt, pcm, i, j);
    __syncthreads();
    S2[tid] = dot_rt(U, ZCt, i, j) + qec[tid];
    __syncthreads();
    if (wid == 0) {
        float ldp = warp_gj_solve(pcm, M, bA, lane);
        if (lane == 0) g_ldp[tt] = ldp;
    } else if (wid == 5) {
        float lds = warp_gj_solve(S2, U, scr, lane);
        if (lane == 0) g_lds[tt] = lds;
    }
    __syncthreads();
    t1[tid] = dot_rc(NJ, bA, i, j) - ((i == j) ? 1.f : 0.f);
    g_bcov[tt][tid] = fc[tid] - dot_rc(bA, M, i, j);
    g_P[tt][tid] = bA[tid];
    if (tid < 16) g_ba[tt][tid] = fmv[tid] - mv(bA, pm, tid);
    __syncthreads();
    Z1[tid] = dot_rc(Id, t1, i, j);  // OmP * t1
    __syncthreads();
    g_Q[tt][tid] = dot_tc(t1, Z1, i, j);
}

// ================= par1: gramA ∥ scan1 =================
#define SEG 8
__global__ void __launch_bounds__(256, 1) k_par1(int Tn, int nsegG) {
    const int tid = threadIdx.x, i = tid >> 4, j = tid & 15;
    if ((int)blockIdx.x < nsegG) {
        const int k = blockIdx.x;
        const int s0 = 16 * k + 1, N = Tn - 1;
        if (s0 > N) return;
        const int send = min(16 * k + 16, N);
        __shared__ float P[256], Q[256], Qo[256], bAs[256], Qs[256], Em[256], nP[256], Y[256], Yo[256];
        Em[tid] = g_Em[tid];
        P[tid] = g_P[s0][tid]; Q[tid] = g_Q[s0][tid]; Qo[tid] = Em[tid];
        __syncthreads();
        g_mP[s0][tid] = P[tid]; g_mQ[s0][tid] = Q[tid]; g_mQo[s0][tid] = Qo[tid];
        for (int s = s0 + 1; s <= send; s++) {
            bAs[tid] = g_P[s][tid]; Qs[tid] = g_Q[s][tid];
            __syncthreads();
            nP[tid] = dot_rc(P, bAs, i, j);
            Y[tid] = dot_rc(Q, bAs, i, j);
            Yo[tid] = dot_rc(Qo, bAs, i, j);
            __syncthreads();
            float q = dot_tc(bAs, Y, i, j) + Qs[tid];
            float qo = dot_tc(bAs, Yo, i, j) + Em[tid];
            P[tid] = nP[tid]; Q[tid] = q; Qo[tid] = qo;
            g_mP[s][tid] = nP[tid]; g_mQ[s][tid] = q; g_mQo[s][tid] = qo;
            __syncthreads();
        }
    } else {
        const int b = blockIdx.x - nsegG;
        const int lo = b * SEG;
        int hi = min(lo + SEG, Tn);
        if (lo >= Tn) return;
        __shared__ float R[256], Rn[256], bA[256];
        __shared__ float u[16], un[16], ba[16];
        R[tid] = (i == j) ? 1.f : 0.f;
        if (tid < 16) u[tid] = 0.f;
        __syncthreads();
        for (int t = hi - 1; t >= lo; t--) {
            g_Lr[t][tid] = R[tid];
            if (tid < 16) g_Lu[t][tid] = u[tid];
            if (t == 0) break;
            bA[tid] = g_P[t][tid];
            if (tid < 16) ba[tid] = g_ba[t][tid];
            __syncthreads();
            Rn[tid] = dot_rc(bA, R, i, j);
            if (tid < 16) un[tid] = ba[tid] + mv(bA, u, tid);
            __syncthreads();
            R[tid] = Rn[tid];
            if (tid < 16) u[tid] = un[tid];
            __syncthreads();
        }
        g_Sr[b][tid] = R[tid];
        if (tid < 16) g_Su[b][tid] = u[tid];
    }
}

// ================= par2: gramB ∥ scan2 =================
__global__ void __launch_bounds__(256, 1) k_par2(int Tn) {
    const int tid = threadIdx.x, i = tid >> 4, j = tid & 15;
    if (blockIdx.x == 0) {
        __shared__ float G[256], Go[256], P[256], Qp[256], Qop[256], Y[256], Yo[256];
        const int N = Tn - 1;
        if (N < 1) return;
        const int nsg = (N + 15) / 16;
        G[tid] = g_Om0[tid]; Go[tid] = g_Em[tid];
        __syncthreads();
        for (int k = 0; k < nsg; k++) {
            g_Gx[k][tid] = G[tid]; g_Gox[k][tid] = Go[tid];
            if (k == nsg - 1) break;
            const int send = min(16 * k + 16, N);
            P[tid] = g_mP[send][tid]; Qp[tid] = g_mQ[send][tid]; Qop[tid] = g_mQo[send][tid];
            __syncthreads();
            Y[tid] = dot_rc(G, P, i, j);
            Yo[tid] = dot_rc(Go, P, i, j);
            __syncthreads();
            G[tid] = dot_tc(P, Y, i, j) + Qp[tid];
            Go[tid] = dot_tc(P, Yo, i, j) + Qop[tid];
            __syncthreads();
        }
    } else {
        const int nseg = (Tn + SEG - 1) / SEG;
        __shared__ float Gr[256], Gn[256], Sr[256];
        __shared__ float Gu[16], gn[16], Su[16];
        Gr[tid] = (i == j) ? 1.f : 0.f;
        if (tid < 16) Gu[tid] = 0.f;
        __syncthreads();
        for (int b = nseg - 1; b >= 0; b--) {
            g_Gr[b][tid] = Gr[tid];
            if (tid < 16) g_Gu[b][tid] = Gu[tid];
            if (b == 0) break;
            Sr[tid] = g_Sr[b][tid];
            if (tid < 16) Su[tid] = g_Su[b][tid];
            __syncthreads();
            Gn[tid] = dot_rc(Sr, Gr, i, j);
            if (tid < 16) gn[tid] = mv(Sr, Gu, tid) + Su[tid];
            __syncthreads();
            Gr[tid] = Gn[tid];
            if (tid < 16) Gu[tid] = gn[tid];
            __syncthreads();
        }
    }
}

// ================= tail =================
__global__ void __launch_bounds__(256, 1) k_tail(
    const float* obs, const float* wp, const float* pb_, const float* wep,
    const float* peb, const float* ppm_, int Tn) {
    const int t = blockIdx.x;
    if (t >= Tn) return;
    __shared__ float OmP[256], omm[256], Om0[256], Wp[256], Wep[256], fc[256], Gr[256];
    __shared__ float Lr[256], bA[256], Rf[256], Ai[256], A[256], Ao[256], AF[256], AoF[256];
    __shared__ float G[256], Go[256], P[256], Y[256], Yo[256], Fm[256];
    __shared__ float fm[16], Gu[16], Lu[16], bav[16], uf[16], Bv[16], Bo[16];
    __shared__ float cv[16], co[16], y[16], bp[16], ebp[16], ppm[16];
    __shared__ double dred[8];
    const int tid = threadIdx.x, i = tid >> 4, j = tid & 15;
    const int lane = tid & 31, wid = tid >> 5;

    OmP[tid] = g_OmP[tid]; omm[tid] = g_om[tid]; Om0[tid] = g_Om0[tid];
    Wp[tid] = wp[tid]; Wep[tid] = wep[tid]; Fm[tid] = g_Fm[tid];
    fc[tid] = g_fcF[tid]; Gr[tid] = g_Gr[t / SEG][tid];
    Lr[tid] = g_Lr[t][tid];
    bA[tid] = (t > 0) ? g_P[t][tid] : 0.f;
    if (tid < 16) {
        fm[tid] = g_fmF[tid]; Gu[tid] = g_Gu[t / SEG][tid];
        bp[tid] = pb_[tid]; ebp[tid] = peb[tid]; ppm[tid] = ppm_[tid];
        Lu[tid] = g_Lu[t][tid];
        bav[tid] = (t > 0) ? g_ba[t][tid] : 0.f;
        y[tid] = obs[t * 16 + tid];
    }
    __syncthreads();

    double acc = 0.0;
    if (t >= 1) {
        const int s = t - 1;
        if (s == 0) {
            G[tid] = Om0[tid]; Go[tid] = g_Em[tid];
            __syncthreads();
        } else {
            const int k = (s - 1) >> 4;
            G[tid] = g_Gx[k][tid]; Go[tid] = g_Gox[k][tid];
            P[tid] = g_mP[s][tid];
            __syncthreads();
            Y[tid] = dot_rc(G, P, i, j);
            Yo[tid] = dot_rc(Go, P, i, j);
            __syncthreads();
            G[tid] = dot_tc(P, Y, i, j) + g_mQ[s][tid];
            Go[tid] = dot_tc(P, Yo, i, j) + g_mQo[s][tid];
            __syncthreads();
        }
        acc += (double)((G[tid] + Go[tid] - 0.5f * Fm[tid]) * g_bcov[t][tid]);
    }
    Rf[tid] = dot_rc(Lr, Gr, i, j);
    Ai[tid] = (t > 0) ? (dot_rc(Wp, bA, i, j) - ((i == j) ? 1.f : 0.f))
                      : ((i == j) ? 1.f : 0.f);
    if (tid < 16) {
        uf[tid] = mv(Lr, Gu, tid) + Lu[tid];
        Bv[tid] = (t > 0) ? (mv(Wp, bav, tid) + bp[tid]) : (-ppm[tid]);
    }
    __syncthreads();
    A[tid] = dot_rc(Ai, Rf, i, j);
    Ao[tid] = dot_rc(Wep, Rf, i, j);
    if (tid < 16) {
        Bv[tid] += mv(Ai, uf, tid);
        Bo[tid] = ebp[tid] - y[tid] + mv(Wep, uf, tid);
    }
    __syncthreads();
    AF[tid] = dot_rc(A, fc, i, j);
    AoF[tid] = dot_rc(Ao, fc, i, j);
    if (tid < 16) {
        cv[tid] = mv(A, fm, tid) + Bv[tid];
        co[tid] = mv(Ao, fm, tid) + Bo[tid];
    }
    __syncthreads();
    {
        const float* Om = (t == 0) ? Om0 : OmP;
        acc += (double)(Om[tid] * (dot_rc(AF, A, i, j) + cv[i] * cv[j])
                      + omm[tid] * (dot_rc(AoF, Ao, i, j) + co[i] * co[j]));
    }
    double v = acc;
#pragma unroll
    for (int o = 16; o; o >>= 1) v += __shfl_xor_sync(0xffffffffu, v, o);
    if (lane == 0) dred[wid] = v;
    __syncthreads();
    if (tid == 0) {
        double tot = 0.0;
#pragma unroll
        for (int w = 0; w < 8; w++) tot += dred[w];
        g_accT[t] = tot;
    }
}

// ================= finalize (parallel tree reduction) =================
__global__ void __launch_bounds__(256, 1) k_fin(float* out, int Tn) {
    __shared__ double r0[8], r1[8], r2[8];
    const int tid = threadIdx.x, lane = tid & 31, wid = tid >> 5;
    const int N = Tn - 1;
    double a = 0.0, b = 0.0, c = 0.0;
    for (int t = tid; t < Tn; t += 256) {
        if (t >= 1) { a += (double)g_ldp[t]; b += (double)g_lds[t]; }
        c += g_accT[t];
    }
#pragma unroll
    for (int o = 16; o; o >>= 1) {
        a += __shfl_xor_sync(0xffffffffu, a, o);
        b += __shfl_xor_sync(0xffffffffu, b, o);
        c += __shfl_xor_sync(0xffffffffu, c, o);
    }
    if (lane == 0) { r0[wid] = a; r1[wid] = b; r2[wid] = c; }
    __syncthreads();
    if (tid == 0) {
        double SP = 0.0, sumS = 0.0, accs = 0.0;
#pragma unroll
        for (int w = 0; w < 8; w++) { SP += r0[w]; sumS += r1[w]; accs += r2[w]; }
        double ldpN = (N >= 1) ? (double)g_ldp[N] : 0.0;
        double ldsN = (N >= 1) ? (double)g_lds[N] : 0.0;
        double set_acc = g_sc[0], K0d = g_sc[1], ldfc0 = g_sc[2], LDSqd = g_sc[3], LDRqd = g_sc[4];
        double Nd = (double)N;
        double sumF = ldfc0 + (SP - ldpN) + (Nd - 1.0) * LDRqd - (sumS - ldsN);
        double FN = (N >= 1) ? (ldpN + LDRqd - ldsN) : ldfc0;
        double tot = set_acc + Nd * (K0d + 0.5 * LDSqd) - 0.5 * SP + 0.5 * sumF
                   + 0.5 * (16.0 * LOG2PI + FN) + 8.0 + accs;
        out[0] = (float)tot;
    }
}

extern "C" void kernel_launch(void* const* d_in, const int* in_sizes, int n_in,
                              void* d_out, int out_size) {
    int Tn = in_sizes[0] / 16;
    if (Tn > TMAX) Tn = TMAX;
    const float* obs = (const float*)d_in[0];
    const float* ppm_ = (const float*)d_in[1];
    const float* ppc = (const float*)d_in[2];
    const float* wp = (const float*)d_in[3];
    const float* pb_ = (const float*)d_in[4];
    const float* ptc = (const float*)d_in[5];
    const float* wep = (const float*)d_in[6];
    const float* peb = (const float*)d_in[7];
    const float* pec = (const float*)d_in[8];
    const float* qpm = (const float*)d_in[9];
    const float* qpc = (const float*)d_in[10];
    const float* wq_ = (const float*)d_in[11];
    const float* qb = (const float*)d_in[12];
    const float* qtc = (const float*)d_in[13];
    const float* hq_ = (const float*)d_in[14];
    const float* qeb = (const float*)d_in[15];
    const float* qec = (const float*)d_in[16];
    const int nsegA = (Tn + SEGA - 1) / SEGA;
    const int ngrp = (nsegA + GRP - 1) / GRP;
    const int nsegG = (Tn + 15) / 16;
    const int nseg1 = (Tn + SEG - 1) / SEG;
    k_setup<<<1, 256>>>(obs, ppm_, ppc, wp, pb_, ptc, wep, peb, pec, qpm, qpc,
                        wq_, qb, qtc, hq_, qeb, qec, Tn);
    k_elemA<<<nsegA, 256>>>(obs, Tn);
    k_elemB1<<<ngrp, 256>>>(Tn);
    k_elemCD<<<Tn, 256>>>(wq_, qtc, hq_, qec, qb, wp, Tn);
    k_par1<<<nsegG + nseg1, 256>>>(Tn, nsegG);
    k_par2<<<2, 256>>>(Tn);
    k_tail<<<Tn, 256>>>(obs, wp, pb_, wep, peb, ppm_, Tn);
    k_fin<<<1, 256>>>((float*)d_out, Tn);
}

// round 15
// speedup vs baseline: 6.7461x; 1.0704x over previous
#include <cuda_runtime.h>
#include <math.h>

#define TMAX 256
#define LOG2PI 1.8378770664093453
#define SEGA 8
#define GRP 8

// ---------------- device scratch ----------------
__device__ float g_pA[TMAX][256], g_pC[TMAX][256], g_pJ[TMAX][256];
__device__ float g_pb[TMAX][16], g_pe[TMAX][16];
__device__ float g_lA[32][256], g_lC[32][256], g_lJ[32][256];
__device__ float g_lb[32][16], g_le[32][16];
__device__ float g_gA[4][256], g_gC[4][256], g_gJ[4][256];
__device__ float g_gb[4][16], g_ge[4][16];
__device__ float g_xC[4][256], g_xb[4][16];
__device__ float g_P[TMAX][256], g_ba[TMAX][16];
__device__ float g_bcov[TMAX][256], g_Q[TMAX][256];
__device__ float g_mP[TMAX][256], g_mQ[TMAX][256], g_mQo[TMAX][256];
__device__ float g_Gx[16][256], g_Gox[16][256];
__device__ float g_ldp[TMAX], g_lds[TMAX];
__device__ double g_accT[TMAX];
__device__ float g_Lr[TMAX][256], g_Lu[TMAX][16];
__device__ float g_Sr[32][256], g_Su[32][16];
__device__ float g_Gr[32][256], g_Gu[32][16];
__device__ float g_OmP[256], g_om[256], g_Om0[256], g_Em[256], g_Fm[256];
__device__ float g_Ac[256], g_Cc[256], g_Jc[256], g_Kc[256], g_Ec[256];
__device__ float g_cb0[16], g_e0v[16];
__device__ float g_fcF[256], g_fmF[16];
__device__ double g_sc[8];

__device__ __forceinline__ float dot_rc(const float* A, const float* B, int i, int j) {
    float s = 0.f;
#pragma unroll
    for (int k = 0; k < 16; k++) s = fmaf(A[i * 16 + k], B[k * 16 + j], s);
    return s;
}
__device__ __forceinline__ float dot_tc(const float* A, const float* B, int i, int j) {
    float s = 0.f;
#pragma unroll
    for (int k = 0; k < 16; k++) s = fmaf(A[k * 16 + i], B[k * 16 + j], s);
    return s;
}
__device__ __forceinline__ float dot_rt(const float* A, const float* B, int i, int j) {
    float s = 0.f;
#pragma unroll
    for (int k = 0; k < 16; k++) s = fmaf(A[i * 16 + k], B[j * 16 + k], s);
    return s;
}
__device__ __forceinline__ float mv(const float* M, const float* v, int r) {
    float s = 0.f;
#pragma unroll
    for (int k = 0; k < 16; k++) s = fmaf(M[r * 16 + k], v[k], s);
    return s;
}

// Warp GJ solve A X = B (16 RHS); writes X^T to Xt; returns sum(log|piv|).
__device__ __forceinline__ float warp_gj_solve(const float* Am, const float* Bm,
                                               float* Xt, int lane) {
    float a[16];
    const float* src = (lane < 16) ? (Am + lane) : (Bm + lane - 16);
#pragma unroll
    for (int r = 0; r < 16; r++) a[r] = src[r * 16];
    float mypiv = 1.f;
#pragma unroll
    for (int p = 0; p < 16; p++) {
        float f[16];
#pragma unroll
        for (int r = 0; r < 16; r++) f[r] = __shfl_sync(0xffffffffu, a[r], p);
        float x = f[p];
        if (lane == p) mypiv = x;
        float r0;
        asm("rcp.approx.f32 %0, %1;" : "=f"(r0) : "f"(x));
        float pivinv = r0 * (2.0f - x * r0);
        a[p] *= pivinv;
#pragma unroll
        for (int r = 0; r < 16; r++)
            if (r != p) a[r] = fmaf(-f[r], a[p], a[r]);
    }
    float lg = __logf(fabsf(mypiv));
#pragma unroll
    for (int o = 16; o; o >>= 1) lg += __shfl_xor_sync(0xffffffffu, lg, o);
    if (lane >= 16) {
        float4* dst = reinterpret_cast<float4*>(Xt + (lane - 16) * 16);
        dst[0] = make_float4(a[0], a[1], a[2], a[3]);
        dst[1] = make_float4(a[4], a[5], a[6], a[7]);
        dst[2] = make_float4(a[8], a[9], a[10], a[11]);
        dst[3] = make_float4(a[12], a[13], a[14], a[15]);
    }
    return lg;
}

// Warp GJ vector solve A x = b; writes x to xout (lane 16 stores).
__device__ __forceinline__ void warp_gj_vecsolve(const float* Am, const float* bv,
                                                 float* xout, int lane) {
    float a[16];
    if (lane < 16) {
#pragma unroll
        for (int r = 0; r < 16; r++) a[r] = Am[r * 16 + lane];
    } else {
#pragma unroll
        for (int r = 0; r < 16; r++) a[r] = bv[r];
    }
#pragma unroll
    for (int p = 0; p < 16; p++) {
        float f[16];
#pragma unroll
        for (int r = 0; r < 16; r++) f[r] = __shfl_sync(0xffffffffu, a[r], p);
        float x = f[p];
        float r0;
        asm("rcp.approx.f32 %0, %1;" : "=f"(r0) : "f"(x));
        float pivinv = r0 * (2.0f - x * r0);
        a[p] *= pivinv;
#pragma unroll
        for (int r = 0; r < 16; r++)
            if (r != p) a[r] = fmaf(-f[r], a[p], a[r]);
    }
    if (lane == 16) {
        float4* dst = reinterpret_cast<float4*>(xout);
        dst[0] = make_float4(a[0], a[1], a[2], a[3]);
        dst[1] = make_float4(a[4], a[5], a[6], a[7]);
        dst[2] = make_float4(a[8], a[9], a[10], a[11]);
        dst[3] = make_float4(a[12], a[13], a[14], a[15]);
    }
}

// Full element compose (multi-RHS GJ): prefix ∘ next -> prefix.
__device__ __forceinline__ void compose_full(
    float* PA, float* PC, float* PJ, float* Pb, float* Pe,
    const float* NA, const float* NC, const float* NJ, const float* Nb, const float* Ne,
    float* IpW, float* ZAt, float* ZCt, float* JA,
    float* w1, float* vJ, float* zb, const float* Id,
    int tid, int i, int j, int lane, int wid) {
    IpW[tid] = Id[tid] + dot_rc(PC, NJ, i, j);
    if (tid < 16) w1[tid] = Pb[tid] + mv(PC, Ne, tid);
    else if (tid < 32) vJ[tid - 16] = mv(NJ, Pb, tid - 16);
    __syncthreads();
    if (wid == 0) {
        warp_gj_solve(IpW, PA, ZAt, lane);
    } else if (wid == 5) {
        warp_gj_solve(IpW, PC, ZCt, lane);
    } else if (wid == 2) {
        warp_gj_vecsolve(IpW, w1, zb, lane);
    } else if (wid != 4) {
        const int h = (wid == 1) ? (tid - 32) : (wid == 3) ? (tid - 64) : (tid - 128);
        JA[h] = dot_rc(NJ, PA, h >> 4, h & 15);
        JA[h + 128] = dot_rc(NJ, PA, (h + 128) >> 4, (h + 128) & 15);
    }
    __syncthreads();
    {
        float na = dot_rt(NA, ZAt, i, j);
        float cw = dot_rt(NA, ZCt, i, j);
        float nj = dot_rc(ZAt, JA, i, j) + PJ[tid];
        float nb = 0.f, ne = 0.f;
        if (tid < 16) {
            nb = mv(NA, zb, tid) + Nb[tid];
#pragma unroll
            for (int k = 0; k < 16; k++) ne = fmaf(ZAt[tid * 16 + k], Ne[k] - vJ[k], ne);
            ne += Pe[tid];
        }
        PA[tid] = na;
        PJ[tid] = nj;
        ZCt[tid] = cw;
        if (tid < 16) { Pb[tid] = nb; Pe[tid] = ne; }
    }
    __syncthreads();
    PC[tid] = dot_rt(ZCt, NA, i, j) + NC[tid];
    __syncthreads();
}

// Light (b,C) compose: state (Cst,bst) ∘ element (global) -> state.
__device__ __forceinline__ void light_compose(
    float* Cst, float* bst,
    const float* gA, const float* gC, const float* gJ,
    const float* gb, const float* ge,
    float* NA, float* NJ, float* IpW, float* ZCt, float* zb,
    float* Nb2, float* w1, const float* Id,
    int tid, int i, int j, int lane, int wid) {
    NA[tid] = gA[tid]; NJ[tid] = gJ[tid];
    if (tid < 16) Nb2[tid] = gb[tid];
    else if (tid < 32) w1[tid - 16] = ge[tid - 16];
    __syncthreads();
    IpW[tid] = Id[tid] + dot_rc(Cst, NJ, i, j);
    if (tid < 16) {
        float s = bst[tid];
#pragma unroll
        for (int k = 0; k < 16; k++) s = fmaf(Cst[tid * 16 + k], w1[k], s);
        zb[tid] = s;
    }
    __syncthreads();
    if (wid == 0) warp_gj_solve(IpW, Cst, ZCt, lane);
    else if (wid == 2) warp_gj_vecsolve(IpW, zb, w1, lane);
    __syncthreads();
    {
        float cw = dot_rt(NA, ZCt, i, j);
        float nb = 0.f;
        if (tid < 16) nb = mv(NA, w1, tid) + Nb2[tid];
        ZCt[tid] = cw;
        if (tid < 16) bst[tid] = nb;
    }
    __syncthreads();
    Cst[tid] = dot_rt(ZCt, NA, i, j) + gC[tid];
    __syncthreads();
}

// ================= setup =================
__global__ void __launch_bounds__(256, 1) k_setup(
    const float* obs, const float* ppm_, const float* ppc, const float* wp,
    const float* pb_, const float* ptc, const float* wep, const float* peb,
    const float* pec, const float* qpm, const float* qpc, const float* wq_,
    const float* qb, const float* qtc, const float* hq_, const float* qeb,
    const float* qec, int Tn) {
    __shared__ float Wq[256], Sq[256], Hq[256], Rq[256], Wp[256], Wep[256], Id[256];
    __shared__ float MI[6][256], VI[6][256];
    __shared__ float Hpc[256], U1[256], V[256], S[256], Sc[256];
    __shared__ float Km[256], Kc[256], Ec[256], IKH[256], B1[256], t3[256];
    __shared__ float ldsh[8];
    __shared__ float bq[16], dq[16], pm0[16], innov[16], y0[16], c2v[16];
    const int tid = threadIdx.x, i = tid >> 4, j = tid & 15;
    const int lane = tid & 31, wid = tid >> 5;
    Wq[tid] = wq_[tid]; Sq[tid] = qtc[tid]; Hq[tid] = hq_[tid]; Rq[tid] = qec[tid];
    Wp[tid] = wp[tid]; Wep[tid] = wep[tid]; Id[tid] = (i == j) ? 1.f : 0.f;
    MI[0][tid] = ptc[tid]; MI[1][tid] = pec[tid]; MI[2][tid] = ppc[tid];
    MI[3][tid] = qtc[tid]; MI[4][tid] = qec[tid]; MI[5][tid] = qpc[tid];
    if (tid < 16) { bq[tid] = qb[tid]; dq[tid] = qeb[tid]; pm0[tid] = qpm[tid]; y0[tid] = obs[tid]; }
    __syncthreads();
    if (wid < 6) {
        float ld = warp_gj_solve(MI[wid], Id, VI[wid], lane);
        if (lane == 0) ldsh[wid] = ld;
    }
    __syncthreads();
    g_OmP[tid] = -0.5f * VI[0][tid];
    g_om[tid] = -0.5f * VI[1][tid];
    g_Om0[tid] = -0.5f * VI[2][tid];
    B1[tid] = dot_rc(VI[0], Wp, i, j);
    t3[tid] = -0.5f * dot_rc(VI[1], Wep, i, j);
    Hpc[tid] = dot_rc(Hq, MI[5], i, j);
    U1[tid] = dot_rc(Hq, Sq, i, j);
    V[tid] = dot_rc(Hq, Wq, i, j);
    if (tid < 16) innov[tid] = y0[tid] - mv(Hq, pm0, tid) - dq[tid];
    __syncthreads();
    g_Fm[tid] = dot_tc(Wp, B1, i, j);
    g_Em[tid] = dot_tc(Wep, t3, i, j);
    S[tid] = dot_rt(Hpc, Hq, i, j) + Rq[tid];
    Sc[tid] = dot_rt(U1, Hq, i, j) + Rq[tid];
    __syncthreads();
    if (wid == 0) {
        float ld = warp_gj_solve(S, Hpc, Km, lane);
        if (lane == 0) ldsh[6] = ld;
    } else if (wid == 2) {
        warp_gj_solve(Sc, U1, Kc, lane);
    } else if (wid == 5) {
        warp_gj_solve(Sc, V, Ec, lane);
    }
    __syncthreads();
    g_pA[0][tid] = 0.f; g_pJ[0][tid] = 0.f;
    g_pC[0][tid] = MI[5][tid] - dot_rc(Km, Hpc, i, j);
    IKH[tid] = Id[tid] - dot_rc(Kc, Hq, i, j);
    if (tid < 16) {
        c2v[tid] = mv(Hq, bq, tid) + dq[tid];
        g_pb[0][tid] = pm0[tid] + mv(Km, innov, tid);
        g_pe[0][tid] = 0.f;
    }
    __syncthreads();
    g_Ac[tid] = dot_rc(IKH, Wq, i, j);
    g_Cc[tid] = dot_rc(IKH, Sq, i, j);
    g_Jc[tid] = dot_rc(Ec, V, i, j);
    g_Kc[tid] = Kc[tid]; g_Ec[tid] = Ec[tid];
    if (tid < 16) {
        g_cb0[tid] = mv(IKH, bq, tid) - mv(Kc, dq, tid);
        g_e0v[tid] = mv(Ec, c2v, tid);
    }
    if (tid == 0) {
        double LDp = ldsh[0], LDe = ldsh[1], LDpr = ldsh[2];
        double LDSq = ldsh[3], LDRq = ldsh[4], ldqp = ldsh[5], ldS0 = ldsh[6];
        g_sc[0] = -0.5 * (16.0 * LOG2PI + LDpr) - 0.5 * (16.0 * LOG2PI + LDe);
        g_sc[1] = -8.0 * LOG2PI - 0.5 * LDe - 0.5 * LDp + 8.0;
        g_sc[2] = ldqp + LDRq - ldS0;
        g_sc[3] = LDSq;
        g_sc[4] = LDRq;
    }
}

// ================= elemA =================
__global__ void __launch_bounds__(256, 1) k_elemA(const float* obs, int Tn) {
    __shared__ float Ac[256], Cc[256], Jc[256], Kc[256], Ec[256], Id[256];
    __shared__ float A[256], C[256], J[256];
    __shared__ float IpW[256], ZAt[256], ZCt[256], JA[256];
    __shared__ float cb0[16], e0v[16];
    __shared__ float bv[16], ev[16], bt[16], et[16], w1[16], vJ[16], zb[16], yv[16];
    const int tid = threadIdx.x, i = tid >> 4, j = tid & 15;
    const int lane = tid & 31, wid = tid >> 5;
    const int t0 = blockIdx.x * SEGA;
    if (t0 >= Tn) return;
    const int tend = min(t0 + SEGA, Tn);
    Ac[tid] = g_Ac[tid]; Cc[tid] = g_Cc[tid]; Jc[tid] = g_Jc[tid];
    Kc[tid] = g_Kc[tid]; Ec[tid] = g_Ec[tid]; Id[tid] = (i == j) ? 1.f : 0.f;
    if (tid < 16) { cb0[tid] = g_cb0[tid]; e0v[tid] = g_e0v[tid]; }
    __syncthreads();
    if (t0 == 0) {
        A[tid] = g_pA[0][tid]; C[tid] = g_pC[0][tid]; J[tid] = g_pJ[0][tid];
        if (tid < 16) { bv[tid] = g_pb[0][tid]; ev[tid] = g_pe[0][tid]; }
    } else {
        if (tid < 16) yv[tid] = obs[t0 * 16 + tid];
        __syncthreads();
        A[tid] = Ac[tid]; C[tid] = Cc[tid]; J[tid] = Jc[tid];
        if (tid < 16) { bv[tid] = cb0[tid] + mv(Kc, yv, tid); ev[tid] = mv(Ec, yv, tid) - e0v[tid]; }
        __syncthreads();
        g_pA[t0][tid] = A[tid]; g_pC[t0][tid] = C[tid]; g_pJ[t0][tid] = J[tid];
        if (tid < 16) { g_pb[t0][tid] = bv[tid]; g_pe[t0][tid] = ev[tid]; }
    }
    __syncthreads();
    for (int t = t0 + 1; t < tend; t++) {
        if (tid < 16) yv[tid] = obs[t * 16 + tid];
        __syncthreads();
        if (tid < 16) bt[tid] = cb0[tid] + mv(Kc, yv, tid);
        else if (tid < 32) et[tid - 16] = mv(Ec, yv, tid - 16) - e0v[tid - 16];
        __syncthreads();
        compose_full(A, C, J, bv, ev, Ac, Cc, Jc, bt, et,
                     IpW, ZAt, ZCt, JA, w1, vJ, zb, Id, tid, i, j, lane, wid);
        g_pA[t][tid] = A[tid]; g_pC[t][tid] = C[tid]; g_pJ[t][tid] = J[tid];
        if (tid < 16) { g_pb[t][tid] = bv[tid]; g_pe[t][tid] = ev[tid]; }
        __syncthreads();
    }
}

// ================= elemB1 =================
__global__ void __launch_bounds__(256, 1) k_elemB1(int Tn) {
    __shared__ float A[256], C[256], J[256], Id[256];
    __shared__ float NA[256], NC[256], NJ[256];
    __shared__ float IpW[256], ZAt[256], ZCt[256], JA[256];
    __shared__ float bv[16], ev[16], Nb[16], Ne[16], w1[16], vJ[16], zb[16];
    const int tid = threadIdx.x, i = tid >> 4, j = tid & 15;
    const int lane = tid & 31, wid = tid >> 5;
    const int nsegA = (Tn + SEGA - 1) / SEGA;
    const int g = blockIdx.x;
    const int k0 = g * GRP;
    if (k0 >= nsegA) return;
    const int kend = min(k0 + GRP, nsegA);
    Id[tid] = (i == j) ? 1.f : 0.f;
    A[tid] = Id[tid]; C[tid] = 0.f; J[tid] = 0.f;
    if (tid < 16) { bv[tid] = 0.f; ev[tid] = 0.f; }
    __syncthreads();
    for (int k = k0; k < kend; k++) {
        g_lA[k][tid] = A[tid]; g_lC[k][tid] = C[tid]; g_lJ[k][tid] = J[tid];
        if (tid < 16) { g_lb[k][tid] = bv[tid]; g_le[k][tid] = ev[tid]; }
        const int tl = min(k * SEGA + SEGA - 1, Tn - 1);
        NA[tid] = g_pA[tl][tid]; NC[tid] = g_pC[tl][tid]; NJ[tid] = g_pJ[tl][tid];
        if (tid < 16) { Nb[tid] = g_pb[tl][tid]; Ne[tid] = g_pe[tl][tid]; }
        __syncthreads();
        compose_full(A, C, J, bv, ev, NA, NC, NJ, Nb, Ne,
                     IpW, ZAt, ZCt, JA, w1, vJ, zb, Id, tid, i, j, lane, wid);
    }
    g_gA[g][tid] = A[tid]; g_gC[g][tid] = C[tid]; g_gJ[g][tid] = J[tid];
    if (tid < 16) { g_gb[g][tid] = bv[tid]; g_ge[g][tid] = ev[tid]; }
}

// ================= elemB2: (b,C) exclusive scan over group totals =================
__global__ void __launch_bounds__(256, 1) k_elemB2(int Tn) {
    __shared__ float Cst[256], Id[256];
    __shared__ float NA[256], NJ[256], IpW[256], ZCt[256];
    __shared__ float bst[16], Nb2[16], w1[16], zb[16];
    const int tid = threadIdx.x, i = tid >> 4, j = tid & 15;
    const int lane = tid & 31, wid = tid >> 5;
    const int nsegA = (Tn + SEGA - 1) / SEGA;
    const int ngrp = (nsegA + GRP - 1) / GRP;
    Id[tid] = (i == j) ? 1.f : 0.f;
    Cst[tid] = 0.f;
    if (tid < 16) bst[tid] = 0.f;
    __syncthreads();
    for (int g = 0; g < ngrp; g++) {
        g_xC[g][tid] = Cst[tid];
        if (tid < 16) g_xb[g][tid] = bst[tid];
        if (g == ngrp - 1) break;
        __syncthreads();
        light_compose(Cst, bst, g_gA[g], g_gC[g], g_gJ[g], g_gb[g], g_ge[g],
                      NA, NJ, IpW, ZCt, zb, Nb2, w1, Id, tid, i, j, lane, wid);
    }
}

// ================= elemCD: 2 light composes + phaseD =================
__global__ void __launch_bounds__(256, 1) k_elemCD(
    const float* wq_, const float* qtc, const float* hq_, const float* qec,
    const float* qb, const float* wp, int Tn) {
    const int t = blockIdx.x;
    if (t >= Tn) return;
    const int kseg = t / SEGA, grp = kseg / GRP;
    __shared__ float Cst[256], Id[256];
    __shared__ float NA[256], NJ[256];
    __shared__ float IpW[256], ZCt[256], fc[256];
    __shared__ float M[256], pcm[256], U[256], S2[256], bA[256], scr[256], t1[256], Z1[256];
    __shared__ float bst[16], Nb2[16], w1[16], zb[16], fmv[16], pm[16], bqv[16];
    const int tid = threadIdx.x, i = tid >> 4, j = tid & 15;
    const int lane = tid & 31, wid = tid >> 5;
    Id[tid] = (i == j) ? 1.f : 0.f;
    Cst[tid] = g_xC[grp][tid];
    if (tid < 16) bst[tid] = g_xb[grp][tid];
    __syncthreads();
    light_compose(Cst, bst, g_lA[kseg], g_lC[kseg], g_lJ[kseg], g_lb[kseg], g_le[kseg],
                  NA, NJ, IpW, ZCt, zb, Nb2, w1, Id, tid, i, j, lane, wid);
    light_compose(Cst, bst, g_pA[t], g_pC[t], g_pJ[t], g_pb[t], g_pe[t],
                  NA, NJ, IpW, ZCt, zb, Nb2, w1, Id, tid, i, j, lane, wid);
    fc[tid] = Cst[tid];
    if (tid < 16) fmv[tid] = bst[tid];
    __syncthreads();
    if (t == Tn - 1) {
        g_fcF[tid] = fc[tid];
        if (tid < 16) g_fmF[tid] = fmv[tid];
        return;  // block-uniform
    }
    const int tt = t + 1;
    NA[tid] = wq_[tid];   // Wq
    NJ[tid] = wp[tid];    // Wp
    ZCt[tid] = hq_[tid];  // Hq
    Id[tid] = g_OmP[tid];
    if (tid < 16) bqv[tid] = qb[tid];
    __syncthreads();
    M[tid] = dot_rc(NA, fc, i, j);
    if (tid < 16) pm[tid] = mv(NA, fmv, tid) + bqv[tid];
    __syncthreads();
    pcm[tid] = dot_rt(M, NA, i, j) + qtc[tid];
    __syncthreads();
    U[tid] = dot_rc(ZCt, pcm, i, j);
    __syncthreads();
    S2[tid] = dot_rt(U, ZCt, i, j) + qec[tid];
    __syncthreads();
    if (wid == 0) {
        float ldp = warp_gj_solve(pcm, M, bA, lane);
        if (lane == 0) g_ldp[tt] = ldp;
    } else if (wid == 5) {
        float lds = warp_gj_solve(S2, U, scr, lane);
        if (lane == 0) g_lds[tt] = lds;
    }
    __syncthreads();
    t1[tid] = dot_rc(NJ, bA, i, j) - ((i == j) ? 1.f : 0.f);
    g_bcov[tt][tid] = fc[tid] - dot_rc(bA, M, i, j);
    g_P[tt][tid] = bA[tid];
    if (tid < 16) g_ba[tt][tid] = fmv[tid] - mv(bA, pm, tid);
    __syncthreads();
    Z1[tid] = dot_rc(Id, t1, i, j);  // OmP * t1
    __syncthreads();
    g_Q[tt][tid] = dot_tc(t1, Z1, i, j);
}

// ================= par1: gramA ∥ scan1 =================
#define SEG 16
__global__ void __launch_bounds__(256, 1) k_par1(int Tn, int nsegG) {
    const int tid = threadIdx.x, i = tid >> 4, j = tid & 15;
    if ((int)blockIdx.x < nsegG) {
        const int k = blockIdx.x;
        const int s0 = 16 * k + 1, N = Tn - 1;
        if (s0 > N) return;
        const int send = min(16 * k + 16, N);
        __shared__ float P[256], Q[256], Qo[256], bAs[256], Qs[256], Em[256], nP[256], Y[256], Yo[256];
        Em[tid] = g_Em[tid];
        P[tid] = g_P[s0][tid]; Q[tid] = g_Q[s0][tid]; Qo[tid] = Em[tid];
        __syncthreads();
        g_mP[s0][tid] = P[tid]; g_mQ[s0][tid] = Q[tid]; g_mQo[s0][tid] = Qo[tid];
        for (int s = s0 + 1; s <= send; s++) {
            bAs[tid] = g_P[s][tid]; Qs[tid] = g_Q[s][tid];
            __syncthreads();
            nP[tid] = dot_rc(P, bAs, i, j);
            Y[tid] = dot_rc(Q, bAs, i, j);
            Yo[tid] = dot_rc(Qo, bAs, i, j);
            __syncthreads();
            float q = dot_tc(bAs, Y, i, j) + Qs[tid];
            float qo = dot_tc(bAs, Yo, i, j) + Em[tid];
            P[tid] = nP[tid]; Q[tid] = q; Qo[tid] = qo;
            g_mP[s][tid] = nP[tid]; g_mQ[s][tid] = q; g_mQo[s][tid] = qo;
            __syncthreads();
        }
    } else {
        const int b = blockIdx.x - nsegG;
        const int lo = b * SEG;
        int hi = min(lo + SEG, Tn);
        if (lo >= Tn) return;
        __shared__ float R[256], Rn[256], bA[256];
        __shared__ float u[16], un[16], ba[16];
        R[tid] = (i == j) ? 1.f : 0.f;
        if (tid < 16) u[tid] = 0.f;
        __syncthreads();
        for (int t = hi - 1; t >= lo; t--) {
            g_Lr[t][tid] = R[tid];
            if (tid < 16) g_Lu[t][tid] = u[tid];
            if (t == 0) break;
            bA[tid] = g_P[t][tid];
            if (tid < 16) ba[tid] = g_ba[t][tid];
            __syncthreads();
            Rn[tid] = dot_rc(bA, R, i, j);
            if (tid < 16) un[tid] = ba[tid] + mv(bA, u, tid);
            __syncthreads();
            R[tid] = Rn[tid];
            if (tid < 16) u[tid] = un[tid];
            __syncthreads();
        }
        g_Sr[b][tid] = R[tid];
        if (tid < 16) g_Su[b][tid] = u[tid];
    }
}

// ================= par2: gramB ∥ scan2 =================
__global__ void __launch_bounds__(256, 1) k_par2(int Tn) {
    const int tid = threadIdx.x, i = tid >> 4, j = tid & 15;
    if (blockIdx.x == 0) {
        __shared__ float G[256], Go[256], P[256], Qp[256], Qop[256], Y[256], Yo[256];
        const int N = Tn - 1;
        if (N < 1) return;
        const int nsg = (N + 15) / 16;
        G[tid] = g_Om0[tid]; Go[tid] = g_Em[tid];
        __syncthreads();
        for (int k = 0; k < nsg; k++) {
            g_Gx[k][tid] = G[tid]; g_Gox[k][tid] = Go[tid];
            if (k == nsg - 1) break;
            const int send = min(16 * k + 16, N);
            P[tid] = g_mP[send][tid]; Qp[tid] = g_mQ[send][tid]; Qop[tid] = g_mQo[send][tid];
            __syncthreads();
            Y[tid] = dot_rc(G, P, i, j);
            Yo[tid] = dot_rc(Go, P, i, j);
            __syncthreads();
            G[tid] = dot_tc(P, Y, i, j) + Qp[tid];
            Go[tid] = dot_tc(P, Yo, i, j) + Qop[tid];
            __syncthreads();
        }
    } else {
        const int nseg = (Tn + SEG - 1) / SEG;
        __shared__ float Gr[256], Gn[256], Sr[256];
        __shared__ float Gu[16], gn[16], Su[16];
        Gr[tid] = (i == j) ? 1.f : 0.f;
        if (tid < 16) Gu[tid] = 0.f;
        __syncthreads();
        for (int b = nseg - 1; b >= 0; b--) {
            g_Gr[b][tid] = Gr[tid];
            if (tid < 16) g_Gu[b][tid] = Gu[tid];
            if (b == 0) break;
            Sr[tid] = g_Sr[b][tid];
            if (tid < 16) Su[tid] = g_Su[b][tid];
            __syncthreads();
            Gn[tid] = dot_rc(Sr, Gr, i, j);
            if (tid < 16) gn[tid] = mv(Sr, Gu, tid) + Su[tid];
            __syncthreads();
            Gr[tid] = Gn[tid];
            if (tid < 16) Gu[tid] = gn[tid];
            __syncthreads();
        }
    }
}

// ================= tail =================
__global__ void __launch_bounds__(256, 1) k_tail(
    const float* obs, const float* wp, const float* pb_, const float* wep,
    const float* peb, const float* ppm_, int Tn) {
    const int t = blockIdx.x;
    if (t >= Tn) return;
    __shared__ float OmP[256], omm[256], Om0[256], Wp[256], Wep[256], fc[256], Gr[256];
    __shared__ float Lr[256], bA[256], Rf[256], Ai[256], A[256], Ao[256], AF[256], AoF[256];
    __shared__ float G[256], Go[256], P[256], Y[256], Yo[256], Fm[256];
    __shared__ float fm[16], Gu[16], Lu[16], bav[16], uf[16], Bv[16], Bo[16];
    __shared__ float cv[16], co[16], y[16], bp[16], ebp[16], ppm[16];
    __shared__ double dred[8];
    const int tid = threadIdx.x, i = tid >> 4, j = tid & 15;
    const int lane = tid & 31, wid = tid >> 5;

    OmP[tid] = g_OmP[tid]; omm[tid] = g_om[tid]; Om0[tid] = g_Om0[tid];
    Wp[tid] = wp[tid]; Wep[tid] = wep[tid]; Fm[tid] = g_Fm[tid];
    fc[tid] = g_fcF[tid]; Gr[tid] = g_Gr[t / SEG][tid];
    Lr[tid] = g_Lr[t][tid];
    bA[tid] = (t > 0) ? g_P[t][tid] : 0.f;
    if (tid < 16) {
        fm[tid] = g_fmF[tid]; Gu[tid] = g_Gu[t / SEG][tid];
        bp[tid] = pb_[tid]; ebp[tid] = peb[tid]; ppm[tid] = ppm_[tid];
        Lu[tid] = g_Lu[t][tid];
        bav[tid] = (t > 0) ? g_ba[t][tid] : 0.f;
        y[tid] = obs[t * 16 + tid];
    }
    __syncthreads();

    double acc = 0.0;
    if (t >= 1) {
        const int s = t - 1;
        if (s == 0) {
            G[tid] = Om0[tid]; Go[tid] = g_Em[tid];
            __syncthreads();
        } else {
            const int k = (s - 1) >> 4;
            G[tid] = g_Gx[k][tid]; Go[tid] = g_Gox[k][tid];
            P[tid] = g_mP[s][tid];
            __syncthreads();
            Y[tid] = dot_rc(G, P, i, j);
            Yo[tid] = dot_rc(Go, P, i, j);
            __syncthreads();
            G[tid] = dot_tc(P, Y, i, j) + g_mQ[s][tid];
            Go[tid] = dot_tc(P, Yo, i, j) + g_mQo[s][tid];
            __syncthreads();
        }
        acc += (double)((G[tid] + Go[tid] - 0.5f * Fm[tid]) * g_bcov[t][tid]);
    }
    Rf[tid] = dot_rc(Lr, Gr, i, j);
    Ai[tid] = (t > 0) ? (dot_rc(Wp, bA, i, j) - ((i == j) ? 1.f : 0.f))
                      : ((i == j) ? 1.f : 0.f);
    if (tid < 16) {
        uf[tid] = mv(Lr, Gu, tid) + Lu[tid];
        Bv[tid] = (t > 0) ? (mv(Wp, bav, tid) + bp[tid]) : (-ppm[tid]);
    }
    __syncthreads();
    A[tid] = dot_rc(Ai, Rf, i, j);
    Ao[tid] = dot_rc(Wep, Rf, i, j);
    if (tid < 16) {
        Bv[tid] += mv(Ai, uf, tid);
        Bo[tid] = ebp[tid] - y[tid] + mv(Wep, uf, tid);
    }
    __syncthreads();
    AF[tid] = dot_rc(A, fc, i, j);
    AoF[tid] = dot_rc(Ao, fc, i, j);
    if (tid < 16) {
        cv[tid] = mv(A, fm, tid) + Bv[tid];
        co[tid] = mv(Ao, fm, tid) + Bo[tid];
    }
    __syncthreads();
    {
        const float* Om = (t == 0) ? Om0 : OmP;
        acc += (double)(Om[tid] * (dot_rc(AF, A, i, j) + cv[i] * cv[j])
                      + omm[tid] * (dot_rc(AoF, Ao, i, j) + co[i] * co[j]));
    }
    double v = acc;
#pragma unroll
    for (int o = 16; o; o >>= 1) v += __shfl_xor_sync(0xffffffffu, v, o);
    if (lane == 0) dred[wid] = v;
    __syncthreads();
    if (tid == 0) {
        double tot = 0.0;
#pragma unroll
        for (int w = 0; w < 8; w++) tot += dred[w];
        g_accT[t] = tot;
    }
}

// ================= finalize =================
__global__ void __launch_bounds__(256, 1) k_fin(float* out, int Tn) {
    __shared__ double r0[8], r1[8], r2[8];
    const int tid = threadIdx.x, lane = tid & 31, wid = tid >> 5;
    const int N = Tn - 1;
    double a = 0.0, b = 0.0, c = 0.0;
    for (int t = tid; t < Tn; t += 256) {
        if (t >= 1) { a += (double)g_ldp[t]; b += (double)g_lds[t]; }
        c += g_accT[t];
    }
#pragma unroll
    for (int o = 16; o; o >>= 1) {
        a += __shfl_xor_sync(0xffffffffu, a, o);
        b += __shfl_xor_sync(0xffffffffu, b, o);
        c += __shfl_xor_sync(0xffffffffu, c, o);
    }
    if (lane == 0) { r0[wid] = a; r1[wid] = b; r2[wid] = c; }
    __syncthreads();
    if (tid == 0) {
        double SP = 0.0, sumS = 0.0, accs = 0.0;
#pragma unroll
        for (int w = 0; w < 8; w++) { SP += r0[w]; sumS += r1[w]; accs += r2[w]; }
        double ldpN = (N >= 1) ? (double)g_ldp[N] : 0.0;
        double ldsN = (N >= 1) ? (double)g_lds[N] : 0.0;
        double set_acc = g_sc[0], K0d = g_sc[1], ldfc0 = g_sc[2], LDSqd = g_sc[3], LDRqd = g_sc[4];
        double Nd = (double)N;
        double sumF = ldfc0 + (SP - ldpN) + (Nd - 1.0) * LDRqd - (sumS - ldsN);
        double FN = (N >= 1) ? (ldpN + LDRqd - ldsN) : ldfc0;
        double tot = set_acc + Nd * (K0d + 0.5 * LDSqd) - 0.5 * SP + 0.5 * sumF
                   + 0.5 * (16.0 * LOG2PI + FN) + 8.0 + accs;
        out[0] = (float)tot;
    }
}

extern "C" void kernel_launch(void* const* d_in, const int* in_sizes, int n_in,
                              void* d_out, int out_size) {
    int Tn = in_sizes[0] / 16;
    if (Tn > TMAX) Tn = TMAX;
    const float* obs = (const float*)d_in[0];
    const float* ppm_ = (const float*)d_in[1];
    const float* ppc = (const float*)d_in[2];
    const float* wp = (const float*)d_in[3];
    const float* pb_ = (const float*)d_in[4];
    const float* ptc = (const float*)d_in[5];
    const float* wep = (const float*)d_in[6];
    const float* peb = (const float*)d_in[7];
    const float* pec = (const float*)d_in[8];
    const float* qpm = (const float*)d_in[9];
    const float* qpc = (const float*)d_in[10];
    const float* wq_ = (const float*)d_in[11];
    const float* qb = (const float*)d_in[12];
    const float* qtc = (const float*)d_in[13];
    const float* hq_ = (const float*)d_in[14];
    const float* qeb = (const float*)d_in[15];
    const float* qec = (const float*)d_in[16];
    const int nsegA = (Tn + SEGA - 1) / SEGA;
    const int ngrp = (nsegA + GRP - 1) / GRP;
    const int nsegG = (Tn + 15) / 16;
    const int nseg1 = (Tn + SEG - 1) / SEG;
    k_setup<<<1, 256>>>(obs, ppm_, ppc, wp, pb_, ptc, wep, peb, pec, qpm, qpc,
                        wq_, qb, qtc, hq_, qeb, qec, Tn);
    k_elemA<<<nsegA, 256>>>(obs, Tn);
    k_elemB1<<<ngrp, 256>>>(Tn);
    k_elemB2<<<1, 256>>>(Tn);
    k_elemCD<<<Tn, 256>>>(wq_, qtc, hq_, qec, qb, wp, Tn);
    k_par1<<<nsegG + nseg1, 256>>>(Tn, nsegG);
    k_par2<<<2, 256>>>(Tn);
    k_tail<<<Tn, 256>>>(obs, wp, pb_, wep, peb, ppm_, Tn);
    k_fin<<<1, 256>>>((float*)d_out, Tn);
}